// round 6
// baseline (speedup 1.0000x reference)
#include <cuda_runtime.h>
#include <cuda_bf16.h>
#include <math.h>
#include <stdint.h>

#define NN 20000
#define EE 320000
#define GG 64
#define MPAD 20096          // 157 * 128
#define NTILES 157

// ---------------- device scratch ----------------
__device__ float g_h1[NN * 128];
__device__ float g_qkvs[(size_t)NN * 1024];
__device__ int g_deg[NN];
__device__ int g_fill[NN];
__device__ int g_rowptr[NN + 1];
__device__ int g_csrc[EE];

// ping-pong bf16x3 A-images: [MPAD][3K], widest K=512 -> 1536 cols
__device__ __nv_bfloat16 g_img0[(size_t)MPAD * 1536];
__device__ __nv_bfloat16 g_img1[(size_t)MPAD * 1536];
__device__ __nv_bfloat16 g_Wbf[2457600];

// weight image offsets (elements), layout [Nc][3K]
#define OFF_S1   0
#define OFF_S2   98304
#define OFF_T1   294912
#define OFF_T2   1081344
#define OFF_P1   1867776
#define OFF_P2   2260992

__device__ __forceinline__ uint32_t smem_u32(const void* p) {
    uint32_t a;
    asm("{ .reg .u64 t; cvta.to.shared.u64 t, %1; cvt.u32.u64 %0, t; }" : "=r"(a) : "l"(p));
    return a;
}
__device__ __forceinline__ void cpa16(uint32_t dst, const void* src) {
    asm volatile("cp.async.cg.shared.global [%0], [%1], 16;" :: "r"(dst), "l"(src));
}

// write 4 consecutive floats as hi|hi|lo into image row (imgK=256 layout)
__device__ __forceinline__ void img_write4(__nv_bfloat16* row, int c, float4 v) {
    __nv_bfloat162 hh0, hh1, ll0, ll1;
    hh0.x = __float2bfloat16(v.x); hh0.y = __float2bfloat16(v.y);
    hh1.x = __float2bfloat16(v.z); hh1.y = __float2bfloat16(v.w);
    ll0.x = __float2bfloat16(v.x - __bfloat162float(hh0.x));
    ll0.y = __float2bfloat16(v.y - __bfloat162float(hh0.y));
    ll1.x = __float2bfloat16(v.z - __bfloat162float(hh1.x));
    ll1.y = __float2bfloat16(v.w - __bfloat162float(hh1.y));
    *(__nv_bfloat162*)(row + c) = hh0;       *(__nv_bfloat162*)(row + c + 2) = hh1;
    *(__nv_bfloat162*)(row + 256 + c) = hh0; *(__nv_bfloat162*)(row + 256 + c + 2) = hh1;
    *(__nv_bfloat162*)(row + 512 + c) = ll0; *(__nv_bfloat162*)(row + 512 + c + 2) = ll1;
}

// ---------------- CSR build ----------------
__global__ void k_zero(float* out) {
    int i = blockIdx.x * blockDim.x + threadIdx.x;
    if (i < NN) { g_deg[i] = 0; g_fill[i] = 0; }
    if (i < GG * 128) out[i] = 0.0f;
}
__global__ void k_hist(const int* __restrict__ dst) {
    int e = blockIdx.x * blockDim.x + threadIdx.x;
    if (e < EE) atomicAdd(&g_deg[dst[e]], 1);
}
__global__ void k_scan() {
    __shared__ int sh[1024];
    __shared__ int carry;
    int tid = threadIdx.x;
    if (tid == 0) carry = 0;
    __syncthreads();
    for (int base = 0; base < NN; base += 1024) {
        int i = base + tid;
        int val = (i < NN) ? g_deg[i] : 0;
        sh[tid] = val;
        __syncthreads();
        for (int off = 1; off < 1024; off <<= 1) {
            int t = (tid >= off) ? sh[tid - off] : 0;
            __syncthreads();
            sh[tid] += t;
            __syncthreads();
        }
        if (i < NN) g_rowptr[i] = carry + sh[tid] - val;
        int tot = sh[1023];
        __syncthreads();
        if (tid == 0) carry += tot;
        __syncthreads();
    }
    if (tid == 0) g_rowptr[NN] = carry;
}
__global__ void k_scatter(const int* __restrict__ src, const int* __restrict__ dst) {
    int e = blockIdx.x * blockDim.x + threadIdx.x;
    if (e >= EE) return;
    int d = dst[e];
    int pos = atomicAdd(&g_fill[d], 1);
    g_csrc[g_rowptr[d] + pos] = src[e];
}

// ---------------- SAGE mean aggregation -> image cols [0,128) ----------------
__global__ void k_sage_agg(const float* __restrict__ x, __nv_bfloat16* __restrict__ img) {
    int w = (blockIdx.x * blockDim.x + threadIdx.x) >> 5;
    int lane = threadIdx.x & 31;
    if (w >= NN) return;
    int beg = g_rowptr[w], end = g_rowptr[w + 1];
    float4 acc = make_float4(0.f, 0.f, 0.f, 0.f);
    for (int e = beg; e < end; e++) {
        int s = g_csrc[e];
        float4 xv = *(const float4*)(x + (size_t)s * 128 + lane * 4);
        acc.x += xv.x; acc.y += xv.y; acc.z += xv.z; acc.w += xv.w;
    }
    float inv = 1.0f / fmaxf((float)(end - beg), 1.0f);
    acc.x *= inv; acc.y *= inv; acc.z *= inv; acc.w *= inv;
    img_write4(img + (size_t)w * 768, lane * 4, acc);
}

// ---------------- x -> image cols [128,256) ----------------
__global__ void k_convX(const float* __restrict__ x, __nv_bfloat16* __restrict__ img) {
    int idx = blockIdx.x * blockDim.x + threadIdx.x;
    if (idx >= NN * 32) return;
    int m = idx >> 5;
    int k = (idx & 31) * 4;
    float4 v = *(const float4*)(x + (size_t)m * 128 + k);
    img_write4(img + (size_t)m * 768, 128 + k, v);
}

// ---------------- weight conversion: [Nc][3K] = hi|lo|hi ----------------
__global__ void k_convW(const float* __restrict__ W1, int K1,
                        const float* __restrict__ W2, int K,
                        int Nw, int dstOff) {
    int idx = blockIdx.x * blockDim.x + threadIdx.x;
    if (idx >= Nw * K) return;
    int n = idx / K;
    int k = idx - n * K;
    float val = (k < K1) ? W1[(size_t)k * Nw + n] : W2[(size_t)(k - K1) * Nw + n];
    __nv_bfloat16 hi = __float2bfloat16(val);
    __nv_bfloat16 lo = __float2bfloat16(val - __bfloat162float(hi));
    __nv_bfloat16* row = g_Wbf + (size_t)dstOff + (size_t)n * (3 * K);
    row[k] = hi;
    row[K + k] = lo;
    row[2 * K + k] = hi;
}

// ---------------- 3-stage pipelined mma.sync bf16 GEMM ----------------
// C = act(A' @ W'^T + bias), 128x128 block, 64 k-tile
#define STAGE_BYTES 32768
#define NSTAGE 3

__global__ void __launch_bounds__(256, 2)
gemm_mma(const __nv_bfloat16* __restrict__ A, const __nv_bfloat16* __restrict__ W,
         const float* __restrict__ b0, const float* __restrict__ b1,
         const float* __restrict__ b2, const float* __restrict__ b3,
         float* __restrict__ C, int Nc, int Ktot, int act,
         __nv_bfloat16* __restrict__ img, int imgK, int imgColOff,
         const int* __restrict__ batch, float* __restrict__ pool) {
    extern __shared__ char smem[];
    const int tid = threadIdx.x;
    const int wid = tid >> 5, lane = tid & 31;
    const int bm = blockIdx.y * 128;
    const int bn = blockIdx.x * 128;
    const int wm = (wid & 1) << 6;
    const int wn = (wid >> 1) << 5;
    const uint32_t sb = smem_u32(smem);

    float acc[4][4][4];
#pragma unroll
    for (int i = 0; i < 4; i++)
#pragma unroll
        for (int j = 0; j < 4; j++)
#pragma unroll
            for (int t = 0; t < 4; t++) acc[i][j][t] = 0.f;

    const int nK = Ktot >> 6;

#define ISSUE(c, buf) do { \
        int _k0 = (c) << 6; \
        uint32_t _base = sb + (buf) * STAGE_BYTES; \
        _Pragma("unroll") \
        for (int l = 0; l < 4; l++) { \
            int idx = tid + l * 256; \
            int row = idx >> 3, u = idx & 7; \
            uint32_t sw = row * 128 + ((u ^ (row & 7)) << 4); \
            cpa16(_base + sw, A + (size_t)(bm + row) * Ktot + _k0 + u * 8); \
            cpa16(_base + 16384 + sw, W + (size_t)(bn + row) * Ktot + _k0 + u * 8); \
        } \
        asm volatile("cp.async.commit_group;" ::: "memory"); \
    } while (0)

    ISSUE(0, 0);
    if (nK > 1) ISSUE(1, 1);

    for (int c = 0; c < nK; c++) {
        // complete stage c
        if (c + 1 < nK) asm volatile("cp.async.wait_group 1;" ::: "memory");
        else            asm volatile("cp.async.wait_group 0;" ::: "memory");
        __syncthreads();   // also protects buffer (c+2)%3 from in-flight readers

        if (c + 2 < nK) {
            int nc = c + 2;
            int nb = nc % NSTAGE;
            ISSUE(nc, nb);
        }

        int buf = c % NSTAGE;
        uint32_t sAb = sb + buf * STAGE_BYTES;
        uint32_t sBb = sAb + 16384;
#pragma unroll
        for (int s = 0; s < 4; s++) {
            uint32_t a[4][4], b[4][2];
#pragma unroll
            for (int i = 0; i < 4; i++) {
                int row = wm + i * 16 + (lane & 15);
                int u = (s << 1) + (lane >> 4);
                uint32_t ad = sAb + row * 128 + ((u ^ (row & 7)) << 4);
                asm volatile("ldmatrix.sync.aligned.m8n8.x4.shared.b16 {%0,%1,%2,%3}, [%4];"
                    : "=r"(a[i][0]), "=r"(a[i][1]), "=r"(a[i][2]), "=r"(a[i][3]) : "r"(ad));
            }
#pragma unroll
            for (int jj = 0; jj < 2; jj++) {
                int row = wn + (jj << 4) + ((lane >> 4) << 3) + (lane & 7);
                int u = (s << 1) + ((lane >> 3) & 1);
                uint32_t ad = sBb + row * 128 + ((u ^ (row & 7)) << 4);
                asm volatile("ldmatrix.sync.aligned.m8n8.x4.shared.b16 {%0,%1,%2,%3}, [%4];"
                    : "=r"(b[jj * 2][0]), "=r"(b[jj * 2][1]),
                      "=r"(b[jj * 2 + 1][0]), "=r"(b[jj * 2 + 1][1]) : "r"(ad));
            }
#pragma unroll
            for (int i = 0; i < 4; i++)
#pragma unroll
                for (int j = 0; j < 4; j++)
                    asm volatile("mma.sync.aligned.m16n8k16.row.col.f32.bf16.bf16.f32 "
                        "{%0,%1,%2,%3}, {%4,%5,%6,%7}, {%8,%9}, {%0,%1,%2,%3};"
                        : "+f"(acc[i][j][0]), "+f"(acc[i][j][1]),
                          "+f"(acc[i][j][2]), "+f"(acc[i][j][3])
                        : "r"(a[i][0]), "r"(a[i][1]), "r"(a[i][2]), "r"(a[i][3]),
                          "r"(b[j][0]), "r"(b[j][1]));
        }
    }

    // epilogue
    const float* bsel[4] = {b0, b1, b2, b3};
    const int stride3K = 3 * imgK;
#pragma unroll
    for (int i = 0; i < 4; i++) {
        int r0 = bm + wm + i * 16 + (lane >> 2);
        int r1 = r0 + 8;
#pragma unroll
        for (int j = 0; j < 4; j++) {
            int c = bn + wn + (j << 3) + ((lane & 3) << 1);
            const float* bp = bsel[c >> 8];
            float bv0 = bp[c & 255], bv1 = bp[(c & 255) + 1];
            float v00 = acc[i][j][0] + bv0, v01 = acc[i][j][1] + bv1;
            float v10 = acc[i][j][2] + bv0, v11 = acc[i][j][3] + bv1;
            if (act == 1) {
                v00 = fmaxf(v00, 0.f); v01 = fmaxf(v01, 0.f);
                v10 = fmaxf(v10, 0.f); v11 = fmaxf(v11, 0.f);
            } else if (act == 2) {
                v00 = 1.f / (1.f + __expf(-v00)); v01 = 1.f / (1.f + __expf(-v01));
                v10 = 1.f / (1.f + __expf(-v10)); v11 = 1.f / (1.f + __expf(-v11));
            }
            if (C) {
                if (r0 < NN) { C[(size_t)r0 * Nc + c] = v00; C[(size_t)r0 * Nc + c + 1] = v01; }
                if (r1 < NN) { C[(size_t)r1 * Nc + c] = v10; C[(size_t)r1 * Nc + c + 1] = v11; }
            }
            if (img) {
                int ic = imgColOff + c;
                if (r0 < NN) {
                    __nv_bfloat16* row = img + (size_t)r0 * stride3K;
                    __nv_bfloat162 hh, ll;
                    hh.x = __float2bfloat16(v00); hh.y = __float2bfloat16(v01);
                    ll.x = __float2bfloat16(v00 - __bfloat162float(hh.x));
                    ll.y = __float2bfloat16(v01 - __bfloat162float(hh.y));
                    *(__nv_bfloat162*)(row + ic) = hh;
                    *(__nv_bfloat162*)(row + imgK + ic) = hh;
                    *(__nv_bfloat162*)(row + 2 * imgK + ic) = ll;
                }
                if (r1 < NN) {
                    __nv_bfloat16* row = img + (size_t)r1 * stride3K;
                    __nv_bfloat162 hh, ll;
                    hh.x = __float2bfloat16(v10); hh.y = __float2bfloat16(v11);
                    ll.x = __float2bfloat16(v10 - __bfloat162float(hh.x));
                    ll.y = __float2bfloat16(v11 - __bfloat162float(hh.y));
                    *(__nv_bfloat162*)(row + ic) = hh;
                    *(__nv_bfloat162*)(row + imgK + ic) = hh;
                    *(__nv_bfloat162*)(row + 2 * imgK + ic) = ll;
                }
            }
            if (pool) {
                if (r0 < NN) {
                    int g = batch[r0] * 128;
                    atomicMax((int*)&pool[g + c], __float_as_int(v00));
                    atomicMax((int*)&pool[g + c + 1], __float_as_int(v01));
                }
                if (r1 < NN) {
                    int g = batch[r1] * 128;
                    atomicMax((int*)&pool[g + c], __float_as_int(v10));
                    atomicMax((int*)&pool[g + c + 1], __float_as_int(v11));
                }
            }
        }
    }
}

// ---------------- attention: warp per node, 8 heads; writes image ----------
__global__ void k_attn(const float* __restrict__ qkvs, __nv_bfloat16* __restrict__ img) {
    int node = (blockIdx.x * blockDim.x + threadIdx.x) >> 5;
    if (node >= NN) return;
    int lane = threadIdx.x & 31;
    const float* base = qkvs + (size_t)node * 1024;
    float4 q0 = *(const float4*)(base + lane * 4);
    float4 q1 = *(const float4*)(base + 128 + lane * 4);
    int beg = g_rowptr[node], end = g_rowptr[node + 1];
    float m0 = -3.0e38f, s0 = 0.f, m1 = -3.0e38f, s1 = 0.f;
    float4 a0 = make_float4(0.f, 0.f, 0.f, 0.f);
    float4 a1 = make_float4(0.f, 0.f, 0.f, 0.f);
    const float scl = 0.17677669529663687f;
#pragma unroll 2
    for (int e = beg; e < end; e++) {
        int sn = g_csrc[e];
        const float* kb = qkvs + (size_t)sn * 1024 + 256;
        float4 k0 = *(const float4*)(kb + lane * 4);
        float4 k1 = *(const float4*)(kb + 128 + lane * 4);
        float4 v0 = *(const float4*)(kb + 256 + lane * 4);
        float4 v1 = *(const float4*)(kb + 384 + lane * 4);
        float d0 = q0.x * k0.x + q0.y * k0.y + q0.z * k0.z + q0.w * k0.w;
        float d1 = q1.x * k1.x + q1.y * k1.y + q1.z * k1.z + q1.w * k1.w;
#pragma unroll
        for (int off = 4; off; off >>= 1) {
            d0 += __shfl_xor_sync(0xffffffffu, d0, off);
            d1 += __shfl_xor_sync(0xffffffffu, d1, off);
        }
        d0 *= scl; d1 *= scl;
        float mn0 = fmaxf(m0, d0);
        float sc0 = __expf(m0 - mn0);
        float p0 = __expf(d0 - mn0);
        s0 = s0 * sc0 + p0;
        a0.x = a0.x * sc0 + p0 * v0.x; a0.y = a0.y * sc0 + p0 * v0.y;
        a0.z = a0.z * sc0 + p0 * v0.z; a0.w = a0.w * sc0 + p0 * v0.w;
        m0 = mn0;
        float mn1 = fmaxf(m1, d1);
        float sc1 = __expf(m1 - mn1);
        float p1 = __expf(d1 - mn1);
        s1 = s1 * sc1 + p1;
        a1.x = a1.x * sc1 + p1 * v1.x; a1.y = a1.y * sc1 + p1 * v1.y;
        a1.z = a1.z * sc1 + p1 * v1.z; a1.w = a1.w * sc1 + p1 * v1.w;
        m1 = mn1;
    }
    float inv0 = (end > beg) ? (1.f / s0) : 0.f;
    float inv1 = (end > beg) ? (1.f / s1) : 0.f;
    const float* sk = base + 768;
    float4 sk0 = *(const float4*)(sk + lane * 4);
    float4 sk1 = *(const float4*)(sk + 128 + lane * 4);
    float4 o0, o1;
    o0.x = fmaxf(sk0.x + a0.x * inv0, 0.f); o0.y = fmaxf(sk0.y + a0.y * inv0, 0.f);
    o0.z = fmaxf(sk0.z + a0.z * inv0, 0.f); o0.w = fmaxf(sk0.w + a0.w * inv0, 0.f);
    o1.x = fmaxf(sk1.x + a1.x * inv1, 0.f); o1.y = fmaxf(sk1.y + a1.y * inv1, 0.f);
    o1.z = fmaxf(sk1.z + a1.z * inv1, 0.f); o1.w = fmaxf(sk1.w + a1.w * inv1, 0.f);
    __nv_bfloat16* row = img + (size_t)node * 768;
    img_write4(row, lane * 4, o0);
    img_write4(row, 128 + lane * 4, o1);
}

// ---------------- host orchestration ----------------
static void run_gemm(const __nv_bfloat16* A, const __nv_bfloat16* W,
                     const float* b0, const float* b1, const float* b2, const float* b3,
                     float* C, int Nc, int Ktot, int act,
                     __nv_bfloat16* img, int imgK, int imgColOff,
                     const int* batch, float* pool) {
    dim3 grid(Nc / 128, NTILES);
    gemm_mma<<<grid, 256, NSTAGE * STAGE_BYTES>>>(A, W, b0, b1, b2, b3, C, Nc, Ktot, act,
                                                  img, imgK, imgColOff, batch, pool);
}

extern "C" void kernel_launch(void* const* d_in, const int* in_sizes, int n_in,
                              void* d_out, int out_size) {
    const float* x     = (const float*)d_in[0];
    const int*   ei    = (const int*)d_in[1];
    const int*   batch = (const int*)d_in[2];
    const float* s1_wl = (const float*)d_in[3];
    const float* s1_bl = (const float*)d_in[4];
    const float* s1_wr = (const float*)d_in[5];
    const float* s2_wl = (const float*)d_in[6];
    const float* s2_bl = (const float*)d_in[7];
    const float* s2_wr = (const float*)d_in[8];
    const float* t1_wq = (const float*)d_in[9];
    const float* t1_bq = (const float*)d_in[10];
    const float* t1_wk = (const float*)d_in[11];
    const float* t1_bk = (const float*)d_in[12];
    const float* t1_wv = (const float*)d_in[13];
    const float* t1_bv = (const float*)d_in[14];
    const float* t1_ws = (const float*)d_in[15];
    const float* t1_bs = (const float*)d_in[16];
    const float* t2_wq = (const float*)d_in[17];
    const float* t2_bq = (const float*)d_in[18];
    const float* t2_wk = (const float*)d_in[19];
    const float* t2_bk = (const float*)d_in[20];
    const float* t2_wv = (const float*)d_in[21];
    const float* t2_bv = (const float*)d_in[22];
    const float* t2_ws = (const float*)d_in[23];
    const float* t2_bs = (const float*)d_in[24];
    const float* p1_w  = (const float*)d_in[25];
    const float* p1_b  = (const float*)d_in[26];
    const float* p2_w  = (const float*)d_in[27];
    const float* p2_b  = (const float*)d_in[28];

    const int* e_src = ei;
    const int* e_dst = ei + EE;

    cudaFuncSetAttribute(gemm_mma, cudaFuncAttributeMaxDynamicSharedMemorySize,
                         NSTAGE * STAGE_BYTES);

    float *d_h1, *d_qkvs;
    __nv_bfloat16 *d_i0, *d_i1, *d_W;
    cudaGetSymbolAddress((void**)&d_h1, g_h1);
    cudaGetSymbolAddress((void**)&d_qkvs, g_qkvs);
    cudaGetSymbolAddress((void**)&d_i0, g_img0);
    cudaGetSymbolAddress((void**)&d_i1, g_img1);
    cudaGetSymbolAddress((void**)&d_W, g_Wbf);

    // CSR build
    k_zero<<<(NN + 255) / 256, 256>>>((float*)d_out);
    k_hist<<<(EE + 255) / 256, 256>>>(e_dst);
    k_scan<<<1, 1024>>>();
    k_scatter<<<(EE + 255) / 256, 256>>>(e_src, e_dst);

    // weight images
#define CONVW(W1, K1, W2, K, NW, OFF) \
    k_convW<<<((NW) * (K) + 255) / 256, 256>>>(W1, K1, W2, K, NW, OFF)
    CONVW(s1_wl, 128, s1_wr, 256, 128, OFF_S1);
    CONVW(s2_wl, 128, s2_wr, 256, 256, OFF_S2);
    CONVW(t1_wq, 256, t1_wq, 256, 256, OFF_T1 + 0 * 256 * 768);
    CONVW(t1_wk, 256, t1_wk, 256, 256, OFF_T1 + 1 * 256 * 768);
    CONVW(t1_wv, 256, t1_wv, 256, 256, OFF_T1 + 2 * 256 * 768);
    CONVW(t1_ws, 256, t1_ws, 256, 256, OFF_T1 + 3 * 256 * 768);
    CONVW(t2_wq, 256, t2_wq, 256, 256, OFF_T2 + 0 * 256 * 768);
    CONVW(t2_wk, 256, t2_wk, 256, 256, OFF_T2 + 1 * 256 * 768);
    CONVW(t2_wv, 256, t2_wv, 256, 256, OFF_T2 + 2 * 256 * 768);
    CONVW(t2_ws, 256, t2_ws, 256, 256, OFF_T2 + 3 * 256 * 768);
    CONVW(p1_w, 256, p1_w, 256, 512, OFF_P1);
    CONVW(p2_w, 512, p2_w, 512, 128, OFF_P2);

    // SAGE 1 input image (img0): mean(x) cols [0,128), x cols [128,256)
    k_convX<<<(NN * 32 + 255) / 256, 256>>>(x, d_i0);
    k_sage_agg<<<(NN * 32 + 255) / 256, 256>>>(x, d_i0);
    run_gemm(d_i0, d_W + OFF_S1, s1_bl, s1_bl, s1_bl, s1_bl,
             d_h1, 128, 768, 1, d_i1, 256, 128, nullptr, nullptr);

    // SAGE 2: mean(h1) -> img1[0:128); S2 -> img0[0:256)
    k_sage_agg<<<(NN * 32 + 255) / 256, 256>>>(d_h1, d_i1);
    run_gemm(d_i1, d_W + OFF_S2, s2_bl, s2_bl, s2_bl, s2_bl,
             nullptr, 256, 768, 1, d_i0, 256, 0, nullptr, nullptr);

    // TransformerConv 1
    run_gemm(d_i0, d_W + OFF_T1, t1_bq, t1_bk, t1_bv, t1_bs,
             d_qkvs, 1024, 768, 0, nullptr, 0, 0, nullptr, nullptr);
    k_attn<<<(NN * 32 + 255) / 256, 256>>>(d_qkvs, d_i1);

    // TransformerConv 2
    run_gemm(d_i1, d_W + OFF_T2, t2_bq, t2_bk, t2_bv, t2_bs,
             d_qkvs, 1024, 768, 0, nullptr, 0, 0, nullptr, nullptr);
    k_attn<<<(NN * 32 + 255) / 256, 256>>>(d_qkvs, d_i0);

    // proj MLP: P1 -> img1 (K=512); P2 -> sigmoid + fused pool
    run_gemm(d_i0, d_W + OFF_P1, p1_b, p1_b + 256, p1_b, p1_b,
             nullptr, 512, 768, 1, d_i1, 512, 0, nullptr, nullptr);
    run_gemm(d_i1, d_W + OFF_P2, p2_b, p2_b, p2_b, p2_b,
             nullptr, 128, 1536, 2, nullptr, 0, 0, batch, (float*)d_out);
}

// round 7
// speedup vs baseline: 1.0371x; 1.0371x over previous
#include <cuda_runtime.h>
#include <cuda_bf16.h>
#include <math.h>
#include <stdint.h>

#define NN 20000
#define EE 320000
#define GG 64
#define MPAD 20096          // 157 * 128
#define NTILES 157

// ---------------- device scratch ----------------
__device__ float g_h1[NN * 128];
__device__ float g_qkvs[(size_t)NN * 1024];
__device__ int g_deg[NN];
__device__ int g_fill[NN];
__device__ int g_rowptr[NN + 1];
__device__ int g_csrc[EE];

// ping-pong bf16x3 A-images: [MPAD][3K], widest K=512 -> 1536 cols
__device__ __nv_bfloat16 g_img0[(size_t)MPAD * 1536];
__device__ __nv_bfloat16 g_img1[(size_t)MPAD * 1536];
__device__ __nv_bfloat16 g_Wbf[2457600];

// weight image offsets (elements), layout [Nc][3K]
#define OFF_S1   0
#define OFF_S2   98304
#define OFF_T1   294912
#define OFF_T2   1081344
#define OFF_P1   1867776
#define OFF_P2   2260992

__device__ __forceinline__ uint32_t smem_u32(const void* p) {
    uint32_t a;
    asm("{ .reg .u64 t; cvta.to.shared.u64 t, %1; cvt.u32.u64 %0, t; }" : "=r"(a) : "l"(p));
    return a;
}
__device__ __forceinline__ void cpa16(uint32_t dst, const void* src) {
    asm volatile("cp.async.cg.shared.global [%0], [%1], 16;" :: "r"(dst), "l"(src));
}

// write 4 consecutive floats as hi|hi|lo into image row (imgK=256 layout)
__device__ __forceinline__ void img_write4(__nv_bfloat16* row, int c, float4 v) {
    __nv_bfloat162 hh0, hh1, ll0, ll1;
    hh0.x = __float2bfloat16(v.x); hh0.y = __float2bfloat16(v.y);
    hh1.x = __float2bfloat16(v.z); hh1.y = __float2bfloat16(v.w);
    ll0.x = __float2bfloat16(v.x - __bfloat162float(hh0.x));
    ll0.y = __float2bfloat16(v.y - __bfloat162float(hh0.y));
    ll1.x = __float2bfloat16(v.z - __bfloat162float(hh1.x));
    ll1.y = __float2bfloat16(v.w - __bfloat162float(hh1.y));
    *(__nv_bfloat162*)(row + c) = hh0;       *(__nv_bfloat162*)(row + c + 2) = hh1;
    *(__nv_bfloat162*)(row + 256 + c) = hh0; *(__nv_bfloat162*)(row + 256 + c + 2) = hh1;
    *(__nv_bfloat162*)(row + 512 + c) = ll0; *(__nv_bfloat162*)(row + 512 + c + 2) = ll1;
}

// ---------------- CSR build ----------------
__global__ void k_zero(float* out) {
    int i = blockIdx.x * blockDim.x + threadIdx.x;
    if (i < NN) { g_deg[i] = 0; g_fill[i] = 0; }
    if (i < GG * 128) out[i] = 0.0f;
}
__global__ void k_hist(const int* __restrict__ dst) {
    int e = blockIdx.x * blockDim.x + threadIdx.x;
    if (e < EE) atomicAdd(&g_deg[dst[e]], 1);
}
__global__ void k_scan() {
    __shared__ int sh[1024];
    __shared__ int carry;
    int tid = threadIdx.x;
    if (tid == 0) carry = 0;
    __syncthreads();
    for (int base = 0; base < NN; base += 1024) {
        int i = base + tid;
        int val = (i < NN) ? g_deg[i] : 0;
        sh[tid] = val;
        __syncthreads();
        for (int off = 1; off < 1024; off <<= 1) {
            int t = (tid >= off) ? sh[tid - off] : 0;
            __syncthreads();
            sh[tid] += t;
            __syncthreads();
        }
        if (i < NN) g_rowptr[i] = carry + sh[tid] - val;
        int tot = sh[1023];
        __syncthreads();
        if (tid == 0) carry += tot;
        __syncthreads();
    }
    if (tid == 0) g_rowptr[NN] = carry;
}
__global__ void k_scatter(const int* __restrict__ src, const int* __restrict__ dst) {
    int e = blockIdx.x * blockDim.x + threadIdx.x;
    if (e >= EE) return;
    int d = dst[e];
    int pos = atomicAdd(&g_fill[d], 1);
    g_csrc[g_rowptr[d] + pos] = src[e];
}

// ---------------- fused prep: sage mean (cols [0,128)) + x (cols [128,256)) ---
__global__ void k_prep1(const float* __restrict__ x, __nv_bfloat16* __restrict__ img) {
    int w = (blockIdx.x * blockDim.x + threadIdx.x) >> 5;
    int lane = threadIdx.x & 31;
    if (w >= NN) return;
    int beg = g_rowptr[w], end = g_rowptr[w + 1];
    float4 acc = make_float4(0.f, 0.f, 0.f, 0.f);
    for (int e = beg; e < end; e++) {
        int s = g_csrc[e];
        float4 xv = *(const float4*)(x + (size_t)s * 128 + lane * 4);
        acc.x += xv.x; acc.y += xv.y; acc.z += xv.z; acc.w += xv.w;
    }
    float inv = 1.0f / fmaxf((float)(end - beg), 1.0f);
    acc.x *= inv; acc.y *= inv; acc.z *= inv; acc.w *= inv;
    __nv_bfloat16* row = img + (size_t)w * 768;
    img_write4(row, lane * 4, acc);
    float4 xo = *(const float4*)(x + (size_t)w * 128 + lane * 4);
    img_write4(row, 128 + lane * 4, xo);
}

// ---------------- SAGE mean aggregation -> image cols [0,128) ----------------
__global__ void k_sage_agg(const float* __restrict__ x, __nv_bfloat16* __restrict__ img) {
    int w = (blockIdx.x * blockDim.x + threadIdx.x) >> 5;
    int lane = threadIdx.x & 31;
    if (w >= NN) return;
    int beg = g_rowptr[w], end = g_rowptr[w + 1];
    float4 acc = make_float4(0.f, 0.f, 0.f, 0.f);
    for (int e = beg; e < end; e++) {
        int s = g_csrc[e];
        float4 xv = *(const float4*)(x + (size_t)s * 128 + lane * 4);
        acc.x += xv.x; acc.y += xv.y; acc.z += xv.z; acc.w += xv.w;
    }
    float inv = 1.0f / fmaxf((float)(end - beg), 1.0f);
    acc.x *= inv; acc.y *= inv; acc.z *= inv; acc.w *= inv;
    img_write4(img + (size_t)w * 768, lane * 4, acc);
}

// ---------------- fused weight conversion: all 12 tensors in one launch -------
struct WJob { const float *w1, *w2; int k1, K, nw, off, cumEnd; };
struct WJobs { WJob j[12]; };
#define WTOTAL 819200

__global__ void k_convW_all(WJobs jobs) {
    int idx = blockIdx.x * blockDim.x + threadIdx.x;
    if (idx >= WTOTAL) return;
    int s = 0;
    while (idx >= jobs.j[s].cumEnd) s++;
    const WJob J = jobs.j[s];
    int local = idx - (s ? jobs.j[s - 1].cumEnd : 0);
    int n = local / J.K;
    int k = local - n * J.K;
    float val = (k < J.k1) ? J.w1[(size_t)k * J.nw + n] : J.w2[(size_t)(k - J.k1) * J.nw + n];
    __nv_bfloat16 hi = __float2bfloat16(val);
    __nv_bfloat16 lo = __float2bfloat16(val - __bfloat162float(hi));
    __nv_bfloat16* row = g_Wbf + (size_t)J.off + (size_t)n * (3 * J.K);
    row[k] = hi;
    row[J.K + k] = lo;
    row[2 * J.K + k] = hi;
}

// ---------------- 2-stage pipelined mma.sync bf16 GEMM, templated BN ---------
template <int BN>
__global__ void __launch_bounds__(256, 2)
gemm_mma(const __nv_bfloat16* __restrict__ A, const __nv_bfloat16* __restrict__ W,
         const float* __restrict__ b0, const float* __restrict__ b1,
         const float* __restrict__ b2, const float* __restrict__ b3,
         float* __restrict__ C, int Nc, int Ktot, int act,
         __nv_bfloat16* __restrict__ img, int imgK, int imgColOff,
         const int* __restrict__ batch, float* __restrict__ pool) {
    constexpr int STB = 16384 + BN * 128;       // A tile 16KB + B tile
    constexpr int MI = (BN == 128) ? 4 : 2;     // warp M sub-tiles (x16 rows)
    extern __shared__ char smem[];
    const int tid = threadIdx.x;
    const int wid = tid >> 5, lane = tid & 31;
    const int bm = blockIdx.y * 128;
    const int bn = blockIdx.x * BN;
    const int wm = (BN == 128) ? ((wid & 1) << 6) : ((wid & 3) << 5);
    const int wn = (BN == 128) ? ((wid >> 1) << 5) : ((wid >> 2) << 5);
    const uint32_t sb = smem_u32(smem);

    float acc[MI][4][4];
#pragma unroll
    for (int i = 0; i < MI; i++)
#pragma unroll
        for (int j = 0; j < 4; j++)
#pragma unroll
            for (int t = 0; t < 4; t++) acc[i][j][t] = 0.f;

    const int nK = Ktot >> 6;

    auto issue = [&](int c, int buf) {
        int k0 = c << 6;
        uint32_t base = sb + buf * STB;
#pragma unroll
        for (int l = 0; l < 4; l++) {
            int idx = tid + l * 256;
            int row = idx >> 3, u = idx & 7;
            uint32_t sw = row * 128 + ((u ^ (row & 7)) << 4);
            cpa16(base + sw, A + (size_t)(bm + row) * Ktot + k0 + u * 8);
        }
#pragma unroll
        for (int l = 0; l < BN / 32; l++) {
            int idx = tid + l * 256;
            int row = idx >> 3, u = idx & 7;
            uint32_t sw = row * 128 + ((u ^ (row & 7)) << 4);
            cpa16(base + 16384 + sw, W + (size_t)(bn + row) * Ktot + k0 + u * 8);
        }
        asm volatile("cp.async.commit_group;" ::: "memory");
    };

    issue(0, 0);
    for (int c = 0; c < nK; c++) {
        int buf = c & 1;
        if (c + 1 < nK) {
            issue(c + 1, (c + 1) & 1);
            asm volatile("cp.async.wait_group 1;" ::: "memory");
        } else {
            asm volatile("cp.async.wait_group 0;" ::: "memory");
        }
        __syncthreads();

        uint32_t sAb = sb + buf * STB;
        uint32_t sBb = sAb + 16384;
#pragma unroll
        for (int s = 0; s < 4; s++) {
            uint32_t a[MI][4], b[4][2];
#pragma unroll
            for (int i = 0; i < MI; i++) {
                int row = wm + i * 16 + (lane & 15);
                int u = (s << 1) + (lane >> 4);
                uint32_t ad = sAb + row * 128 + ((u ^ (row & 7)) << 4);
                asm volatile("ldmatrix.sync.aligned.m8n8.x4.shared.b16 {%0,%1,%2,%3}, [%4];"
                    : "=r"(a[i][0]), "=r"(a[i][1]), "=r"(a[i][2]), "=r"(a[i][3]) : "r"(ad));
            }
#pragma unroll
            for (int jj = 0; jj < 2; jj++) {
                int row = wn + (jj << 4) + ((lane >> 4) << 3) + (lane & 7);
                int u = (s << 1) + ((lane >> 3) & 1);
                uint32_t ad = sBb + row * 128 + ((u ^ (row & 7)) << 4);
                asm volatile("ldmatrix.sync.aligned.m8n8.x4.shared.b16 {%0,%1,%2,%3}, [%4];"
                    : "=r"(b[jj * 2][0]), "=r"(b[jj * 2][1]),
                      "=r"(b[jj * 2 + 1][0]), "=r"(b[jj * 2 + 1][1]) : "r"(ad));
            }
#pragma unroll
            for (int i = 0; i < MI; i++)
#pragma unroll
                for (int j = 0; j < 4; j++)
                    asm volatile("mma.sync.aligned.m16n8k16.row.col.f32.bf16.bf16.f32 "
                        "{%0,%1,%2,%3}, {%4,%5,%6,%7}, {%8,%9}, {%0,%1,%2,%3};"
                        : "+f"(acc[i][j][0]), "+f"(acc[i][j][1]),
                          "+f"(acc[i][j][2]), "+f"(acc[i][j][3])
                        : "r"(a[i][0]), "r"(a[i][1]), "r"(a[i][2]), "r"(a[i][3]),
                          "r"(b[j][0]), "r"(b[j][1]));
        }
        __syncthreads();
    }

    // epilogue
    const float* bsel[4] = {b0, b1, b2, b3};
    const int stride3K = 3 * imgK;
#pragma unroll
    for (int i = 0; i < MI; i++) {
        int r0 = bm + wm + i * 16 + (lane >> 2);
        int r1 = r0 + 8;
#pragma unroll
        for (int j = 0; j < 4; j++) {
            int c = bn + wn + (j << 3) + ((lane & 3) << 1);
            const float* bp = bsel[c >> 8];
            float bv0 = bp[c & 255], bv1 = bp[(c & 255) + 1];
            float v00 = acc[i][j][0] + bv0, v01 = acc[i][j][1] + bv1;
            float v10 = acc[i][j][2] + bv0, v11 = acc[i][j][3] + bv1;
            if (act == 1) {
                v00 = fmaxf(v00, 0.f); v01 = fmaxf(v01, 0.f);
                v10 = fmaxf(v10, 0.f); v11 = fmaxf(v11, 0.f);
            } else if (act == 2) {
                v00 = 1.f / (1.f + __expf(-v00)); v01 = 1.f / (1.f + __expf(-v01));
                v10 = 1.f / (1.f + __expf(-v10)); v11 = 1.f / (1.f + __expf(-v11));
            }
            if (C) {
                if (r0 < NN) { C[(size_t)r0 * Nc + c] = v00; C[(size_t)r0 * Nc + c + 1] = v01; }
                if (r1 < NN) { C[(size_t)r1 * Nc + c] = v10; C[(size_t)r1 * Nc + c + 1] = v11; }
            }
            if (img) {
                int ic = imgColOff + c;
                if (r0 < NN) {
                    __nv_bfloat16* row = img + (size_t)r0 * stride3K;
                    __nv_bfloat162 hh, ll;
                    hh.x = __float2bfloat16(v00); hh.y = __float2bfloat16(v01);
                    ll.x = __float2bfloat16(v00 - __bfloat162float(hh.x));
                    ll.y = __float2bfloat16(v01 - __bfloat162float(hh.y));
                    *(__nv_bfloat162*)(row + ic) = hh;
                    *(__nv_bfloat162*)(row + imgK + ic) = hh;
                    *(__nv_bfloat162*)(row + 2 * imgK + ic) = ll;
                }
                if (r1 < NN) {
                    __nv_bfloat16* row = img + (size_t)r1 * stride3K;
                    __nv_bfloat162 hh, ll;
                    hh.x = __float2bfloat16(v10); hh.y = __float2bfloat16(v11);
                    ll.x = __float2bfloat16(v10 - __bfloat162float(hh.x));
                    ll.y = __float2bfloat16(v11 - __bfloat162float(hh.y));
                    *(__nv_bfloat162*)(row + ic) = hh;
                    *(__nv_bfloat162*)(row + imgK + ic) = hh;
                    *(__nv_bfloat162*)(row + 2 * imgK + ic) = ll;
                }
            }
            if (pool) {
                if (r0 < NN) {
                    int g = batch[r0] * 128;
                    atomicMax((int*)&pool[g + c], __float_as_int(v00));
                    atomicMax((int*)&pool[g + c + 1], __float_as_int(v01));
                }
                if (r1 < NN) {
                    int g = batch[r1] * 128;
                    atomicMax((int*)&pool[g + c], __float_as_int(v10));
                    atomicMax((int*)&pool[g + c + 1], __float_as_int(v11));
                }
            }
        }
    }
}

// ---------------- attention: warp per node, 8 heads; writes image ----------
__global__ void k_attn(const float* __restrict__ qkvs, __nv_bfloat16* __restrict__ img) {
    int node = (blockIdx.x * blockDim.x + threadIdx.x) >> 5;
    if (node >= NN) return;
    int lane = threadIdx.x & 31;
    const float* base = qkvs + (size_t)node * 1024;
    float4 q0 = *(const float4*)(base + lane * 4);
    float4 q1 = *(const float4*)(base + 128 + lane * 4);
    int beg = g_rowptr[node], end = g_rowptr[node + 1];
    float m0 = -3.0e38f, s0 = 0.f, m1 = -3.0e38f, s1 = 0.f;
    float4 a0 = make_float4(0.f, 0.f, 0.f, 0.f);
    float4 a1 = make_float4(0.f, 0.f, 0.f, 0.f);
    const float scl = 0.17677669529663687f;
#pragma unroll 2
    for (int e = beg; e < end; e++) {
        int sn = g_csrc[e];
        const float* kb = qkvs + (size_t)sn * 1024 + 256;
        float4 k0 = *(const float4*)(kb + lane * 4);
        float4 k1 = *(const float4*)(kb + 128 + lane * 4);
        float4 v0 = *(const float4*)(kb + 256 + lane * 4);
        float4 v1 = *(const float4*)(kb + 384 + lane * 4);
        float d0 = q0.x * k0.x + q0.y * k0.y + q0.z * k0.z + q0.w * k0.w;
        float d1 = q1.x * k1.x + q1.y * k1.y + q1.z * k1.z + q1.w * k1.w;
#pragma unroll
        for (int off = 4; off; off >>= 1) {
            d0 += __shfl_xor_sync(0xffffffffu, d0, off);
            d1 += __shfl_xor_sync(0xffffffffu, d1, off);
        }
        d0 *= scl; d1 *= scl;
        float mn0 = fmaxf(m0, d0);
        float sc0 = __expf(m0 - mn0);
        float p0 = __expf(d0 - mn0);
        s0 = s0 * sc0 + p0;
        a0.x = a0.x * sc0 + p0 * v0.x; a0.y = a0.y * sc0 + p0 * v0.y;
        a0.z = a0.z * sc0 + p0 * v0.z; a0.w = a0.w * sc0 + p0 * v0.w;
        m0 = mn0;
        float mn1 = fmaxf(m1, d1);
        float sc1 = __expf(m1 - mn1);
        float p1 = __expf(d1 - mn1);
        s1 = s1 * sc1 + p1;
        a1.x = a1.x * sc1 + p1 * v1.x; a1.y = a1.y * sc1 + p1 * v1.y;
        a1.z = a1.z * sc1 + p1 * v1.z; a1.w = a1.w * sc1 + p1 * v1.w;
        m1 = mn1;
    }
    float inv0 = (end > beg) ? (1.f / s0) : 0.f;
    float inv1 = (end > beg) ? (1.f / s1) : 0.f;
    const float* sk = base + 768;
    float4 sk0 = *(const float4*)(sk + lane * 4);
    float4 sk1 = *(const float4*)(sk + 128 + lane * 4);
    float4 o0, o1;
    o0.x = fmaxf(sk0.x + a0.x * inv0, 0.f); o0.y = fmaxf(sk0.y + a0.y * inv0, 0.f);
    o0.z = fmaxf(sk0.z + a0.z * inv0, 0.f); o0.w = fmaxf(sk0.w + a0.w * inv0, 0.f);
    o1.x = fmaxf(sk1.x + a1.x * inv1, 0.f); o1.y = fmaxf(sk1.y + a1.y * inv1, 0.f);
    o1.z = fmaxf(sk1.z + a1.z * inv1, 0.f); o1.w = fmaxf(sk1.w + a1.w * inv1, 0.f);
    __nv_bfloat16* row = img + (size_t)node * 768;
    img_write4(row, lane * 4, o0);
    img_write4(row, 128 + lane * 4, o1);
}

// ---------------- host orchestration ----------------
static void run_gemm(int bn, const __nv_bfloat16* A, const __nv_bfloat16* W,
                     const float* b0, const float* b1, const float* b2, const float* b3,
                     float* C, int Nc, int Ktot, int act,
                     __nv_bfloat16* img, int imgK, int imgColOff,
                     const int* batch, float* pool) {
    dim3 grid(Nc / bn, NTILES);
    if (bn == 64)
        gemm_mma<64><<<grid, 256, 2 * (16384 + 64 * 128)>>>(A, W, b0, b1, b2, b3, C, Nc,
                                                            Ktot, act, img, imgK, imgColOff,
                                                            batch, pool);
    else
        gemm_mma<128><<<grid, 256, 2 * (16384 + 128 * 128)>>>(A, W, b0, b1, b2, b3, C, Nc,
                                                              Ktot, act, img, imgK, imgColOff,
                                                              batch, pool);
}

extern "C" void kernel_launch(void* const* d_in, const int* in_sizes, int n_in,
                              void* d_out, int out_size) {
    const float* x     = (const float*)d_in[0];
    const int*   ei    = (const int*)d_in[1];
    const int*   batch = (const int*)d_in[2];
    const float* s1_wl = (const float*)d_in[3];
    const float* s1_bl = (const float*)d_in[4];
    const float* s1_wr = (const float*)d_in[5];
    const float* s2_wl = (const float*)d_in[6];
    const float* s2_bl = (const float*)d_in[7];
    const float* s2_wr = (const float*)d_in[8];
    const float* t1_wq = (const float*)d_in[9];
    const float* t1_bq = (const float*)d_in[10];
    const float* t1_wk = (const float*)d_in[11];
    const float* t1_bk = (const float*)d_in[12];
    const float* t1_wv = (const float*)d_in[13];
    const float* t1_bv = (const float*)d_in[14];
    const float* t1_ws = (const float*)d_in[15];
    const float* t1_bs = (const float*)d_in[16];
    const float* t2_wq = (const float*)d_in[17];
    const float* t2_bq = (const float*)d_in[18];
    const float* t2_wk = (const float*)d_in[19];
    const float* t2_bk = (const float*)d_in[20];
    const float* t2_wv = (const float*)d_in[21];
    const float* t2_bv = (const float*)d_in[22];
    const float* t2_ws = (const float*)d_in[23];
    const float* t2_bs = (const float*)d_in[24];
    const float* p1_w  = (const float*)d_in[25];
    const float* p1_b  = (const float*)d_in[26];
    const float* p2_w  = (const float*)d_in[27];
    const float* p2_b  = (const float*)d_in[28];

    const int* e_src = ei;
    const int* e_dst = ei + EE;

    cudaFuncSetAttribute(gemm_mma<128>, cudaFuncAttributeMaxDynamicSharedMemorySize,
                         2 * (16384 + 128 * 128));
    cudaFuncSetAttribute(gemm_mma<64>, cudaFuncAttributeMaxDynamicSharedMemorySize,
                         2 * (16384 + 64 * 128));

    float *d_h1, *d_qkvs;
    __nv_bfloat16 *d_i0, *d_i1, *d_W;
    cudaGetSymbolAddress((void**)&d_h1, g_h1);
    cudaGetSymbolAddress((void**)&d_qkvs, g_qkvs);
    cudaGetSymbolAddress((void**)&d_i0, g_img0);
    cudaGetSymbolAddress((void**)&d_i1, g_img1);
    cudaGetSymbolAddress((void**)&d_W, g_Wbf);

    // CSR build
    k_zero<<<(NN + 255) / 256, 256>>>((float*)d_out);
    k_hist<<<(EE + 255) / 256, 256>>>(e_dst);
    k_scan<<<1, 1024>>>();
    k_scatter<<<(EE + 255) / 256, 256>>>(e_src, e_dst);

    // fused weight conversion (one launch for all 12 tensors)
    {
        WJobs jobs;
        int cum = 0, idx = 0;
        auto add = [&](const float* w1, const float* w2, int k1, int K, int nw, int off) {
            cum += nw * K;
            jobs.j[idx++] = WJob{w1, w2, k1, K, nw, off, cum};
        };
        add(s1_wl, s1_wr, 128, 256, 128, OFF_S1);
        add(s2_wl, s2_wr, 128, 256, 256, OFF_S2);
        add(t1_wq, t1_wq, 256, 256, 256, OFF_T1 + 0 * 256 * 768);
        add(t1_wk, t1_wk, 256, 256, 256, OFF_T1 + 1 * 256 * 768);
        add(t1_wv, t1_wv, 256, 256, 256, OFF_T1 + 2 * 256 * 768);
        add(t1_ws, t1_ws, 256, 256, 256, OFF_T1 + 3 * 256 * 768);
        add(t2_wq, t2_wq, 256, 256, 256, OFF_T2 + 0 * 256 * 768);
        add(t2_wk, t2_wk, 256, 256, 256, OFF_T2 + 1 * 256 * 768);
        add(t2_wv, t2_wv, 256, 256, 256, OFF_T2 + 2 * 256 * 768);
        add(t2_ws, t2_ws, 256, 256, 256, OFF_T2 + 3 * 256 * 768);
        add(p1_w, p1_w, 256, 256, 512, OFF_P1);
        add(p2_w, p2_w, 512, 512, 128, OFF_P2);
        k_convW_all<<<(WTOTAL + 255) / 256, 256>>>(jobs);
    }

    // SAGE 1 input image (img0): mean(x) + x in one launch
    k_prep1<<<(NN * 32 + 255) / 256, 256>>>(x, d_i0);
    run_gemm(64, d_i0, d_W + OFF_S1, s1_bl, s1_bl, s1_bl, s1_bl,
             d_h1, 128, 768, 1, d_i1, 256, 128, nullptr, nullptr);

    // SAGE 2: mean(h1) -> img1[0:128); S2 -> img0[0:256)
    k_sage_agg<<<(NN * 32 + 255) / 256, 256>>>(d_h1, d_i1);
    run_gemm(64, d_i1, d_W + OFF_S2, s2_bl, s2_bl, s2_bl, s2_bl,
             nullptr, 256, 768, 1, d_i0, 256, 0, nullptr, nullptr);

    // TransformerConv 1
    run_gemm(128, d_i0, d_W + OFF_T1, t1_bq, t1_bk, t1_bv, t1_bs,
             d_qkvs, 1024, 768, 0, nullptr, 0, 0, nullptr, nullptr);
    k_attn<<<(NN * 32 + 255) / 256, 256>>>(d_qkvs, d_i1);

    // TransformerConv 2
    run_gemm(128, d_i1, d_W + OFF_T2, t2_bq, t2_bk, t2_bv, t2_bs,
             d_qkvs, 1024, 768, 0, nullptr, 0, 0, nullptr, nullptr);
    k_attn<<<(NN * 32 + 255) / 256, 256>>>(d_qkvs, d_i0);

    // proj MLP: P1 -> img1 (K=512 layout); P2 -> sigmoid + fused pool
    run_gemm(64, d_i0, d_W + OFF_P1, p1_b, p1_b + 256, p1_b, p1_b,
             nullptr, 512, 768, 1, d_i1, 512, 0, nullptr, nullptr);
    run_gemm(64, d_i1, d_W + OFF_P2, p2_b, p2_b, p2_b, p2_b,
             nullptr, 128, 1536, 2, nullptr, 0, 0, batch, (float*)d_out);
}

// round 8
// speedup vs baseline: 1.0704x; 1.0321x over previous
#include <cuda_runtime.h>
#include <cuda_bf16.h>
#include <math.h>
#include <stdint.h>

#define NN 20000
#define EE 320000
#define GG 64
#define MPAD 20096          // 157 * 128
#define NTILES 157

// ---------------- device scratch ----------------
__device__ float g_h1[NN * 128];
__device__ float g_qkvs[(size_t)NN * 1024];
__device__ int g_deg[NN];
__device__ int g_fill[NN];
__device__ int g_rowptr[NN + 1];
__device__ int g_csrc[EE];

// ping-pong compact bf16 hi|lo A-images: [MPAD][2K], widest K=512 -> 1024 cols
__device__ __nv_bfloat16 g_img0[(size_t)MPAD * 1024];
__device__ __nv_bfloat16 g_img1[(size_t)MPAD * 1024];
__device__ __nv_bfloat16 g_Wbf[2457600];

// weight image offsets (elements), layout [Nc][3K] = hi|lo|hi
#define OFF_S1   0
#define OFF_S2   98304
#define OFF_T1   294912
#define OFF_T2   1081344
#define OFF_P1   1867776
#define OFF_P2   2260992

__device__ __forceinline__ uint32_t smem_u32(const void* p) {
    uint32_t a;
    asm("{ .reg .u64 t; cvta.to.shared.u64 t, %1; cvt.u32.u64 %0, t; }" : "=r"(a) : "l"(p));
    return a;
}
__device__ __forceinline__ void cpa16(uint32_t dst, const void* src) {
    asm volatile("cp.async.cg.shared.global [%0], [%1], 16;" :: "r"(dst), "l"(src));
}

// write 4 consecutive floats as hi @ c, lo @ K+c (compact image, row stride 2K)
__device__ __forceinline__ void img_write4(__nv_bfloat16* row, int K, int c, float4 v) {
    __nv_bfloat162 hh0, hh1, ll0, ll1;
    hh0.x = __float2bfloat16(v.x); hh0.y = __float2bfloat16(v.y);
    hh1.x = __float2bfloat16(v.z); hh1.y = __float2bfloat16(v.w);
    ll0.x = __float2bfloat16(v.x - __bfloat162float(hh0.x));
    ll0.y = __float2bfloat16(v.y - __bfloat162float(hh0.y));
    ll1.x = __float2bfloat16(v.z - __bfloat162float(hh1.x));
    ll1.y = __float2bfloat16(v.w - __bfloat162float(hh1.y));
    *(__nv_bfloat162*)(row + c) = hh0;     *(__nv_bfloat162*)(row + c + 2) = hh1;
    *(__nv_bfloat162*)(row + K + c) = ll0; *(__nv_bfloat162*)(row + K + c + 2) = ll1;
}

// ---------------- CSR build ----------------
__global__ void k_zero(float* out) {
    int i = blockIdx.x * blockDim.x + threadIdx.x;
    if (i < NN) { g_deg[i] = 0; g_fill[i] = 0; }
    if (i < GG * 128) out[i] = 0.0f;
}
__global__ void k_hist(const int* __restrict__ dst) {
    int e = blockIdx.x * blockDim.x + threadIdx.x;
    if (e < EE) atomicAdd(&g_deg[dst[e]], 1);
}
__global__ void k_scan() {
    __shared__ int sh[1024];
    __shared__ int carry;
    int tid = threadIdx.x;
    if (tid == 0) carry = 0;
    __syncthreads();
    for (int base = 0; base < NN; base += 1024) {
        int i = base + tid;
        int val = (i < NN) ? g_deg[i] : 0;
        sh[tid] = val;
        __syncthreads();
        for (int off = 1; off < 1024; off <<= 1) {
            int t = (tid >= off) ? sh[tid - off] : 0;
            __syncthreads();
            sh[tid] += t;
            __syncthreads();
        }
        if (i < NN) g_rowptr[i] = carry + sh[tid] - val;
        int tot = sh[1023];
        __syncthreads();
        if (tid == 0) carry += tot;
        __syncthreads();
    }
    if (tid == 0) g_rowptr[NN] = carry;
}
__global__ void k_scatter(const int* __restrict__ src, const int* __restrict__ dst) {
    int e = blockIdx.x * blockDim.x + threadIdx.x;
    if (e >= EE) return;
    int d = dst[e];
    int pos = atomicAdd(&g_fill[d], 1);
    g_csrc[g_rowptr[d] + pos] = src[e];
}

// ---------------- fused prep: sage mean (cols [0,128)) + x (cols [128,256)) ---
__global__ void k_prep1(const float* __restrict__ x, __nv_bfloat16* __restrict__ img) {
    int w = (blockIdx.x * blockDim.x + threadIdx.x) >> 5;
    int lane = threadIdx.x & 31;
    if (w >= NN) return;
    int beg = g_rowptr[w], end = g_rowptr[w + 1];
    float4 acc = make_float4(0.f, 0.f, 0.f, 0.f);
    for (int e = beg; e < end; e++) {
        int s = g_csrc[e];
        float4 xv = *(const float4*)(x + (size_t)s * 128 + lane * 4);
        acc.x += xv.x; acc.y += xv.y; acc.z += xv.z; acc.w += xv.w;
    }
    float inv = 1.0f / fmaxf((float)(end - beg), 1.0f);
    acc.x *= inv; acc.y *= inv; acc.z *= inv; acc.w *= inv;
    __nv_bfloat16* row = img + (size_t)w * 512;
    img_write4(row, 256, lane * 4, acc);
    float4 xo = *(const float4*)(x + (size_t)w * 128 + lane * 4);
    img_write4(row, 256, 128 + lane * 4, xo);
}

// ---------------- SAGE mean aggregation -> image cols [0,128) ----------------
__global__ void k_sage_agg(const float* __restrict__ x, __nv_bfloat16* __restrict__ img) {
    int w = (blockIdx.x * blockDim.x + threadIdx.x) >> 5;
    int lane = threadIdx.x & 31;
    if (w >= NN) return;
    int beg = g_rowptr[w], end = g_rowptr[w + 1];
    float4 acc = make_float4(0.f, 0.f, 0.f, 0.f);
    for (int e = beg; e < end; e++) {
        int s = g_csrc[e];
        float4 xv = *(const float4*)(x + (size_t)s * 128 + lane * 4);
        acc.x += xv.x; acc.y += xv.y; acc.z += xv.z; acc.w += xv.w;
    }
    float inv = 1.0f / fmaxf((float)(end - beg), 1.0f);
    acc.x *= inv; acc.y *= inv; acc.z *= inv; acc.w *= inv;
    img_write4(img + (size_t)w * 512, 256, lane * 4, acc);
}

// ---------------- fused weight conversion: all 12 tensors in one launch -------
struct WJob { const float *w1, *w2; int k1, K, nw, off, cumEnd; };
struct WJobs { WJob j[12]; };
#define WTOTAL 819200

__global__ void k_convW_all(WJobs jobs) {
    int idx = blockIdx.x * blockDim.x + threadIdx.x;
    if (idx >= WTOTAL) return;
    int s = 0;
    while (idx >= jobs.j[s].cumEnd) s++;
    const WJob J = jobs.j[s];
    int local = idx - (s ? jobs.j[s - 1].cumEnd : 0);
    int n = local / J.K;
    int k = local - n * J.K;
    float val = (k < J.k1) ? J.w1[(size_t)k * J.nw + n] : J.w2[(size_t)(k - J.k1) * J.nw + n];
    __nv_bfloat16 hi = __float2bfloat16(val);
    __nv_bfloat16 lo = __float2bfloat16(val - __bfloat162float(hi));
    __nv_bfloat16* row = g_Wbf + (size_t)J.off + (size_t)n * (3 * J.K);
    row[k] = hi;
    row[J.K + k] = lo;
    row[2 * J.K + k] = hi;
}

// ---------------- 2-stage pipelined mma.sync bf16 GEMM, templated BN ---------
// A compact [M][2K] hi|lo; W [Nc][3K] hi|lo|hi; logical K-tiles 3K/64.
template <int BN>
__global__ void __launch_bounds__(256, 2)
gemm_mma(const __nv_bfloat16* __restrict__ A, const __nv_bfloat16* __restrict__ W,
         const float* __restrict__ b0, const float* __restrict__ b1,
         const float* __restrict__ b2, const float* __restrict__ b3,
         float* __restrict__ C, int Nc, int Kbase, int act,
         __nv_bfloat16* __restrict__ img, int imgK, int imgColOff,
         const int* __restrict__ batch, float* __restrict__ pool) {
    constexpr int STB = 16384 + BN * 128;       // A tile 16KB + B tile
    constexpr int MI = (BN == 128) ? 4 : 2;     // warp M sub-tiles (x16 rows)
    extern __shared__ char smem[];
    const int tid = threadIdx.x;
    const int wid = tid >> 5, lane = tid & 31;
    const int bm = blockIdx.y * 128;
    const int bn = blockIdx.x * BN;
    const int wm = (BN == 128) ? ((wid & 1) << 6) : ((wid & 3) << 5);
    const int wn = (BN == 128) ? ((wid >> 1) << 5) : ((wid >> 2) << 5);
    const uint32_t sb = smem_u32(smem);

    float acc[MI][4][4];
#pragma unroll
    for (int i = 0; i < MI; i++)
#pragma unroll
        for (int j = 0; j < 4; j++)
#pragma unroll
            for (int t = 0; t < 4; t++) acc[i][j][t] = 0.f;

    const int KA = Kbase >> 6;        // hi chunks
    const int nK = 3 * KA;            // logical k-tiles
    const int KtotW = 3 * Kbase;
    const int KtotA = 2 * Kbase;

    auto issue = [&](int c, int buf) {
        int ac = (c < KA) ? c : (c - KA);       // physical A chunk
        int ka0 = ac << 6;
        int kw0 = c << 6;
        uint32_t base = sb + buf * STB;
#pragma unroll
        for (int l = 0; l < 4; l++) {
            int idx = tid + l * 256;
            int row = idx >> 3, u = idx & 7;
            uint32_t sw = row * 128 + ((u ^ (row & 7)) << 4);
            cpa16(base + sw, A + (size_t)(bm + row) * KtotA + ka0 + u * 8);
        }
#pragma unroll
        for (int l = 0; l < BN / 32; l++) {
            int idx = tid + l * 256;
            int row = idx >> 3, u = idx & 7;
            uint32_t sw = row * 128 + ((u ^ (row & 7)) << 4);
            cpa16(base + 16384 + sw, W + (size_t)(bn + row) * KtotW + kw0 + u * 8);
        }
        asm volatile("cp.async.commit_group;" ::: "memory");
    };

    issue(0, 0);
    for (int c = 0; c < nK; c++) {
        int buf = c & 1;
        if (c + 1 < nK) {
            issue(c + 1, (c + 1) & 1);
            asm volatile("cp.async.wait_group 1;" ::: "memory");
        } else {
            asm volatile("cp.async.wait_group 0;" ::: "memory");
        }
        __syncthreads();

        uint32_t sAb = sb + buf * STB;
        uint32_t sBb = sAb + 16384;
#pragma unroll
        for (int s = 0; s < 4; s++) {
            uint32_t a[MI][4], b[4][2];
#pragma unroll
            for (int i = 0; i < MI; i++) {
                int row = wm + i * 16 + (lane & 15);
                int u = (s << 1) + (lane >> 4);
                uint32_t ad = sAb + row * 128 + ((u ^ (row & 7)) << 4);
                asm volatile("ldmatrix.sync.aligned.m8n8.x4.shared.b16 {%0,%1,%2,%3}, [%4];"
                    : "=r"(a[i][0]), "=r"(a[i][1]), "=r"(a[i][2]), "=r"(a[i][3]) : "r"(ad));
            }
#pragma unroll
            for (int jj = 0; jj < 2; jj++) {
                int row = wn + (jj << 4) + ((lane >> 4) << 3) + (lane & 7);
                int u = (s << 1) + ((lane >> 3) & 1);
                uint32_t ad = sBb + row * 128 + ((u ^ (row & 7)) << 4);
                asm volatile("ldmatrix.sync.aligned.m8n8.x4.shared.b16 {%0,%1,%2,%3}, [%4];"
                    : "=r"(b[jj * 2][0]), "=r"(b[jj * 2][1]),
                      "=r"(b[jj * 2 + 1][0]), "=r"(b[jj * 2 + 1][1]) : "r"(ad));
            }
#pragma unroll
            for (int i = 0; i < MI; i++)
#pragma unroll
                for (int j = 0; j < 4; j++)
                    asm volatile("mma.sync.aligned.m16n8k16.row.col.f32.bf16.bf16.f32 "
                        "{%0,%1,%2,%3}, {%4,%5,%6,%7}, {%8,%9}, {%0,%1,%2,%3};"
                        : "+f"(acc[i][j][0]), "+f"(acc[i][j][1]),
                          "+f"(acc[i][j][2]), "+f"(acc[i][j][3])
                        : "r"(a[i][0]), "r"(a[i][1]), "r"(a[i][2]), "r"(a[i][3]),
                          "r"(b[j][0]), "r"(b[j][1]));
        }
        __syncthreads();
    }

    // epilogue
    const float* bsel[4] = {b0, b1, b2, b3};
    const int stride2K = 2 * imgK;
#pragma unroll
    for (int i = 0; i < MI; i++) {
        int r0 = bm + wm + i * 16 + (lane >> 2);
        int r1 = r0 + 8;
#pragma unroll
        for (int j = 0; j < 4; j++) {
            int c = bn + wn + (j << 3) + ((lane & 3) << 1);
            const float* bp = bsel[c >> 8];
            float bv0 = bp[c & 255], bv1 = bp[(c & 255) + 1];
            float v00 = acc[i][j][0] + bv0, v01 = acc[i][j][1] + bv1;
            float v10 = acc[i][j][2] + bv0, v11 = acc[i][j][3] + bv1;
            if (act == 1) {
                v00 = fmaxf(v00, 0.f); v01 = fmaxf(v01, 0.f);
                v10 = fmaxf(v10, 0.f); v11 = fmaxf(v11, 0.f);
            } else if (act == 2) {
                v00 = 1.f / (1.f + __expf(-v00)); v01 = 1.f / (1.f + __expf(-v01));
                v10 = 1.f / (1.f + __expf(-v10)); v11 = 1.f / (1.f + __expf(-v11));
            }
            if (C) {
                if (r0 < NN) { C[(size_t)r0 * Nc + c] = v00; C[(size_t)r0 * Nc + c + 1] = v01; }
                if (r1 < NN) { C[(size_t)r1 * Nc + c] = v10; C[(size_t)r1 * Nc + c + 1] = v11; }
            }
            if (img) {
                int ic = imgColOff + c;
                if (r0 < NN) {
                    __nv_bfloat16* row = img + (size_t)r0 * stride2K;
                    __nv_bfloat162 hh, ll;
                    hh.x = __float2bfloat16(v00); hh.y = __float2bfloat16(v01);
                    ll.x = __float2bfloat16(v00 - __bfloat162float(hh.x));
                    ll.y = __float2bfloat16(v01 - __bfloat162float(hh.y));
                    *(__nv_bfloat162*)(row + ic) = hh;
                    *(__nv_bfloat162*)(row + imgK + ic) = ll;
                }
                if (r1 < NN) {
                    __nv_bfloat16* row = img + (size_t)r1 * stride2K;
                    __nv_bfloat162 hh, ll;
                    hh.x = __float2bfloat16(v10); hh.y = __float2bfloat16(v11);
                    ll.x = __float2bfloat16(v10 - __bfloat162float(hh.x));
                    ll.y = __float2bfloat16(v11 - __bfloat162float(hh.y));
                    *(__nv_bfloat162*)(row + ic) = hh;
                    *(__nv_bfloat162*)(row + imgK + ic) = ll;
                }
            }
            if (pool) {
                if (r0 < NN) {
                    int g = batch[r0] * 128;
                    atomicMax((int*)&pool[g + c], __float_as_int(v00));
                    atomicMax((int*)&pool[g + c + 1], __float_as_int(v01));
                }
                if (r1 < NN) {
                    int g = batch[r1] * 128;
                    atomicMax((int*)&pool[g + c], __float_as_int(v10));
                    atomicMax((int*)&pool[g + c + 1], __float_as_int(v11));
                }
            }
        }
    }
}

// ---------------- attention: warp per node, 8 heads; writes compact image ----
__global__ void k_attn(const float* __restrict__ qkvs, __nv_bfloat16* __restrict__ img) {
    int node = (blockIdx.x * blockDim.x + threadIdx.x) >> 5;
    if (node >= NN) return;
    int lane = threadIdx.x & 31;
    const float* base = qkvs + (size_t)node * 1024;
    float4 q0 = *(const float4*)(base + lane * 4);
    float4 q1 = *(const float4*)(base + 128 + lane * 4);
    int beg = g_rowptr[node], end = g_rowptr[node + 1];
    float m0 = -3.0e38f, s0 = 0.f, m1 = -3.0e38f, s1 = 0.f;
    float4 a0 = make_float4(0.f, 0.f, 0.f, 0.f);
    float4 a1 = make_float4(0.f, 0.f, 0.f, 0.f);
    const float scl = 0.17677669529663687f;
#pragma unroll 2
    for (int e = beg; e < end; e++) {
        int sn = g_csrc[e];
        const float* kb = qkvs + (size_t)sn * 1024 + 256;
        float4 k0 = *(const float4*)(kb + lane * 4);
        float4 k1 = *(const float4*)(kb + 128 + lane * 4);
        float4 v0 = *(const float4*)(kb + 256 + lane * 4);
        float4 v1 = *(const float4*)(kb + 384 + lane * 4);
        float d0 = q0.x * k0.x + q0.y * k0.y + q0.z * k0.z + q0.w * k0.w;
        float d1 = q1.x * k1.x + q1.y * k1.y + q1.z * k1.z + q1.w * k1.w;
#pragma unroll
        for (int off = 4; off; off >>= 1) {
            d0 += __shfl_xor_sync(0xffffffffu, d0, off);
            d1 += __shfl_xor_sync(0xffffffffu, d1, off);
        }
        d0 *= scl; d1 *= scl;
        float mn0 = fmaxf(m0, d0);
        float sc0 = __expf(m0 - mn0);
        float p0 = __expf(d0 - mn0);
        s0 = s0 * sc0 + p0;
        a0.x = a0.x * sc0 + p0 * v0.x; a0.y = a0.y * sc0 + p0 * v0.y;
        a0.z = a0.z * sc0 + p0 * v0.z; a0.w = a0.w * sc0 + p0 * v0.w;
        m0 = mn0;
        float mn1 = fmaxf(m1, d1);
        float sc1 = __expf(m1 - mn1);
        float p1 = __expf(d1 - mn1);
        s1 = s1 * sc1 + p1;
        a1.x = a1.x * sc1 + p1 * v1.x; a1.y = a1.y * sc1 + p1 * v1.y;
        a1.z = a1.z * sc1 + p1 * v1.z; a1.w = a1.w * sc1 + p1 * v1.w;
        m1 = mn1;
    }
    float inv0 = (end > beg) ? (1.f / s0) : 0.f;
    float inv1 = (end > beg) ? (1.f / s1) : 0.f;
    const float* sk = base + 768;
    float4 sk0 = *(const float4*)(sk + lane * 4);
    float4 sk1 = *(const float4*)(sk + 128 + lane * 4);
    float4 o0, o1;
    o0.x = fmaxf(sk0.x + a0.x * inv0, 0.f); o0.y = fmaxf(sk0.y + a0.y * inv0, 0.f);
    o0.z = fmaxf(sk0.z + a0.z * inv0, 0.f); o0.w = fmaxf(sk0.w + a0.w * inv0, 0.f);
    o1.x = fmaxf(sk1.x + a1.x * inv1, 0.f); o1.y = fmaxf(sk1.y + a1.y * inv1, 0.f);
    o1.z = fmaxf(sk1.z + a1.z * inv1, 0.f); o1.w = fmaxf(sk1.w + a1.w * inv1, 0.f);
    __nv_bfloat16* row = img + (size_t)node * 512;
    img_write4(row, 256, lane * 4, o0);
    img_write4(row, 256, 128 + lane * 4, o1);
}

// ---------------- host orchestration ----------------
static void run_gemm(int bn, const __nv_bfloat16* A, const __nv_bfloat16* W,
                     const float* b0, const float* b1, const float* b2, const float* b3,
                     float* C, int Nc, int Kbase, int act,
                     __nv_bfloat16* img, int imgK, int imgColOff,
                     const int* batch, float* pool) {
    dim3 grid(Nc / bn, NTILES);
    if (bn == 64)
        gemm_mma<64><<<grid, 256, 2 * (16384 + 64 * 128)>>>(A, W, b0, b1, b2, b3, C, Nc,
                                                            Kbase, act, img, imgK, imgColOff,
                                                            batch, pool);
    else
        gemm_mma<128><<<grid, 256, 2 * (16384 + 128 * 128)>>>(A, W, b0, b1, b2, b3, C, Nc,
                                                              Kbase, act, img, imgK, imgColOff,
                                                              batch, pool);
}

extern "C" void kernel_launch(void* const* d_in, const int* in_sizes, int n_in,
                              void* d_out, int out_size) {
    const float* x     = (const float*)d_in[0];
    const int*   ei    = (const int*)d_in[1];
    const int*   batch = (const int*)d_in[2];
    const float* s1_wl = (const float*)d_in[3];
    const float* s1_bl = (const float*)d_in[4];
    const float* s1_wr = (const float*)d_in[5];
    const float* s2_wl = (const float*)d_in[6];
    const float* s2_bl = (const float*)d_in[7];
    const float* s2_wr = (const float*)d_in[8];
    const float* t1_wq = (const float*)d_in[9];
    const float* t1_bq = (const float*)d_in[10];
    const float* t1_wk = (const float*)d_in[11];
    const float* t1_bk = (const float*)d_in[12];
    const float* t1_wv = (const float*)d_in[13];
    const float* t1_bv = (const float*)d_in[14];
    const float* t1_ws = (const float*)d_in[15];
    const float* t1_bs = (const float*)d_in[16];
    const float* t2_wq = (const float*)d_in[17];
    const float* t2_bq = (const float*)d_in[18];
    const float* t2_wk = (const float*)d_in[19];
    const float* t2_bk = (const float*)d_in[20];
    const float* t2_wv = (const float*)d_in[21];
    const float* t2_bv = (const float*)d_in[22];
    const float* t2_ws = (const float*)d_in[23];
    const float* t2_bs = (const float*)d_in[24];
    const float* p1_w  = (const float*)d_in[25];
    const float* p1_b  = (const float*)d_in[26];
    const float* p2_w  = (const float*)d_in[27];
    const float* p2_b  = (const float*)d_in[28];

    const int* e_src = ei;
    const int* e_dst = ei + EE;

    cudaFuncSetAttribute(gemm_mma<128>, cudaFuncAttributeMaxDynamicSharedMemorySize,
                         2 * (16384 + 128 * 128));
    cudaFuncSetAttribute(gemm_mma<64>, cudaFuncAttributeMaxDynamicSharedMemorySize,
                         2 * (16384 + 64 * 128));

    float *d_h1, *d_qkvs;
    __nv_bfloat16 *d_i0, *d_i1, *d_W;
    cudaGetSymbolAddress((void**)&d_h1, g_h1);
    cudaGetSymbolAddress((void**)&d_qkvs, g_qkvs);
    cudaGetSymbolAddress((void**)&d_i0, g_img0);
    cudaGetSymbolAddress((void**)&d_i1, g_img1);
    cudaGetSymbolAddress((void**)&d_W, g_Wbf);

    // CSR build
    k_zero<<<(NN + 255) / 256, 256>>>((float*)d_out);
    k_hist<<<(EE + 255) / 256, 256>>>(e_dst);
    k_scan<<<1, 1024>>>();
    k_scatter<<<(EE + 255) / 256, 256>>>(e_src, e_dst);

    // fused weight conversion (one launch for all 12 tensors)
    {
        WJobs jobs;
        int cum = 0, idx = 0;
        auto add = [&](const float* w1, const float* w2, int k1, int K, int nw, int off) {
            cum += nw * K;
            jobs.j[idx++] = WJob{w1, w2, k1, K, nw, off, cum};
        };
        add(s1_wl, s1_wr, 128, 256, 128, OFF_S1);
        add(s2_wl, s2_wr, 128, 256, 256, OFF_S2);
        add(t1_wq, t1_wq, 256, 256, 256, OFF_T1 + 0 * 256 * 768);
        add(t1_wk, t1_wk, 256, 256, 256, OFF_T1 + 1 * 256 * 768);
        add(t1_wv, t1_wv, 256, 256, 256, OFF_T1 + 2 * 256 * 768);
        add(t1_ws, t1_ws, 256, 256, 256, OFF_T1 + 3 * 256 * 768);
        add(t2_wq, t2_wq, 256, 256, 256, OFF_T2 + 0 * 256 * 768);
        add(t2_wk, t2_wk, 256, 256, 256, OFF_T2 + 1 * 256 * 768);
        add(t2_wv, t2_wv, 256, 256, 256, OFF_T2 + 2 * 256 * 768);
        add(t2_ws, t2_ws, 256, 256, 256, OFF_T2 + 3 * 256 * 768);
        add(p1_w, p1_w, 256, 256, 512, OFF_P1);
        add(p2_w, p2_w, 512, 512, 128, OFF_P2);
        k_convW_all<<<(WTOTAL + 255) / 256, 256>>>(jobs);
    }

    // SAGE 1 input image (img0): mean(x) + x in one launch
    k_prep1<<<(NN * 32 + 255) / 256, 256>>>(x, d_i0);
    run_gemm(64, d_i0, d_W + OFF_S1, s1_bl, s1_bl, s1_bl, s1_bl,
             d_h1, 128, 256, 1, d_i1, 256, 128, nullptr, nullptr);

    // SAGE 2: mean(h1) -> img1[0:128); S2 -> img0[0:256)
    k_sage_agg<<<(NN * 32 + 255) / 256, 256>>>(d_h1, d_i1);
    run_gemm(64, d_i1, d_W + OFF_S2, s2_bl, s2_bl, s2_bl, s2_bl,
             nullptr, 256, 256, 1, d_i0, 256, 0, nullptr, nullptr);

    // TransformerConv 1
    run_gemm(128, d_i0, d_W + OFF_T1, t1_bq, t1_bk, t1_bv, t1_bs,
             d_qkvs, 1024, 256, 0, nullptr, 0, 0, nullptr, nullptr);
    k_attn<<<(NN * 32 + 255) / 256, 256>>>(d_qkvs, d_i1);

    // TransformerConv 2
    run_gemm(128, d_i1, d_W + OFF_T2, t2_bq, t2_bk, t2_bv, t2_bs,
             d_qkvs, 1024, 256, 0, nullptr, 0, 0, nullptr, nullptr);
    k_attn<<<(NN * 32 + 255) / 256, 256>>>(d_qkvs, d_i0);

    // proj MLP: P1 -> img1 (K=512 compact); P2 -> sigmoid + fused pool
    run_gemm(64, d_i0, d_W + OFF_P1, p1_b, p1_b + 256, p1_b, p1_b,
             nullptr, 512, 256, 1, d_i1, 512, 0, nullptr, nullptr);
    run_gemm(64, d_i1, d_W + OFF_P2, p2_b, p2_b, p2_b, p2_b,
             nullptr, 128, 512, 2, nullptr, 0, 0, batch, (float*)d_out);
}

// round 9
// speedup vs baseline: 1.0915x; 1.0197x over previous
#include <cuda_runtime.h>
#include <cuda_bf16.h>
#include <math.h>
#include <stdint.h>

#define NN 20000
#define EE 320000
#define GG 64
#define MPAD 20096          // 157 * 128
#define NTILES 157

// ---------------- device scratch ----------------
__device__ float g_h1[NN * 128];
__device__ float g_qkvs[(size_t)NN * 1024];
__device__ int g_deg[NN];
__device__ int g_fill[NN];
__device__ int g_rowptr[NN + 1];
__device__ int g_csrc[EE];

// ping-pong compact bf16 hi|lo A-images: [MPAD][2K], widest K=512 -> 1024 cols
__device__ __nv_bfloat16 g_img0[(size_t)MPAD * 1024];
__device__ __nv_bfloat16 g_img1[(size_t)MPAD * 1024];
__device__ __nv_bfloat16 g_Wbf[2457600];

// weight image offsets (elements), layout [Nc][3K] = hi|lo|hi
#define OFF_S1   0
#define OFF_S2   98304
#define OFF_T1   294912
#define OFF_T2   1081344
#define OFF_P1   1867776
#define OFF_P2   2260992

__device__ __forceinline__ uint32_t smem_u32(const void* p) {
    uint32_t a;
    asm("{ .reg .u64 t; cvta.to.shared.u64 t, %1; cvt.u32.u64 %0, t; }" : "=r"(a) : "l"(p));
    return a;
}
__device__ __forceinline__ void cpa16(uint32_t dst, const void* src) {
    asm volatile("cp.async.cg.shared.global [%0], [%1], 16;" :: "r"(dst), "l"(src));
}

// write 4 consecutive floats as hi @ c, lo @ K+c (compact image, row stride 2K)
__device__ __forceinline__ void img_write4(__nv_bfloat16* row, int K, int c, float4 v) {
    __nv_bfloat162 hh0, hh1, ll0, ll1;
    hh0.x = __float2bfloat16(v.x); hh0.y = __float2bfloat16(v.y);
    hh1.x = __float2bfloat16(v.z); hh1.y = __float2bfloat16(v.w);
    ll0.x = __float2bfloat16(v.x - __bfloat162float(hh0.x));
    ll0.y = __float2bfloat16(v.y - __bfloat162float(hh0.y));
    ll1.x = __float2bfloat16(v.z - __bfloat162float(hh1.x));
    ll1.y = __float2bfloat16(v.w - __bfloat162float(hh1.y));
    *(__nv_bfloat162*)(row + c) = hh0;     *(__nv_bfloat162*)(row + c + 2) = hh1;
    *(__nv_bfloat162*)(row + K + c) = ll0; *(__nv_bfloat162*)(row + K + c + 2) = ll1;
}

// ---------------- CSR build ----------------
__global__ void k_zero(float* out) {
    int i = blockIdx.x * blockDim.x + threadIdx.x;
    if (i < NN) { g_deg[i] = 0; g_fill[i] = 0; }
    if (i < GG * 128) out[i] = 0.0f;
}
__global__ void k_hist(const int* __restrict__ dst) {
    int e = blockIdx.x * blockDim.x + threadIdx.x;
    if (e < EE) atomicAdd(&g_deg[dst[e]], 1);
}
// fast scan: thread-serial partials (20/thread) + one 1024 Hillis-Steele
__global__ void k_scan() {
    __shared__ int sh[1024];
    const int PER = 20;  // 1024*20 >= NN
    int tid = threadIdx.x;
    int base = tid * PER;
    int local[PER];
    int sum = 0;
#pragma unroll
    for (int i = 0; i < PER; i++) {
        int idx = base + i;
        int v = (idx < NN) ? g_deg[idx] : 0;
        local[i] = sum;
        sum += v;
    }
    sh[tid] = sum;
    __syncthreads();
    for (int off = 1; off < 1024; off <<= 1) {
        int t = (tid >= off) ? sh[tid - off] : 0;
        __syncthreads();
        sh[tid] += t;
        __syncthreads();
    }
    int carry = (tid > 0) ? sh[tid - 1] : 0;
#pragma unroll
    for (int i = 0; i < PER; i++) {
        int idx = base + i;
        if (idx < NN) g_rowptr[idx] = carry + local[i];
    }
    if (tid == 1023) g_rowptr[NN] = sh[1023];
}
__global__ void k_scatter(const int* __restrict__ src, const int* __restrict__ dst) {
    int e = blockIdx.x * blockDim.x + threadIdx.x;
    if (e >= EE) return;
    int d = dst[e];
    int pos = atomicAdd(&g_fill[d], 1);
    g_csrc[g_rowptr[d] + pos] = src[e];
}

// ---------------- fused prep: sage mean (cols [0,128)) + x (cols [128,256)) ---
__global__ void k_prep1(const float* __restrict__ x, __nv_bfloat16* __restrict__ img) {
    int w = (blockIdx.x * blockDim.x + threadIdx.x) >> 5;
    int lane = threadIdx.x & 31;
    if (w >= NN) return;
    int beg = g_rowptr[w], end = g_rowptr[w + 1];
    float4 acc = make_float4(0.f, 0.f, 0.f, 0.f);
#pragma unroll 4
    for (int e = beg; e < end; e++) {
        int s = g_csrc[e];
        float4 xv = *(const float4*)(x + (size_t)s * 128 + lane * 4);
        acc.x += xv.x; acc.y += xv.y; acc.z += xv.z; acc.w += xv.w;
    }
    float inv = 1.0f / fmaxf((float)(end - beg), 1.0f);
    acc.x *= inv; acc.y *= inv; acc.z *= inv; acc.w *= inv;
    __nv_bfloat16* row = img + (size_t)w * 512;
    img_write4(row, 256, lane * 4, acc);
    float4 xo = *(const float4*)(x + (size_t)w * 128 + lane * 4);
    img_write4(row, 256, 128 + lane * 4, xo);
}

// ---------------- SAGE mean aggregation -> image cols [0,128) ----------------
__global__ void k_sage_agg(const float* __restrict__ x, __nv_bfloat16* __restrict__ img) {
    int w = (blockIdx.x * blockDim.x + threadIdx.x) >> 5;
    int lane = threadIdx.x & 31;
    if (w >= NN) return;
    int beg = g_rowptr[w], end = g_rowptr[w + 1];
    float4 acc = make_float4(0.f, 0.f, 0.f, 0.f);
#pragma unroll 4
    for (int e = beg; e < end; e++) {
        int s = g_csrc[e];
        float4 xv = *(const float4*)(x + (size_t)s * 128 + lane * 4);
        acc.x += xv.x; acc.y += xv.y; acc.z += xv.z; acc.w += xv.w;
    }
    float inv = 1.0f / fmaxf((float)(end - beg), 1.0f);
    acc.x *= inv; acc.y *= inv; acc.z *= inv; acc.w *= inv;
    img_write4(img + (size_t)w * 512, 256, lane * 4, acc);
}

// ---------------- fused weight conversion: all 12 tensors in one launch -------
struct WJob { const float *w1, *w2; int k1, K, nw, off, cumEnd; };
struct WJobs { WJob j[12]; };
#define WTOTAL 819200

__global__ void k_convW_all(WJobs jobs) {
    int idx = blockIdx.x * blockDim.x + threadIdx.x;
    if (idx >= WTOTAL) return;
    int s = 0;
    while (idx >= jobs.j[s].cumEnd) s++;
    const WJob J = jobs.j[s];
    int local = idx - (s ? jobs.j[s - 1].cumEnd : 0);
    int n = local / J.K;
    int k = local - n * J.K;
    float val = (k < J.k1) ? J.w1[(size_t)k * J.nw + n] : J.w2[(size_t)(k - J.k1) * J.nw + n];
    __nv_bfloat16 hi = __float2bfloat16(val);
    __nv_bfloat16 lo = __float2bfloat16(val - __bfloat162float(hi));
    __nv_bfloat16* row = g_Wbf + (size_t)J.off + (size_t)n * (3 * J.K);
    row[k] = hi;
    row[J.K + k] = lo;
    row[2 * J.K + k] = hi;
}

// ---------------- 3-stage pipelined mma.sync bf16 GEMM, templated BN ---------
// A compact [M][2K] hi|lo; W [Nc][3K] hi|lo|hi; logical K-tiles 3K/64.
// Race-free ordering: wait -> sync -> issue(c+2) -> compute(c).
#define NSTAGE 3

template <int BN>
__global__ void __launch_bounds__(256, 2)
gemm_mma(const __nv_bfloat16* __restrict__ A, const __nv_bfloat16* __restrict__ W,
         const float* __restrict__ b0, const float* __restrict__ b1,
         const float* __restrict__ b2, const float* __restrict__ b3,
         float* __restrict__ C, int Nc, int Kbase, int act,
         __nv_bfloat16* __restrict__ img, int imgK, int imgColOff,
         const int* __restrict__ batch, float* __restrict__ pool) {
    constexpr int STB = 16384 + BN * 128;       // A tile 16KB + B tile
    constexpr int MI = (BN == 128) ? 4 : 2;     // warp M sub-tiles (x16 rows)
    extern __shared__ char smem[];
    const int tid = threadIdx.x;
    const int wid = tid >> 5, lane = tid & 31;
    const int bm = blockIdx.y * 128;
    const int bn = blockIdx.x * BN;
    const int wm = (BN == 128) ? ((wid & 1) << 6) : ((wid & 3) << 5);
    const int wn = (BN == 128) ? ((wid >> 1) << 5) : ((wid >> 2) << 5);
    const uint32_t sb = smem_u32(smem);

    float acc[MI][4][4];
#pragma unroll
    for (int i = 0; i < MI; i++)
#pragma unroll
        for (int j = 0; j < 4; j++)
#pragma unroll
            for (int t = 0; t < 4; t++) acc[i][j][t] = 0.f;

    const int KA = Kbase >> 6;        // hi chunks
    const int nK = 3 * KA;            // logical k-tiles
    const int KtotW = 3 * Kbase;
    const int KtotA = 2 * Kbase;

    auto issue = [&](int c, int buf) {
        int ac = (c < KA) ? c : (c - KA);       // physical A chunk
        int ka0 = ac << 6;
        int kw0 = c << 6;
        uint32_t base = sb + buf * STB;
#pragma unroll
        for (int l = 0; l < 4; l++) {
            int idx = tid + l * 256;
            int row = idx >> 3, u = idx & 7;
            uint32_t sw = row * 128 + ((u ^ (row & 7)) << 4);
            cpa16(base + sw, A + (size_t)(bm + row) * KtotA + ka0 + u * 8);
        }
#pragma unroll
        for (int l = 0; l < BN / 32; l++) {
            int idx = tid + l * 256;
            int row = idx >> 3, u = idx & 7;
            uint32_t sw = row * 128 + ((u ^ (row & 7)) << 4);
            cpa16(base + 16384 + sw, W + (size_t)(bn + row) * KtotW + kw0 + u * 8);
        }
        asm volatile("cp.async.commit_group;" ::: "memory");
    };

    issue(0, 0);
    if (nK > 1) issue(1, 1);
    for (int c = 0; c < nK; c++) {
        if (c + 1 < nK) asm volatile("cp.async.wait_group 1;" ::: "memory");
        else            asm volatile("cp.async.wait_group 0;" ::: "memory");
        __syncthreads();          // retires all readers of buffer (c-1)%3
        if (c + 2 < nK) issue(c + 2, (c + 2) % NSTAGE);   // writes (c-1)%3: safe

        int buf = c % NSTAGE;
        uint32_t sAb = sb + buf * STB;
        uint32_t sBb = sAb + 16384;
#pragma unroll
        for (int s = 0; s < 4; s++) {
            uint32_t a[MI][4], b[4][2];
#pragma unroll
            for (int i = 0; i < MI; i++) {
                int row = wm + i * 16 + (lane & 15);
                int u = (s << 1) + (lane >> 4);
                uint32_t ad = sAb + row * 128 + ((u ^ (row & 7)) << 4);
                asm volatile("ldmatrix.sync.aligned.m8n8.x4.shared.b16 {%0,%1,%2,%3}, [%4];"
                    : "=r"(a[i][0]), "=r"(a[i][1]), "=r"(a[i][2]), "=r"(a[i][3]) : "r"(ad));
            }
#pragma unroll
            for (int jj = 0; jj < 2; jj++) {
                int row = wn + (jj << 4) + ((lane >> 4) << 3) + (lane & 7);
                int u = (s << 1) + ((lane >> 3) & 1);
                uint32_t ad = sBb + row * 128 + ((u ^ (row & 7)) << 4);
                asm volatile("ldmatrix.sync.aligned.m8n8.x4.shared.b16 {%0,%1,%2,%3}, [%4];"
                    : "=r"(b[jj * 2][0]), "=r"(b[jj * 2][1]),
                      "=r"(b[jj * 2 + 1][0]), "=r"(b[jj * 2 + 1][1]) : "r"(ad));
            }
#pragma unroll
            for (int i = 0; i < MI; i++)
#pragma unroll
                for (int j = 0; j < 4; j++)
                    asm volatile("mma.sync.aligned.m16n8k16.row.col.f32.bf16.bf16.f32 "
                        "{%0,%1,%2,%3}, {%4,%5,%6,%7}, {%8,%9}, {%0,%1,%2,%3};"
                        : "+f"(acc[i][j][0]), "+f"(acc[i][j][1]),
                          "+f"(acc[i][j][2]), "+f"(acc[i][j][3])
                        : "r"(a[i][0]), "r"(a[i][1]), "r"(a[i][2]), "r"(a[i][3]),
                          "r"(b[j][0]), "r"(b[j][1]));
        }
    }

    // epilogue
    const float* bsel[4] = {b0, b1, b2, b3};
    const int stride2K = 2 * imgK;
#pragma unroll
    for (int i = 0; i < MI; i++) {
        int r0 = bm + wm + i * 16 + (lane >> 2);
        int r1 = r0 + 8;
#pragma unroll
        for (int j = 0; j < 4; j++) {
            int c = bn + wn + (j << 3) + ((lane & 3) << 1);
            const float* bp = bsel[c >> 8];
            float bv0 = bp[c & 255], bv1 = bp[(c & 255) + 1];
            float v00 = acc[i][j][0] + bv0, v01 = acc[i][j][1] + bv1;
            float v10 = acc[i][j][2] + bv0, v11 = acc[i][j][3] + bv1;
            if (act == 1) {
                v00 = fmaxf(v00, 0.f); v01 = fmaxf(v01, 0.f);
                v10 = fmaxf(v10, 0.f); v11 = fmaxf(v11, 0.f);
            } else if (act == 2) {
                v00 = 1.f / (1.f + __expf(-v00)); v01 = 1.f / (1.f + __expf(-v01));
                v10 = 1.f / (1.f + __expf(-v10)); v11 = 1.f / (1.f + __expf(-v11));
            }
            if (C) {
                if (r0 < NN) { C[(size_t)r0 * Nc + c] = v00; C[(size_t)r0 * Nc + c + 1] = v01; }
                if (r1 < NN) { C[(size_t)r1 * Nc + c] = v10; C[(size_t)r1 * Nc + c + 1] = v11; }
            }
            if (img) {
                int ic = imgColOff + c;
                if (r0 < NN) {
                    __nv_bfloat16* row = img + (size_t)r0 * stride2K;
                    __nv_bfloat162 hh, ll;
                    hh.x = __float2bfloat16(v00); hh.y = __float2bfloat16(v01);
                    ll.x = __float2bfloat16(v00 - __bfloat162float(hh.x));
                    ll.y = __float2bfloat16(v01 - __bfloat162float(hh.y));
                    *(__nv_bfloat162*)(row + ic) = hh;
                    *(__nv_bfloat162*)(row + imgK + ic) = ll;
                }
                if (r1 < NN) {
                    __nv_bfloat16* row = img + (size_t)r1 * stride2K;
                    __nv_bfloat162 hh, ll;
                    hh.x = __float2bfloat16(v10); hh.y = __float2bfloat16(v11);
                    ll.x = __float2bfloat16(v10 - __bfloat162float(hh.x));
                    ll.y = __float2bfloat16(v11 - __bfloat162float(hh.y));
                    *(__nv_bfloat162*)(row + ic) = hh;
                    *(__nv_bfloat162*)(row + imgK + ic) = ll;
                }
            }
            if (pool) {
                if (r0 < NN) {
                    int g = batch[r0] * 128;
                    atomicMax((int*)&pool[g + c], __float_as_int(v00));
                    atomicMax((int*)&pool[g + c + 1], __float_as_int(v01));
                }
                if (r1 < NN) {
                    int g = batch[r1] * 128;
                    atomicMax((int*)&pool[g + c], __float_as_int(v10));
                    atomicMax((int*)&pool[g + c + 1], __float_as_int(v11));
                }
            }
        }
    }
}

// ---------------- attention: warp per node, 8 heads, pairwise edges ----------
__device__ __forceinline__ float dot4(float4 a, float4 b) {
    return a.x * b.x + a.y * b.y + a.z * b.z + a.w * b.w;
}

__global__ void k_attn(const float* __restrict__ qkvs, __nv_bfloat16* __restrict__ img) {
    int node = (blockIdx.x * blockDim.x + threadIdx.x) >> 5;
    if (node >= NN) return;
    int lane = threadIdx.x & 31;
    const float* base = qkvs + (size_t)node * 1024;
    float4 q0 = *(const float4*)(base + lane * 4);
    float4 q1 = *(const float4*)(base + 128 + lane * 4);
    int beg = g_rowptr[node], end = g_rowptr[node + 1];
    float m0 = -3.0e38f, s0 = 0.f, m1 = -3.0e38f, s1 = 0.f;
    float4 a0 = make_float4(0.f, 0.f, 0.f, 0.f);
    float4 a1 = make_float4(0.f, 0.f, 0.f, 0.f);
    const float scl = 0.17677669529663687f;
    int e = beg;
    for (; e + 1 < end; e += 2) {
        int sa = g_csrc[e], sbn = g_csrc[e + 1];
        const float* ka = qkvs + (size_t)sa * 1024 + 256;
        const float* kb = qkvs + (size_t)sbn * 1024 + 256;
        float4 ka0 = *(const float4*)(ka + lane * 4);
        float4 ka1 = *(const float4*)(ka + 128 + lane * 4);
        float4 va0 = *(const float4*)(ka + 256 + lane * 4);
        float4 va1 = *(const float4*)(ka + 384 + lane * 4);
        float4 kb0 = *(const float4*)(kb + lane * 4);
        float4 kb1 = *(const float4*)(kb + 128 + lane * 4);
        float4 vb0 = *(const float4*)(kb + 256 + lane * 4);
        float4 vb1 = *(const float4*)(kb + 384 + lane * 4);
        float da0 = dot4(q0, ka0), da1 = dot4(q1, ka1);
        float db0 = dot4(q0, kb0), db1 = dot4(q1, kb1);
#pragma unroll
        for (int off = 4; off; off >>= 1) {
            da0 += __shfl_xor_sync(0xffffffffu, da0, off);
            da1 += __shfl_xor_sync(0xffffffffu, da1, off);
            db0 += __shfl_xor_sync(0xffffffffu, db0, off);
            db1 += __shfl_xor_sync(0xffffffffu, db1, off);
        }
        da0 *= scl; da1 *= scl; db0 *= scl; db1 *= scl;
        // merged two-edge online softmax update, head group 0
        {
            float mn = fmaxf(m0, fmaxf(da0, db0));
            float sc = __expf(m0 - mn);
            float pa = __expf(da0 - mn);
            float pb = __expf(db0 - mn);
            s0 = s0 * sc + pa + pb;
            a0.x = a0.x * sc + pa * va0.x + pb * vb0.x;
            a0.y = a0.y * sc + pa * va0.y + pb * vb0.y;
            a0.z = a0.z * sc + pa * va0.z + pb * vb0.z;
            a0.w = a0.w * sc + pa * va0.w + pb * vb0.w;
            m0 = mn;
        }
        // head group 1
        {
            float mn = fmaxf(m1, fmaxf(da1, db1));
            float sc = __expf(m1 - mn);
            float pa = __expf(da1 - mn);
            float pb = __expf(db1 - mn);
            s1 = s1 * sc + pa + pb;
            a1.x = a1.x * sc + pa * va1.x + pb * vb1.x;
            a1.y = a1.y * sc + pa * va1.y + pb * vb1.y;
            a1.z = a1.z * sc + pa * va1.z + pb * vb1.z;
            a1.w = a1.w * sc + pa * va1.w + pb * vb1.w;
            m1 = mn;
        }
    }
    if (e < end) {   // tail edge
        int sn = g_csrc[e];
        const float* kb = qkvs + (size_t)sn * 1024 + 256;
        float4 k0 = *(const float4*)(kb + lane * 4);
        float4 k1 = *(const float4*)(kb + 128 + lane * 4);
        float4 v0 = *(const float4*)(kb + 256 + lane * 4);
        float4 v1 = *(const float4*)(kb + 384 + lane * 4);
        float d0 = dot4(q0, k0), d1 = dot4(q1, k1);
#pragma unroll
        for (int off = 4; off; off >>= 1) {
            d0 += __shfl_xor_sync(0xffffffffu, d0, off);
            d1 += __shfl_xor_sync(0xffffffffu, d1, off);
        }
        d0 *= scl; d1 *= scl;
        float mn0 = fmaxf(m0, d0);
        float sc0 = __expf(m0 - mn0);
        float p0 = __expf(d0 - mn0);
        s0 = s0 * sc0 + p0;
        a0.x = a0.x * sc0 + p0 * v0.x; a0.y = a0.y * sc0 + p0 * v0.y;
        a0.z = a0.z * sc0 + p0 * v0.z; a0.w = a0.w * sc0 + p0 * v0.w;
        m0 = mn0;
        float mn1 = fmaxf(m1, d1);
        float sc1 = __expf(m1 - mn1);
        float p1 = __expf(d1 - mn1);
        s1 = s1 * sc1 + p1;
        a1.x = a1.x * sc1 + p1 * v1.x; a1.y = a1.y * sc1 + p1 * v1.y;
        a1.z = a1.z * sc1 + p1 * v1.z; a1.w = a1.w * sc1 + p1 * v1.w;
        m1 = mn1;
    }
    float inv0 = (end > beg) ? (1.f / s0) : 0.f;
    float inv1 = (end > beg) ? (1.f / s1) : 0.f;
    const float* sk = base + 768;
    float4 sk0 = *(const float4*)(sk + lane * 4);
    float4 sk1 = *(const float4*)(sk + 128 + lane * 4);
    float4 o0, o1;
    o0.x = fmaxf(sk0.x + a0.x * inv0, 0.f); o0.y = fmaxf(sk0.y + a0.y * inv0, 0.f);
    o0.z = fmaxf(sk0.z + a0.z * inv0, 0.f); o0.w = fmaxf(sk0.w + a0.w * inv0, 0.f);
    o1.x = fmaxf(sk1.x + a1.x * inv1, 0.f); o1.y = fmaxf(sk1.y + a1.y * inv1, 0.f);
    o1.z = fmaxf(sk1.z + a1.z * inv1, 0.f); o1.w = fmaxf(sk1.w + a1.w * inv1, 0.f);
    __nv_bfloat16* row = img + (size_t)node * 512;
    img_write4(row, 256, lane * 4, o0);
    img_write4(row, 256, 128 + lane * 4, o1);
}

// ---------------- host orchestration ----------------
static void run_gemm(int bn, const __nv_bfloat16* A, const __nv_bfloat16* W,
                     const float* b0, const float* b1, const float* b2, const float* b3,
                     float* C, int Nc, int Kbase, int act,
                     __nv_bfloat16* img, int imgK, int imgColOff,
                     const int* batch, float* pool) {
    dim3 grid(Nc / bn, NTILES);
    if (bn == 64)
        gemm_mma<64><<<grid, 256, NSTAGE * (16384 + 64 * 128)>>>(A, W, b0, b1, b2, b3, C, Nc,
                                                                 Kbase, act, img, imgK,
                                                                 imgColOff, batch, pool);
    else
        gemm_mma<128><<<grid, 256, NSTAGE * (16384 + 128 * 128)>>>(A, W, b0, b1, b2, b3, C, Nc,
                                                                   Kbase, act, img, imgK,
                                                                   imgColOff, batch, pool);
}

extern "C" void kernel_launch(void* const* d_in, const int* in_sizes, int n_in,
                              void* d_out, int out_size) {
    const float* x     = (const float*)d_in[0];
    const int*   ei    = (const int*)d_in[1];
    const int*   batch = (const int*)d_in[2];
    const float* s1_wl = (const float*)d_in[3];
    const float* s1_bl = (const float*)d_in[4];
    const float* s1_wr = (const float*)d_in[5];
    const float* s2_wl = (const float*)d_in[6];
    const float* s2_bl = (const float*)d_in[7];
    const float* s2_wr = (const float*)d_in[8];
    const float* t1_wq = (const float*)d_in[9];
    const float* t1_bq = (const float*)d_in[10];
    const float* t1_wk = (const float*)d_in[11];
    const float* t1_bk = (const float*)d_in[12];
    const float* t1_wv = (const float*)d_in[13];
    const float* t1_bv = (const float*)d_in[14];
    const float* t1_ws = (const float*)d_in[15];
    const float* t1_bs = (const float*)d_in[16];
    const float* t2_wq = (const float*)d_in[17];
    const float* t2_bq = (const float*)d_in[18];
    const float* t2_wk = (const float*)d_in[19];
    const float* t2_bk = (const float*)d_in[20];
    const float* t2_wv = (const float*)d_in[21];
    const float* t2_bv = (const float*)d_in[22];
    const float* t2_ws = (const float*)d_in[23];
    const float* t2_bs = (const float*)d_in[24];
    const float* p1_w  = (const float*)d_in[25];
    const float* p1_b  = (const float*)d_in[26];
    const float* p2_w  = (const float*)d_in[27];
    const float* p2_b  = (const float*)d_in[28];

    const int* e_src = ei;
    const int* e_dst = ei + EE;

    cudaFuncSetAttribute(gemm_mma<128>, cudaFuncAttributeMaxDynamicSharedMemorySize,
                         NSTAGE * (16384 + 128 * 128));
    cudaFuncSetAttribute(gemm_mma<64>, cudaFuncAttributeMaxDynamicSharedMemorySize,
                         NSTAGE * (16384 + 64 * 128));

    float *d_h1, *d_qkvs;
    __nv_bfloat16 *d_i0, *d_i1, *d_W;
    cudaGetSymbolAddress((void**)&d_h1, g_h1);
    cudaGetSymbolAddress((void**)&d_qkvs, g_qkvs);
    cudaGetSymbolAddress((void**)&d_i0, g_img0);
    cudaGetSymbolAddress((void**)&d_i1, g_img1);
    cudaGetSymbolAddress((void**)&d_W, g_Wbf);

    // CSR build
    k_zero<<<(NN + 255) / 256, 256>>>((float*)d_out);
    k_hist<<<(EE + 255) / 256, 256>>>(e_dst);
    k_scan<<<1, 1024>>>();
    k_scatter<<<(EE + 255) / 256, 256>>>(e_src, e_dst);

    // fused weight conversion (one launch for all 12 tensors)
    {
        WJobs jobs;
        int cum = 0, idx = 0;
        auto add = [&](const float* w1, const float* w2, int k1, int K, int nw, int off) {
            cum += nw * K;
            jobs.j[idx++] = WJob{w1, w2, k1, K, nw, off, cum};
        };
        add(s1_wl, s1_wr, 128, 256, 128, OFF_S1);
        add(s2_wl, s2_wr, 128, 256, 256, OFF_S2);
        add(t1_wq, t1_wq, 256, 256, 256, OFF_T1 + 0 * 256 * 768);
        add(t1_wk, t1_wk, 256, 256, 256, OFF_T1 + 1 * 256 * 768);
        add(t1_wv, t1_wv, 256, 256, 256, OFF_T1 + 2 * 256 * 768);
        add(t1_ws, t1_ws, 256, 256, 256, OFF_T1 + 3 * 256 * 768);
        add(t2_wq, t2_wq, 256, 256, 256, OFF_T2 + 0 * 256 * 768);
        add(t2_wk, t2_wk, 256, 256, 256, OFF_T2 + 1 * 256 * 768);
        add(t2_wv, t2_wv, 256, 256, 256, OFF_T2 + 2 * 256 * 768);
        add(t2_ws, t2_ws, 256, 256, 256, OFF_T2 + 3 * 256 * 768);
        add(p1_w, p1_w, 256, 256, 512, OFF_P1);
        add(p2_w, p2_w, 512, 512, 128, OFF_P2);
        k_convW_all<<<(WTOTAL + 255) / 256, 256>>>(jobs);
    }

    // SAGE 1 input image (img0): mean(x) + x in one launch
    k_prep1<<<(NN * 32 + 255) / 256, 256>>>(x, d_i0);
    run_gemm(64, d_i0, d_W + OFF_S1, s1_bl, s1_bl, s1_bl, s1_bl,
             d_h1, 128, 256, 1, d_i1, 256, 128, nullptr, nullptr);

    // SAGE 2: mean(h1) -> img1[0:128); S2 -> img0[0:256)
    k_sage_agg<<<(NN * 32 + 255) / 256, 256>>>(d_h1, d_i1);
    run_gemm(64, d_i1, d_W + OFF_S2, s2_bl, s2_bl, s2_bl, s2_bl,
             nullptr, 256, 256, 1, d_i0, 256, 0, nullptr, nullptr);

    // TransformerConv 1
    run_gemm(128, d_i0, d_W + OFF_T1, t1_bq, t1_bk, t1_bv, t1_bs,
             d_qkvs, 1024, 256, 0, nullptr, 0, 0, nullptr, nullptr);
    k_attn<<<(NN * 32 + 255) / 256, 256>>>(d_qkvs, d_i1);

    // TransformerConv 2
    run_gemm(128, d_i1, d_W + OFF_T2, t2_bq, t2_bk, t2_bv, t2_bs,
             d_qkvs, 1024, 256, 0, nullptr, 0, 0, nullptr, nullptr);
    k_attn<<<(NN * 32 + 255) / 256, 256>>>(d_qkvs, d_i0);

    // proj MLP: P1 -> img1 (K=512 compact); P2 -> sigmoid + fused pool
    run_gemm(64, d_i0, d_W + OFF_P1, p1_b, p1_b + 256, p1_b, p1_b,
             nullptr, 512, 256, 1, d_i1, 512, 0, nullptr, nullptr);
    run_gemm(64, d_i1, d_W + OFF_P2, p2_b, p2_b, p2_b, p2_b,
             nullptr, 128, 512, 2, nullptr, 0, 0, batch, (float*)d_out);
}

// round 10
// speedup vs baseline: 1.1363x; 1.0410x over previous
#include <cuda_runtime.h>
#include <cuda_bf16.h>
#include <cuda_fp16.h>
#include <math.h>
#include <stdint.h>

#define NN 20000
#define EE 320000
#define GG 64
#define MPAD 20096          // 157 * 128
#define NTILES 157

// ---------------- device scratch ----------------
__device__ float g_h1[NN * 128];
__device__ float g_qkvs[(size_t)NN * 1024];   // q [0,256), skip [768,1024) fp32
__device__ __half g_kvh[(size_t)NN * 512];    // k [0,256), v [256,512) fp16
__device__ int g_deg[NN];
__device__ int g_fill[NN];
__device__ int g_rowptr[NN + 1];
__device__ int g_csrc[EE];

// ping-pong compact bf16 hi|lo A-images: [MPAD][2K], widest K=512 -> 1024 cols
__device__ __nv_bfloat16 g_img0[(size_t)MPAD * 1024];
__device__ __nv_bfloat16 g_img1[(size_t)MPAD * 1024];
__device__ __nv_bfloat16 g_Wbf[2457600];

// weight image offsets (elements), layout [Nc][3K] = hi|lo|hi
#define OFF_S1   0
#define OFF_S2   98304
#define OFF_T1   294912
#define OFF_T2   1081344
#define OFF_P1   1867776
#define OFF_P2   2260992

__device__ __forceinline__ uint32_t smem_u32(const void* p) {
    uint32_t a;
    asm("{ .reg .u64 t; cvta.to.shared.u64 t, %1; cvt.u32.u64 %0, t; }" : "=r"(a) : "l"(p));
    return a;
}
__device__ __forceinline__ void cpa16(uint32_t dst, const void* src) {
    asm volatile("cp.async.cg.shared.global [%0], [%1], 16;" :: "r"(dst), "l"(src));
}

// write 4 consecutive floats as hi @ c, lo @ K+c (compact image, row stride 2K)
__device__ __forceinline__ void img_write4(__nv_bfloat16* row, int K, int c, float4 v) {
    __nv_bfloat162 hh0, hh1, ll0, ll1;
    hh0.x = __float2bfloat16(v.x); hh0.y = __float2bfloat16(v.y);
    hh1.x = __float2bfloat16(v.z); hh1.y = __float2bfloat16(v.w);
    ll0.x = __float2bfloat16(v.x - __bfloat162float(hh0.x));
    ll0.y = __float2bfloat16(v.y - __bfloat162float(hh0.y));
    ll1.x = __float2bfloat16(v.z - __bfloat162float(hh1.x));
    ll1.y = __float2bfloat16(v.w - __bfloat162float(hh1.y));
    *(__nv_bfloat162*)(row + c) = hh0;     *(__nv_bfloat162*)(row + c + 2) = hh1;
    *(__nv_bfloat162*)(row + K + c) = ll0; *(__nv_bfloat162*)(row + K + c + 2) = ll1;
}

// load 4 consecutive fp16 values as float4
__device__ __forceinline__ float4 ldkv4(const __half* p) {
    uint2 u = *(const uint2*)p;
    __half2 a = *reinterpret_cast<const __half2*>(&u.x);
    __half2 b = *reinterpret_cast<const __half2*>(&u.y);
    float2 fa = __half22float2(a), fb = __half22float2(b);
    return make_float4(fa.x, fa.y, fb.x, fb.y);
}

// ---------------- CSR build ----------------
__global__ void k_zero(float* out) {
    int i = blockIdx.x * blockDim.x + threadIdx.x;
    if (i < NN) { g_deg[i] = 0; g_fill[i] = 0; }
    if (i < GG * 128) out[i] = 0.0f;
}
__global__ void k_hist(const int* __restrict__ dst) {
    int e = blockIdx.x * blockDim.x + threadIdx.x;
    if (e < EE) atomicAdd(&g_deg[dst[e]], 1);
}
// fast scan: thread-serial partials (20/thread) + one 1024 Hillis-Steele
__global__ void k_scan() {
    __shared__ int sh[1024];
    const int PER = 20;  // 1024*20 >= NN
    int tid = threadIdx.x;
    int base = tid * PER;
    int local[PER];
    int sum = 0;
#pragma unroll
    for (int i = 0; i < PER; i++) {
        int idx = base + i;
        int v = (idx < NN) ? g_deg[idx] : 0;
        local[i] = sum;
        sum += v;
    }
    sh[tid] = sum;
    __syncthreads();
    for (int off = 1; off < 1024; off <<= 1) {
        int t = (tid >= off) ? sh[tid - off] : 0;
        __syncthreads();
        sh[tid] += t;
        __syncthreads();
    }
    int carry = (tid > 0) ? sh[tid - 1] : 0;
#pragma unroll
    for (int i = 0; i < PER; i++) {
        int idx = base + i;
        if (idx < NN) g_rowptr[idx] = carry + local[i];
    }
    if (tid == 1023) g_rowptr[NN] = sh[1023];
}
__global__ void k_scatter(const int* __restrict__ src, const int* __restrict__ dst) {
    int e = blockIdx.x * blockDim.x + threadIdx.x;
    if (e >= EE) return;
    int d = dst[e];
    int pos = atomicAdd(&g_fill[d], 1);
    g_csrc[g_rowptr[d] + pos] = src[e];
}

// ---------------- fused prep: sage mean (cols [0,128)) + x (cols [128,256)) ---
__global__ void k_prep1(const float* __restrict__ x, __nv_bfloat16* __restrict__ img) {
    int w = (blockIdx.x * blockDim.x + threadIdx.x) >> 5;
    int lane = threadIdx.x & 31;
    if (w >= NN) return;
    int beg = g_rowptr[w], end = g_rowptr[w + 1];
    float4 acc = make_float4(0.f, 0.f, 0.f, 0.f);
#pragma unroll 4
    for (int e = beg; e < end; e++) {
        int s = g_csrc[e];
        float4 xv = *(const float4*)(x + (size_t)s * 128 + lane * 4);
        acc.x += xv.x; acc.y += xv.y; acc.z += xv.z; acc.w += xv.w;
    }
    float inv = 1.0f / fmaxf((float)(end - beg), 1.0f);
    acc.x *= inv; acc.y *= inv; acc.z *= inv; acc.w *= inv;
    __nv_bfloat16* row = img + (size_t)w * 512;
    img_write4(row, 256, lane * 4, acc);
    float4 xo = *(const float4*)(x + (size_t)w * 128 + lane * 4);
    img_write4(row, 256, 128 + lane * 4, xo);
}

// ---------------- SAGE mean aggregation -> image cols [0,128) ----------------
__global__ void k_sage_agg(const float* __restrict__ x, __nv_bfloat16* __restrict__ img) {
    int w = (blockIdx.x * blockDim.x + threadIdx.x) >> 5;
    int lane = threadIdx.x & 31;
    if (w >= NN) return;
    int beg = g_rowptr[w], end = g_rowptr[w + 1];
    float4 acc = make_float4(0.f, 0.f, 0.f, 0.f);
#pragma unroll 4
    for (int e = beg; e < end; e++) {
        int s = g_csrc[e];
        float4 xv = *(const float4*)(x + (size_t)s * 128 + lane * 4);
        acc.x += xv.x; acc.y += xv.y; acc.z += xv.z; acc.w += xv.w;
    }
    float inv = 1.0f / fmaxf((float)(end - beg), 1.0f);
    acc.x *= inv; acc.y *= inv; acc.z *= inv; acc.w *= inv;
    img_write4(img + (size_t)w * 512, 256, lane * 4, acc);
}

// ---------------- fused weight conversion: all 12 tensors in one launch -------
struct WJob { const float *w1, *w2; int k1, K, nw, off, cumEnd; };
struct WJobs { WJob j[12]; };
#define WTOTAL 819200

__global__ void k_convW_all(WJobs jobs) {
    int idx = blockIdx.x * blockDim.x + threadIdx.x;
    if (idx >= WTOTAL) return;
    int s = 0;
    while (idx >= jobs.j[s].cumEnd) s++;
    const WJob J = jobs.j[s];
    int local = idx - (s ? jobs.j[s - 1].cumEnd : 0);
    int n = local / J.K;
    int k = local - n * J.K;
    float val = (k < J.k1) ? J.w1[(size_t)k * J.nw + n] : J.w2[(size_t)(k - J.k1) * J.nw + n];
    __nv_bfloat16 hi = __float2bfloat16(val);
    __nv_bfloat16 lo = __float2bfloat16(val - __bfloat162float(hi));
    __nv_bfloat16* row = g_Wbf + (size_t)J.off + (size_t)n * (3 * J.K);
    row[k] = hi;
    row[J.K + k] = lo;
    row[2 * J.K + k] = hi;
}

// ---------------- 3-stage pipelined mma.sync bf16 GEMM, templated BN ---------
// A compact [M][2K] hi|lo; W [Nc][3K] hi|lo|hi; logical K-tiles 3K/64.
#define NSTAGE 3

template <int BN>
__global__ void __launch_bounds__(256, 2)
gemm_mma(const __nv_bfloat16* __restrict__ A, const __nv_bfloat16* __restrict__ W,
         const float* __restrict__ b0, const float* __restrict__ b1,
         const float* __restrict__ b2, const float* __restrict__ b3,
         float* __restrict__ C, int Nc, int Kbase, int act,
         __nv_bfloat16* __restrict__ img, int imgK, int imgColOff,
         const int* __restrict__ batch, float* __restrict__ pool,
         __half* __restrict__ kvh) {
    constexpr int STB = 16384 + BN * 128;       // A tile 16KB + B tile
    constexpr int MI = (BN == 128) ? 4 : 2;     // warp M sub-tiles (x16 rows)
    extern __shared__ char smem[];
    const int tid = threadIdx.x;
    const int wid = tid >> 5, lane = tid & 31;
    const int bm = blockIdx.y * 128;
    const int bn = blockIdx.x * BN;
    const int wm = (BN == 128) ? ((wid & 1) << 6) : ((wid & 3) << 5);
    const int wn = (BN == 128) ? ((wid >> 1) << 5) : ((wid >> 2) << 5);
    const uint32_t sb = smem_u32(smem);

    float acc[MI][4][4];
#pragma unroll
    for (int i = 0; i < MI; i++)
#pragma unroll
        for (int j = 0; j < 4; j++)
#pragma unroll
            for (int t = 0; t < 4; t++) acc[i][j][t] = 0.f;

    const int KA = Kbase >> 6;        // hi chunks
    const int nK = 3 * KA;            // logical k-tiles
    const int KtotW = 3 * Kbase;
    const int KtotA = 2 * Kbase;

    auto issue = [&](int c, int buf) {
        int ac = (c < KA) ? c : (c - KA);       // physical A chunk
        int ka0 = ac << 6;
        int kw0 = c << 6;
        uint32_t base = sb + buf * STB;
#pragma unroll
        for (int l = 0; l < 4; l++) {
            int idx = tid + l * 256;
            int row = idx >> 3, u = idx & 7;
            uint32_t sw = row * 128 + ((u ^ (row & 7)) << 4);
            cpa16(base + sw, A + (size_t)(bm + row) * KtotA + ka0 + u * 8);
        }
#pragma unroll
        for (int l = 0; l < BN / 32; l++) {
            int idx = tid + l * 256;
            int row = idx >> 3, u = idx & 7;
            uint32_t sw = row * 128 + ((u ^ (row & 7)) << 4);
            cpa16(base + 16384 + sw, W + (size_t)(bn + row) * KtotW + kw0 + u * 8);
        }
        asm volatile("cp.async.commit_group;" ::: "memory");
    };

    issue(0, 0);
    if (nK > 1) issue(1, 1);
    for (int c = 0; c < nK; c++) {
        if (c + 1 < nK) asm volatile("cp.async.wait_group 1;" ::: "memory");
        else            asm volatile("cp.async.wait_group 0;" ::: "memory");
        __syncthreads();          // retires all readers of buffer (c-1)%3
        if (c + 2 < nK) issue(c + 2, (c + 2) % NSTAGE);   // writes (c-1)%3: safe

        int buf = c % NSTAGE;
        uint32_t sAb = sb + buf * STB;
        uint32_t sBb = sAb + 16384;
#pragma unroll
        for (int s = 0; s < 4; s++) {
            uint32_t a[MI][4], b[4][2];
#pragma unroll
            for (int i = 0; i < MI; i++) {
                int row = wm + i * 16 + (lane & 15);
                int u = (s << 1) + (lane >> 4);
                uint32_t ad = sAb + row * 128 + ((u ^ (row & 7)) << 4);
                asm volatile("ldmatrix.sync.aligned.m8n8.x4.shared.b16 {%0,%1,%2,%3}, [%4];"
                    : "=r"(a[i][0]), "=r"(a[i][1]), "=r"(a[i][2]), "=r"(a[i][3]) : "r"(ad));
            }
#pragma unroll
            for (int jj = 0; jj < 2; jj++) {
                int row = wn + (jj << 4) + ((lane >> 4) << 3) + (lane & 7);
                int u = (s << 1) + ((lane >> 3) & 1);
                uint32_t ad = sBb + row * 128 + ((u ^ (row & 7)) << 4);
                asm volatile("ldmatrix.sync.aligned.m8n8.x4.shared.b16 {%0,%1,%2,%3}, [%4];"
                    : "=r"(b[jj * 2][0]), "=r"(b[jj * 2][1]),
                      "=r"(b[jj * 2 + 1][0]), "=r"(b[jj * 2 + 1][1]) : "r"(ad));
            }
#pragma unroll
            for (int i = 0; i < MI; i++)
#pragma unroll
                for (int j = 0; j < 4; j++)
                    asm volatile("mma.sync.aligned.m16n8k16.row.col.f32.bf16.bf16.f32 "
                        "{%0,%1,%2,%3}, {%4,%5,%6,%7}, {%8,%9}, {%0,%1,%2,%3};"
                        : "+f"(acc[i][j][0]), "+f"(acc[i][j][1]),
                          "+f"(acc[i][j][2]), "+f"(acc[i][j][3])
                        : "r"(a[i][0]), "r"(a[i][1]), "r"(a[i][2]), "r"(a[i][3]),
                          "r"(b[j][0]), "r"(b[j][1]));
        }
    }

    // epilogue
    const float* bsel[4] = {b0, b1, b2, b3};
    const int stride2K = 2 * imgK;
#pragma unroll
    for (int i = 0; i < MI; i++) {
        int r0 = bm + wm + i * 16 + (lane >> 2);
        int r1 = r0 + 8;
#pragma unroll
        for (int j = 0; j < 4; j++) {
            int c = bn + wn + (j << 3) + ((lane & 3) << 1);
            const float* bp = bsel[c >> 8];
            float bv0 = bp[c & 255], bv1 = bp[(c & 255) + 1];
            float v00 = acc[i][j][0] + bv0, v01 = acc[i][j][1] + bv1;
            float v10 = acc[i][j][2] + bv0, v11 = acc[i][j][3] + bv1;
            if (act == 1) {
                v00 = fmaxf(v00, 0.f); v01 = fmaxf(v01, 0.f);
                v10 = fmaxf(v10, 0.f); v11 = fmaxf(v11, 0.f);
            } else if (act == 2) {
                v00 = 1.f / (1.f + __expf(-v00)); v01 = 1.f / (1.f + __expf(-v01));
                v10 = 1.f / (1.f + __expf(-v10)); v11 = 1.f / (1.f + __expf(-v11));
            }
            bool kvcol = (kvh != nullptr) && (c >= 256) && (c < 768);
            if (kvcol) {
                // k/v columns -> fp16 packed buffer only
                int lc = c - 256;
                if (r0 < NN)
                    *(__half2*)(kvh + (size_t)r0 * 512 + lc) = __floats2half2_rn(v00, v01);
                if (r1 < NN)
                    *(__half2*)(kvh + (size_t)r1 * 512 + lc) = __floats2half2_rn(v10, v11);
            } else if (C) {
                if (r0 < NN) { C[(size_t)r0 * Nc + c] = v00; C[(size_t)r0 * Nc + c + 1] = v01; }
                if (r1 < NN) { C[(size_t)r1 * Nc + c] = v10; C[(size_t)r1 * Nc + c + 1] = v11; }
            }
            if (img) {
                int ic = imgColOff + c;
                if (r0 < NN) {
                    __nv_bfloat16* row = img + (size_t)r0 * stride2K;
                    __nv_bfloat162 hh, ll;
                    hh.x = __float2bfloat16(v00); hh.y = __float2bfloat16(v01);
                    ll.x = __float2bfloat16(v00 - __bfloat162float(hh.x));
                    ll.y = __float2bfloat16(v01 - __bfloat162float(hh.y));
                    *(__nv_bfloat162*)(row + ic) = hh;
                    *(__nv_bfloat162*)(row + imgK + ic) = ll;
                }
                if (r1 < NN) {
                    __nv_bfloat16* row = img + (size_t)r1 * stride2K;
                    __nv_bfloat162 hh, ll;
                    hh.x = __float2bfloat16(v10); hh.y = __float2bfloat16(v11);
                    ll.x = __float2bfloat16(v10 - __bfloat162float(hh.x));
                    ll.y = __float2bfloat16(v11 - __bfloat162float(hh.y));
                    *(__nv_bfloat162*)(row + ic) = hh;
                    *(__nv_bfloat162*)(row + imgK + ic) = ll;
                }
            }
            if (pool) {
                if (r0 < NN) {
                    int g = batch[r0] * 128;
                    atomicMax((int*)&pool[g + c], __float_as_int(v00));
                    atomicMax((int*)&pool[g + c + 1], __float_as_int(v01));
                }
                if (r1 < NN) {
                    int g = batch[r1] * 128;
                    atomicMax((int*)&pool[g + c], __float_as_int(v10));
                    atomicMax((int*)&pool[g + c + 1], __float_as_int(v11));
                }
            }
        }
    }
}

// ---------------- attention: warp per node, 8 heads, pairwise fp16 k/v -------
__device__ __forceinline__ float dot4(float4 a, float4 b) {
    return a.x * b.x + a.y * b.y + a.z * b.z + a.w * b.w;
}

__global__ void k_attn(const float* __restrict__ qkvs, const __half* __restrict__ kvh,
                       __nv_bfloat16* __restrict__ img) {
    int node = (blockIdx.x * blockDim.x + threadIdx.x) >> 5;
    if (node >= NN) return;
    int lane = threadIdx.x & 31;
    const float* base = qkvs + (size_t)node * 1024;
    const float scl = 0.17677669529663687f;
    float4 q0 = *(const float4*)(base + lane * 4);
    float4 q1 = *(const float4*)(base + 128 + lane * 4);
    q0.x *= scl; q0.y *= scl; q0.z *= scl; q0.w *= scl;
    q1.x *= scl; q1.y *= scl; q1.z *= scl; q1.w *= scl;
    int beg = g_rowptr[node], end = g_rowptr[node + 1];
    float m0 = -3.0e38f, s0 = 0.f, m1 = -3.0e38f, s1 = 0.f;
    float4 a0 = make_float4(0.f, 0.f, 0.f, 0.f);
    float4 a1 = make_float4(0.f, 0.f, 0.f, 0.f);
    int e = beg;
    for (; e + 1 < end; e += 2) {
        int sa = g_csrc[e], sbn = g_csrc[e + 1];
        const __half* ka = kvh + (size_t)sa * 512;
        const __half* kb = kvh + (size_t)sbn * 512;
        float4 ka0 = ldkv4(ka + lane * 4);
        float4 ka1 = ldkv4(ka + 128 + lane * 4);
        float4 va0 = ldkv4(ka + 256 + lane * 4);
        float4 va1 = ldkv4(ka + 384 + lane * 4);
        float4 kb0 = ldkv4(kb + lane * 4);
        float4 kb1 = ldkv4(kb + 128 + lane * 4);
        float4 vb0 = ldkv4(kb + 256 + lane * 4);
        float4 vb1 = ldkv4(kb + 384 + lane * 4);
        float da0 = dot4(q0, ka0), da1 = dot4(q1, ka1);
        float db0 = dot4(q0, kb0), db1 = dot4(q1, kb1);
#pragma unroll
        for (int off = 4; off; off >>= 1) {
            da0 += __shfl_xor_sync(0xffffffffu, da0, off);
            da1 += __shfl_xor_sync(0xffffffffu, da1, off);
            db0 += __shfl_xor_sync(0xffffffffu, db0, off);
            db1 += __shfl_xor_sync(0xffffffffu, db1, off);
        }
        {
            float mn = fmaxf(m0, fmaxf(da0, db0));
            float sc = __expf(m0 - mn);
            float pa = __expf(da0 - mn);
            float pb = __expf(db0 - mn);
            s0 = s0 * sc + pa + pb;
            a0.x = a0.x * sc + pa * va0.x + pb * vb0.x;
            a0.y = a0.y * sc + pa * va0.y + pb * vb0.y;
            a0.z = a0.z * sc + pa * va0.z + pb * vb0.z;
            a0.w = a0.w * sc + pa * va0.w + pb * vb0.w;
            m0 = mn;
        }
        {
            float mn = fmaxf(m1, fmaxf(da1, db1));
            float sc = __expf(m1 - mn);
            float pa = __expf(da1 - mn);
            float pb = __expf(db1 - mn);
            s1 = s1 * sc + pa + pb;
            a1.x = a1.x * sc + pa * va1.x + pb * vb1.x;
            a1.y = a1.y * sc + pa * va1.y + pb * vb1.y;
            a1.z = a1.z * sc + pa * va1.z + pb * vb1.z;
            a1.w = a1.w * sc + pa * va1.w + pb * vb1.w;
            m1 = mn;
        }
    }
    if (e < end) {   // tail edge
        int sn = g_csrc[e];
        const __half* kb = kvh + (size_t)sn * 512;
        float4 k0 = ldkv4(kb + lane * 4);
        float4 k1 = ldkv4(kb + 128 + lane * 4);
        float4 v0 = ldkv4(kb + 256 + lane * 4);
        float4 v1 = ldkv4(kb + 384 + lane * 4);
        float d0 = dot4(q0, k0), d1 = dot4(q1, k1);
#pragma unroll
        for (int off = 4; off; off >>= 1) {
            d0 += __shfl_xor_sync(0xffffffffu, d0, off);
            d1 += __shfl_xor_sync(0xffffffffu, d1, off);
        }
        float mn0 = fmaxf(m0, d0);
        float sc0 = __expf(m0 - mn0);
        float p0 = __expf(d0 - mn0);
        s0 = s0 * sc0 + p0;
        a0.x = a0.x * sc0 + p0 * v0.x; a0.y = a0.y * sc0 + p0 * v0.y;
        a0.z = a0.z * sc0 + p0 * v0.z; a0.w = a0.w * sc0 + p0 * v0.w;
        m0 = mn0;
        float mn1 = fmaxf(m1, d1);
        float sc1 = __expf(m1 - mn1);
        float p1 = __expf(d1 - mn1);
        s1 = s1 * sc1 + p1;
        a1.x = a1.x * sc1 + p1 * v1.x; a1.y = a1.y * sc1 + p1 * v1.y;
        a1.z = a1.z * sc1 + p1 * v1.z; a1.w = a1.w * sc1 + p1 * v1.w;
        m1 = mn1;
    }
    float inv0 = (end > beg) ? (1.f / s0) : 0.f;
    float inv1 = (end > beg) ? (1.f / s1) : 0.f;
    const float* sk = base + 768;
    float4 sk0 = *(const float4*)(sk + lane * 4);
    float4 sk1 = *(const float4*)(sk + 128 + lane * 4);
    float4 o0, o1;
    o0.x = fmaxf(sk0.x + a0.x * inv0, 0.f); o0.y = fmaxf(sk0.y + a0.y * inv0, 0.f);
    o0.z = fmaxf(sk0.z + a0.z * inv0, 0.f); o0.w = fmaxf(sk0.w + a0.w * inv0, 0.f);
    o1.x = fmaxf(sk1.x + a1.x * inv1, 0.f); o1.y = fmaxf(sk1.y + a1.y * inv1, 0.f);
    o1.z = fmaxf(sk1.z + a1.z * inv1, 0.f); o1.w = fmaxf(sk1.w + a1.w * inv1, 0.f);
    __nv_bfloat16* row = img + (size_t)node * 512;
    img_write4(row, 256, lane * 4, o0);
    img_write4(row, 256, 128 + lane * 4, o1);
}

// ---------------- host orchestration ----------------
static void run_gemm(int bn, const __nv_bfloat16* A, const __nv_bfloat16* W,
                     const float* b0, const float* b1, const float* b2, const float* b3,
                     float* C, int Nc, int Kbase, int act,
                     __nv_bfloat16* img, int imgK, int imgColOff,
                     const int* batch, float* pool, __half* kvh) {
    dim3 grid(Nc / bn, NTILES);
    if (bn == 64)
        gemm_mma<64><<<grid, 256, NSTAGE * (16384 + 64 * 128)>>>(A, W, b0, b1, b2, b3, C, Nc,
                                                                 Kbase, act, img, imgK,
                                                                 imgColOff, batch, pool, kvh);
    else
        gemm_mma<128><<<grid, 256, NSTAGE * (16384 + 128 * 128)>>>(A, W, b0, b1, b2, b3, C, Nc,
                                                                   Kbase, act, img, imgK,
                                                                   imgColOff, batch, pool, kvh);
}

extern "C" void kernel_launch(void* const* d_in, const int* in_sizes, int n_in,
                              void* d_out, int out_size) {
    const float* x     = (const float*)d_in[0];
    const int*   ei    = (const int*)d_in[1];
    const int*   batch = (const int*)d_in[2];
    const float* s1_wl = (const float*)d_in[3];
    const float* s1_bl = (const float*)d_in[4];
    const float* s1_wr = (const float*)d_in[5];
    const float* s2_wl = (const float*)d_in[6];
    const float* s2_bl = (const float*)d_in[7];
    const float* s2_wr = (const float*)d_in[8];
    const float* t1_wq = (const float*)d_in[9];
    const float* t1_bq = (const float*)d_in[10];
    const float* t1_wk = (const float*)d_in[11];
    const float* t1_bk = (const float*)d_in[12];
    const float* t1_wv = (const float*)d_in[13];
    const float* t1_bv = (const float*)d_in[14];
    const float* t1_ws = (const float*)d_in[15];
    const float* t1_bs = (const float*)d_in[16];
    const float* t2_wq = (const float*)d_in[17];
    const float* t2_bq = (const float*)d_in[18];
    const float* t2_wk = (const float*)d_in[19];
    const float* t2_bk = (const float*)d_in[20];
    const float* t2_wv = (const float*)d_in[21];
    const float* t2_bv = (const float*)d_in[22];
    const float* t2_ws = (const float*)d_in[23];
    const float* t2_bs = (const float*)d_in[24];
    const float* p1_w  = (const float*)d_in[25];
    const float* p1_b  = (const float*)d_in[26];
    const float* p2_w  = (const float*)d_in[27];
    const float* p2_b  = (const float*)d_in[28];

    const int* e_src = ei;
    const int* e_dst = ei + EE;

    cudaFuncSetAttribute(gemm_mma<128>, cudaFuncAttributeMaxDynamicSharedMemorySize,
                         NSTAGE * (16384 + 128 * 128));
    cudaFuncSetAttribute(gemm_mma<64>, cudaFuncAttributeMaxDynamicSharedMemorySize,
                         NSTAGE * (16384 + 64 * 128));

    float *d_h1, *d_qkvs;
    __half* d_kvh;
    __nv_bfloat16 *d_i0, *d_i1, *d_W;
    cudaGetSymbolAddress((void**)&d_h1, g_h1);
    cudaGetSymbolAddress((void**)&d_qkvs, g_qkvs);
    cudaGetSymbolAddress((void**)&d_kvh, g_kvh);
    cudaGetSymbolAddress((void**)&d_i0, g_img0);
    cudaGetSymbolAddress((void**)&d_i1, g_img1);
    cudaGetSymbolAddress((void**)&d_W, g_Wbf);

    // CSR build
    k_zero<<<(NN + 255) / 256, 256>>>((float*)d_out);
    k_hist<<<(EE + 255) / 256, 256>>>(e_dst);
    k_scan<<<1, 1024>>>();
    k_scatter<<<(EE + 255) / 256, 256>>>(e_src, e_dst);

    // fused weight conversion (one launch for all 12 tensors)
    {
        WJobs jobs;
        int cum = 0, idx = 0;
        auto add = [&](const float* w1, const float* w2, int k1, int K, int nw, int off) {
            cum += nw * K;
            jobs.j[idx++] = WJob{w1, w2, k1, K, nw, off, cum};
        };
        add(s1_wl, s1_wr, 128, 256, 128, OFF_S1);
        add(s2_wl, s2_wr, 128, 256, 256, OFF_S2);
        add(t1_wq, t1_wq, 256, 256, 256, OFF_T1 + 0 * 256 * 768);
        add(t1_wk, t1_wk, 256, 256, 256, OFF_T1 + 1 * 256 * 768);
        add(t1_wv, t1_wv, 256, 256, 256, OFF_T1 + 2 * 256 * 768);
        add(t1_ws, t1_ws, 256, 256, 256, OFF_T1 + 3 * 256 * 768);
        add(t2_wq, t2_wq, 256, 256, 256, OFF_T2 + 0 * 256 * 768);
        add(t2_wk, t2_wk, 256, 256, 256, OFF_T2 + 1 * 256 * 768);
        add(t2_wv, t2_wv, 256, 256, 256, OFF_T2 + 2 * 256 * 768);
        add(t2_ws, t2_ws, 256, 256, 256, OFF_T2 + 3 * 256 * 768);
        add(p1_w, p1_w, 256, 256, 512, OFF_P1);
        add(p2_w, p2_w, 512, 512, 128, OFF_P2);
        k_convW_all<<<(WTOTAL + 255) / 256, 256>>>(jobs);
    }

    // SAGE 1 input image (img0): mean(x) + x in one launch
    k_prep1<<<(NN * 32 + 255) / 256, 256>>>(x, d_i0);
    run_gemm(64, d_i0, d_W + OFF_S1, s1_bl, s1_bl, s1_bl, s1_bl,
             d_h1, 128, 256, 1, d_i1, 256, 128, nullptr, nullptr, nullptr);

    // SAGE 2: mean(h1) -> img1[0:128); S2 -> img0[0:256)
    k_sage_agg<<<(NN * 32 + 255) / 256, 256>>>(d_h1, d_i1);
    run_gemm(64, d_i1, d_W + OFF_S2, s2_bl, s2_bl, s2_bl, s2_bl,
             nullptr, 256, 256, 1, d_i0, 256, 0, nullptr, nullptr, nullptr);

    // TransformerConv 1: q/skip fp32 -> qkvs, k/v fp16 -> kvh
    run_gemm(128, d_i0, d_W + OFF_T1, t1_bq, t1_bk, t1_bv, t1_bs,
             d_qkvs, 1024, 256, 0, nullptr, 0, 0, nullptr, nullptr, d_kvh);
    k_attn<<<(NN * 32 + 255) / 256, 256>>>(d_qkvs, d_kvh, d_i1);

    // TransformerConv 2
    run_gemm(128, d_i1, d_W + OFF_T2, t2_bq, t2_bk, t2_bv, t2_bs,
             d_qkvs, 1024, 256, 0, nullptr, 0, 0, nullptr, nullptr, d_kvh);
    k_attn<<<(NN * 32 + 255) / 256, 256>>>(d_qkvs, d_kvh, d_i0);

    // proj MLP: P1 -> img1 (K=512 compact); P2 -> sigmoid + fused pool
    run_gemm(64, d_i0, d_W + OFF_P1, p1_b, p1_b + 256, p1_b, p1_b,
             nullptr, 512, 256, 1, d_i1, 512, 0, nullptr, nullptr, nullptr);
    run_gemm(64, d_i1, d_W + OFF_P2, p2_b, p2_b, p2_b, p2_b,
             nullptr, 128, 512, 2, nullptr, 0, 0, batch, (float*)d_out, nullptr);
}

// round 11
// speedup vs baseline: 1.1725x; 1.0319x over previous
#include <cuda_runtime.h>
#include <cuda_bf16.h>
#include <cuda_fp16.h>
#include <math.h>
#include <stdint.h>

#define NN 20000
#define EE 320000
#define GG 64
#define MPAD 20096          // 157 * 128
#define NTILES 157

// ---------------- device scratch ----------------
__device__ __half g_h1h[NN * 128];              // h1 fp16 (for SAGE-2 aggregation)
__device__ __half g_kvh[(size_t)NN * 1024];     // q|k|v|skip fp16 per node
__device__ int g_deg[NN];
__device__ int g_fill[NN];
__device__ int g_rowptr[NN + 1];
__device__ int g_csrc[EE];

// ping-pong compact bf16 hi|lo A-images: [MPAD][2K], widest K=512 -> 1024 cols
__device__ __nv_bfloat16 g_img0[(size_t)MPAD * 1024];
__device__ __nv_bfloat16 g_img1[(size_t)MPAD * 1024];
__device__ __nv_bfloat16 g_Wbf[2457600];

// weight image offsets (elements), layout [Nc][3K] = hi|lo|hi
#define OFF_S1   0
#define OFF_S2   98304
#define OFF_T1   294912
#define OFF_T2   1081344
#define OFF_P1   1867776
#define OFF_P2   2260992

__device__ __forceinline__ uint32_t smem_u32(const void* p) {
    uint32_t a;
    asm("{ .reg .u64 t; cvta.to.shared.u64 t, %1; cvt.u32.u64 %0, t; }" : "=r"(a) : "l"(p));
    return a;
}
__device__ __forceinline__ void cpa16(uint32_t dst, const void* src) {
    asm volatile("cp.async.cg.shared.global [%0], [%1], 16;" :: "r"(dst), "l"(src));
}

// write 4 consecutive floats as hi @ c, lo @ K+c (compact image, row stride 2K)
__device__ __forceinline__ void img_write4(__nv_bfloat16* row, int K, int c, float4 v) {
    __nv_bfloat162 hh0, hh1, ll0, ll1;
    hh0.x = __float2bfloat16(v.x); hh0.y = __float2bfloat16(v.y);
    hh1.x = __float2bfloat16(v.z); hh1.y = __float2bfloat16(v.w);
    ll0.x = __float2bfloat16(v.x - __bfloat162float(hh0.x));
    ll0.y = __float2bfloat16(v.y - __bfloat162float(hh0.y));
    ll1.x = __float2bfloat16(v.z - __bfloat162float(hh1.x));
    ll1.y = __float2bfloat16(v.w - __bfloat162float(hh1.y));
    *(__nv_bfloat162*)(row + c) = hh0;     *(__nv_bfloat162*)(row + c + 2) = hh1;
    *(__nv_bfloat162*)(row + K + c) = ll0; *(__nv_bfloat162*)(row + K + c + 2) = ll1;
}

// load 4 consecutive fp16 values as float4
__device__ __forceinline__ float4 ldkv4(const __half* p) {
    uint2 u = *(const uint2*)p;
    __half2 a = *reinterpret_cast<const __half2*>(&u.x);
    __half2 b = *reinterpret_cast<const __half2*>(&u.y);
    float2 fa = __half22float2(a), fb = __half22float2(b);
    return make_float4(fa.x, fa.y, fb.x, fb.y);
}

// ---------------- CSR build ----------------
__global__ void k_zero(float* out) {
    int i = blockIdx.x * blockDim.x + threadIdx.x;
    if (i < NN) { g_deg[i] = 0; g_fill[i] = 0; }
    if (i < GG * 128) out[i] = 0.0f;
}
__global__ void k_hist(const int* __restrict__ dst) {
    int e = blockIdx.x * blockDim.x + threadIdx.x;
    if (e < EE) atomicAdd(&g_deg[dst[e]], 1);
}
// fast scan: thread-serial partials (20/thread) + one 1024 Hillis-Steele
__global__ void k_scan() {
    __shared__ int sh[1024];
    const int PER = 20;  // 1024*20 >= NN
    int tid = threadIdx.x;
    int base = tid * PER;
    int local[PER];
    int sum = 0;
#pragma unroll
    for (int i = 0; i < PER; i++) {
        int idx = base + i;
        int v = (idx < NN) ? g_deg[idx] : 0;
        local[i] = sum;
        sum += v;
    }
    sh[tid] = sum;
    __syncthreads();
    for (int off = 1; off < 1024; off <<= 1) {
        int t = (tid >= off) ? sh[tid - off] : 0;
        __syncthreads();
        sh[tid] += t;
        __syncthreads();
    }
    int carry = (tid > 0) ? sh[tid - 1] : 0;
#pragma unroll
    for (int i = 0; i < PER; i++) {
        int idx = base + i;
        if (idx < NN) g_rowptr[idx] = carry + local[i];
    }
    if (tid == 1023) g_rowptr[NN] = sh[1023];
}
__global__ void k_scatter(const int* __restrict__ src, const int* __restrict__ dst) {
    int e = blockIdx.x * blockDim.x + threadIdx.x;
    if (e >= EE) return;
    int d = dst[e];
    int pos = atomicAdd(&g_fill[d], 1);
    g_csrc[g_rowptr[d] + pos] = src[e];
}

// ---------------- fused prep: sage mean (cols [0,128)) + x (cols [128,256)) ---
__global__ void k_prep1(const float* __restrict__ x, __nv_bfloat16* __restrict__ img) {
    int w = (blockIdx.x * blockDim.x + threadIdx.x) >> 5;
    int lane = threadIdx.x & 31;
    if (w >= NN) return;
    int beg = g_rowptr[w], end = g_rowptr[w + 1];
    float4 acc = make_float4(0.f, 0.f, 0.f, 0.f);
#pragma unroll 4
    for (int e = beg; e < end; e++) {
        int s = g_csrc[e];
        float4 xv = *(const float4*)(x + (size_t)s * 128 + lane * 4);
        acc.x += xv.x; acc.y += xv.y; acc.z += xv.z; acc.w += xv.w;
    }
    float inv = 1.0f / fmaxf((float)(end - beg), 1.0f);
    acc.x *= inv; acc.y *= inv; acc.z *= inv; acc.w *= inv;
    __nv_bfloat16* row = img + (size_t)w * 512;
    img_write4(row, 256, lane * 4, acc);
    float4 xo = *(const float4*)(x + (size_t)w * 128 + lane * 4);
    img_write4(row, 256, 128 + lane * 4, xo);
}

// ---------------- SAGE mean aggregation over fp16 h1 -> image cols [0,128) ---
__global__ void k_sage_agg_h(const __half* __restrict__ x, __nv_bfloat16* __restrict__ img) {
    int w = (blockIdx.x * blockDim.x + threadIdx.x) >> 5;
    int lane = threadIdx.x & 31;
    if (w >= NN) return;
    int beg = g_rowptr[w], end = g_rowptr[w + 1];
    float4 acc = make_float4(0.f, 0.f, 0.f, 0.f);
#pragma unroll 4
    for (int e = beg; e < end; e++) {
        int s = g_csrc[e];
        float4 xv = ldkv4(x + (size_t)s * 128 + lane * 4);
        acc.x += xv.x; acc.y += xv.y; acc.z += xv.z; acc.w += xv.w;
    }
    float inv = 1.0f / fmaxf((float)(end - beg), 1.0f);
    acc.x *= inv; acc.y *= inv; acc.z *= inv; acc.w *= inv;
    img_write4(img + (size_t)w * 512, 256, lane * 4, acc);
}

// ---------------- fused weight conversion: all 12 tensors in one launch -------
struct WJob { const float *w1, *w2; int k1, K, nw, off, cumEnd; };
struct WJobs { WJob j[12]; };
#define WTOTAL 819200

__global__ void k_convW_all(WJobs jobs) {
    int idx = blockIdx.x * blockDim.x + threadIdx.x;
    if (idx >= WTOTAL) return;
    int s = 0;
    while (idx >= jobs.j[s].cumEnd) s++;
    const WJob J = jobs.j[s];
    int local = idx - (s ? jobs.j[s - 1].cumEnd : 0);
    int n = local / J.K;
    int k = local - n * J.K;
    float val = (k < J.k1) ? J.w1[(size_t)k * J.nw + n] : J.w2[(size_t)(k - J.k1) * J.nw + n];
    __nv_bfloat16 hi = __float2bfloat16(val);
    __nv_bfloat16 lo = __float2bfloat16(val - __bfloat162float(hi));
    __nv_bfloat16* row = g_Wbf + (size_t)J.off + (size_t)n * (3 * J.K);
    row[k] = hi;
    row[J.K + k] = lo;
    row[2 * J.K + k] = hi;
}

// ---------------- 3-stage pipelined mma.sync bf16 GEMM, templated BN ---------
// A compact [M][2K] hi|lo; W [Nc][3K] hi|lo|hi; logical K-tiles 3K/64.
#define NSTAGE 3

template <int BN>
__global__ void __launch_bounds__(256, 2)
gemm_mma(const __nv_bfloat16* __restrict__ A, const __nv_bfloat16* __restrict__ W,
         const float* __restrict__ b0, const float* __restrict__ b1,
         const float* __restrict__ b2, const float* __restrict__ b3,
         int Nc, int Kbase, int act,
         __nv_bfloat16* __restrict__ img, int imgK, int imgColOff,
         const int* __restrict__ batch, float* __restrict__ pool,
         __half* __restrict__ outh) {
    constexpr int STB = 16384 + BN * 128;       // A tile 16KB + B tile
    constexpr int MI = (BN == 128) ? 4 : 2;     // warp M sub-tiles (x16 rows)
    extern __shared__ char smem[];
    const int tid = threadIdx.x;
    const int wid = tid >> 5, lane = tid & 31;
    const int bm = blockIdx.y * 128;
    const int bn = blockIdx.x * BN;
    const int wm = (BN == 128) ? ((wid & 1) << 6) : ((wid & 3) << 5);
    const int wn = (BN == 128) ? ((wid >> 1) << 5) : ((wid >> 2) << 5);
    const uint32_t sb = smem_u32(smem);

    float acc[MI][4][4];
#pragma unroll
    for (int i = 0; i < MI; i++)
#pragma unroll
        for (int j = 0; j < 4; j++)
#pragma unroll
            for (int t = 0; t < 4; t++) acc[i][j][t] = 0.f;

    const int KA = Kbase >> 6;        // hi chunks
    const int nK = 3 * KA;            // logical k-tiles
    const int KtotW = 3 * Kbase;
    const int KtotA = 2 * Kbase;

    auto issue = [&](int c, int buf) {
        int ac = (c < KA) ? c : (c - KA);       // physical A chunk
        int ka0 = ac << 6;
        int kw0 = c << 6;
        uint32_t base = sb + buf * STB;
#pragma unroll
        for (int l = 0; l < 4; l++) {
            int idx = tid + l * 256;
            int row = idx >> 3, u = idx & 7;
            uint32_t sw = row * 128 + ((u ^ (row & 7)) << 4);
            cpa16(base + sw, A + (size_t)(bm + row) * KtotA + ka0 + u * 8);
        }
#pragma unroll
        for (int l = 0; l < BN / 32; l++) {
            int idx = tid + l * 256;
            int row = idx >> 3, u = idx & 7;
            uint32_t sw = row * 128 + ((u ^ (row & 7)) << 4);
            cpa16(base + 16384 + sw, W + (size_t)(bn + row) * KtotW + kw0 + u * 8);
        }
        asm volatile("cp.async.commit_group;" ::: "memory");
    };

    issue(0, 0);
    if (nK > 1) issue(1, 1);
    for (int c = 0; c < nK; c++) {
        if (c + 1 < nK) asm volatile("cp.async.wait_group 1;" ::: "memory");
        else            asm volatile("cp.async.wait_group 0;" ::: "memory");
        __syncthreads();          // retires all readers of buffer (c-1)%3
        if (c + 2 < nK) issue(c + 2, (c + 2) % NSTAGE);   // writes (c-1)%3: safe

        int buf = c % NSTAGE;
        uint32_t sAb = sb + buf * STB;
        uint32_t sBb = sAb + 16384;
#pragma unroll
        for (int s = 0; s < 4; s++) {
            uint32_t a[MI][4], b[4][2];
#pragma unroll
            for (int i = 0; i < MI; i++) {
                int row = wm + i * 16 + (lane & 15);
                int u = (s << 1) + (lane >> 4);
                uint32_t ad = sAb + row * 128 + ((u ^ (row & 7)) << 4);
                asm volatile("ldmatrix.sync.aligned.m8n8.x4.shared.b16 {%0,%1,%2,%3}, [%4];"
                    : "=r"(a[i][0]), "=r"(a[i][1]), "=r"(a[i][2]), "=r"(a[i][3]) : "r"(ad));
            }
#pragma unroll
            for (int jj = 0; jj < 2; jj++) {
                int row = wn + (jj << 4) + ((lane >> 4) << 3) + (lane & 7);
                int u = (s << 1) + ((lane >> 3) & 1);
                uint32_t ad = sBb + row * 128 + ((u ^ (row & 7)) << 4);
                asm volatile("ldmatrix.sync.aligned.m8n8.x4.shared.b16 {%0,%1,%2,%3}, [%4];"
                    : "=r"(b[jj * 2][0]), "=r"(b[jj * 2][1]),
                      "=r"(b[jj * 2 + 1][0]), "=r"(b[jj * 2 + 1][1]) : "r"(ad));
            }
#pragma unroll
            for (int i = 0; i < MI; i++)
#pragma unroll
                for (int j = 0; j < 4; j++)
                    asm volatile("mma.sync.aligned.m16n8k16.row.col.f32.bf16.bf16.f32 "
                        "{%0,%1,%2,%3}, {%4,%5,%6,%7}, {%8,%9}, {%0,%1,%2,%3};"
                        : "+f"(acc[i][j][0]), "+f"(acc[i][j][1]),
                          "+f"(acc[i][j][2]), "+f"(acc[i][j][3])
                        : "r"(a[i][0]), "r"(a[i][1]), "r"(a[i][2]), "r"(a[i][3]),
                          "r"(b[j][0]), "r"(b[j][1]));
        }
    }

    // epilogue
    const float* bsel[4] = {b0, b1, b2, b3};
    const int stride2K = 2 * imgK;
#pragma unroll
    for (int i = 0; i < MI; i++) {
        int r0 = bm + wm + i * 16 + (lane >> 2);
        int r1 = r0 + 8;
#pragma unroll
        for (int j = 0; j < 4; j++) {
            int c = bn + wn + (j << 3) + ((lane & 3) << 1);
            const float* bp = bsel[c >> 8];
            float bv0 = bp[c & 255], bv1 = bp[(c & 255) + 1];
            float v00 = acc[i][j][0] + bv0, v01 = acc[i][j][1] + bv1;
            float v10 = acc[i][j][2] + bv0, v11 = acc[i][j][3] + bv1;
            if (act == 1) {
                v00 = fmaxf(v00, 0.f); v01 = fmaxf(v01, 0.f);
                v10 = fmaxf(v10, 0.f); v11 = fmaxf(v11, 0.f);
            } else if (act == 2) {
                v00 = 1.f / (1.f + __expf(-v00)); v01 = 1.f / (1.f + __expf(-v01));
                v10 = 1.f / (1.f + __expf(-v10)); v11 = 1.f / (1.f + __expf(-v11));
            }
            if (outh) {
                if (r0 < NN)
                    *(__half2*)(outh + (size_t)r0 * Nc + c) = __floats2half2_rn(v00, v01);
                if (r1 < NN)
                    *(__half2*)(outh + (size_t)r1 * Nc + c) = __floats2half2_rn(v10, v11);
            }
            if (img) {
                int ic = imgColOff + c;
                if (r0 < NN) {
                    __nv_bfloat16* row = img + (size_t)r0 * stride2K;
                    __nv_bfloat162 hh, ll;
                    hh.x = __float2bfloat16(v00); hh.y = __float2bfloat16(v01);
                    ll.x = __float2bfloat16(v00 - __bfloat162float(hh.x));
                    ll.y = __float2bfloat16(v01 - __bfloat162float(hh.y));
                    *(__nv_bfloat162*)(row + ic) = hh;
                    *(__nv_bfloat162*)(row + imgK + ic) = ll;
                }
                if (r1 < NN) {
                    __nv_bfloat16* row = img + (size_t)r1 * stride2K;
                    __nv_bfloat162 hh, ll;
                    hh.x = __float2bfloat16(v10); hh.y = __float2bfloat16(v11);
                    ll.x = __float2bfloat16(v10 - __bfloat162float(hh.x));
                    ll.y = __float2bfloat16(v11 - __bfloat162float(hh.y));
                    *(__nv_bfloat162*)(row + ic) = hh;
                    *(__nv_bfloat162*)(row + imgK + ic) = ll;
                }
            }
            if (pool) {
                if (r0 < NN) {
                    int g = batch[r0] * 128;
                    atomicMax((int*)&pool[g + c], __float_as_int(v00));
                    atomicMax((int*)&pool[g + c + 1], __float_as_int(v01));
                }
                if (r1 < NN) {
                    int g = batch[r1] * 128;
                    atomicMax((int*)&pool[g + c], __float_as_int(v10));
                    atomicMax((int*)&pool[g + c + 1], __float_as_int(v11));
                }
            }
        }
    }
}

// ---------------- attention: warp per node, 8 heads, pairwise, all-fp16 ------
__device__ __forceinline__ float dot4(float4 a, float4 b) {
    return a.x * b.x + a.y * b.y + a.z * b.z + a.w * b.w;
}

__global__ void k_attn(const __half* __restrict__ kvh, __nv_bfloat16* __restrict__ img) {
    int node = (blockIdx.x * blockDim.x + threadIdx.x) >> 5;
    if (node >= NN) return;
    int lane = threadIdx.x & 31;
    const __half* base = kvh + (size_t)node * 1024;
    const float scl = 0.17677669529663687f;
    float4 q0 = ldkv4(base + lane * 4);
    float4 q1 = ldkv4(base + 128 + lane * 4);
    q0.x *= scl; q0.y *= scl; q0.z *= scl; q0.w *= scl;
    q1.x *= scl; q1.y *= scl; q1.z *= scl; q1.w *= scl;
    int beg = g_rowptr[node], end = g_rowptr[node + 1];
    float m0 = -3.0e38f, s0 = 0.f, m1 = -3.0e38f, s1 = 0.f;
    float4 a0 = make_float4(0.f, 0.f, 0.f, 0.f);
    float4 a1 = make_float4(0.f, 0.f, 0.f, 0.f);
    int e = beg;
    for (; e + 1 < end; e += 2) {
        int sa = g_csrc[e], sbn = g_csrc[e + 1];
        const __half* ka = kvh + (size_t)sa * 1024 + 256;
        const __half* kb = kvh + (size_t)sbn * 1024 + 256;
        float4 ka0 = ldkv4(ka + lane * 4);
        float4 ka1 = ldkv4(ka + 128 + lane * 4);
        float4 va0 = ldkv4(ka + 256 + lane * 4);
        float4 va1 = ldkv4(ka + 384 + lane * 4);
        float4 kb0 = ldkv4(kb + lane * 4);
        float4 kb1 = ldkv4(kb + 128 + lane * 4);
        float4 vb0 = ldkv4(kb + 256 + lane * 4);
        float4 vb1 = ldkv4(kb + 384 + lane * 4);
        float da0 = dot4(q0, ka0), da1 = dot4(q1, ka1);
        float db0 = dot4(q0, kb0), db1 = dot4(q1, kb1);
#pragma unroll
        for (int off = 4; off; off >>= 1) {
            da0 += __shfl_xor_sync(0xffffffffu, da0, off);
            da1 += __shfl_xor_sync(0xffffffffu, da1, off);
            db0 += __shfl_xor_sync(0xffffffffu, db0, off);
            db1 += __shfl_xor_sync(0xffffffffu, db1, off);
        }
        {
            float mn = fmaxf(m0, fmaxf(da0, db0));
            float sc = __expf(m0 - mn);
            float pa = __expf(da0 - mn);
            float pb = __expf(db0 - mn);
            s0 = s0 * sc + pa + pb;
            a0.x = a0.x * sc + pa * va0.x + pb * vb0.x;
            a0.y = a0.y * sc + pa * va0.y + pb * vb0.y;
            a0.z = a0.z * sc + pa * va0.z + pb * vb0.z;
            a0.w = a0.w * sc + pa * va0.w + pb * vb0.w;
            m0 = mn;
        }
        {
            float mn = fmaxf(m1, fmaxf(da1, db1));
            float sc = __expf(m1 - mn);
            float pa = __expf(da1 - mn);
            float pb = __expf(db1 - mn);
            s1 = s1 * sc + pa + pb;
            a1.x = a1.x * sc + pa * va1.x + pb * vb1.x;
            a1.y = a1.y * sc + pa * va1.y + pb * vb1.y;
            a1.z = a1.z * sc + pa * va1.z + pb * vb1.z;
            a1.w = a1.w * sc + pa * va1.w + pb * vb1.w;
            m1 = mn;
        }
    }
    if (e < end) {   // tail edge
        int sn = g_csrc[e];
        const __half* kb = kvh + (size_t)sn * 1024 + 256;
        float4 k0 = ldkv4(kb + lane * 4);
        float4 k1 = ldkv4(kb + 128 + lane * 4);
        float4 v0 = ldkv4(kb + 256 + lane * 4);
        float4 v1 = ldkv4(kb + 384 + lane * 4);
        float d0 = dot4(q0, k0), d1 = dot4(q1, k1);
#pragma unroll
        for (int off = 4; off; off >>= 1) {
            d0 += __shfl_xor_sync(0xffffffffu, d0, off);
            d1 += __shfl_xor_sync(0xffffffffu, d1, off);
        }
        float mn0 = fmaxf(m0, d0);
        float sc0 = __expf(m0 - mn0);
        float p0 = __expf(d0 - mn0);
        s0 = s0 * sc0 + p0;
        a0.x = a0.x * sc0 + p0 * v0.x; a0.y = a0.y * sc0 + p0 * v0.y;
        a0.z = a0.z * sc0 + p0 * v0.z; a0.w = a0.w * sc0 + p0 * v0.w;
        m0 = mn0;
        float mn1 = fmaxf(m1, d1);
        float sc1 = __expf(m1 - mn1);
        float p1 = __expf(d1 - mn1);
        s1 = s1 * sc1 + p1;
        a1.x = a1.x * sc1 + p1 * v1.x; a1.y = a1.y * sc1 + p1 * v1.y;
        a1.z = a1.z * sc1 + p1 * v1.z; a1.w = a1.w * sc1 + p1 * v1.w;
        m1 = mn1;
    }
    float inv0 = (end > beg) ? (1.f / s0) : 0.f;
    float inv1 = (end > beg) ? (1.f / s1) : 0.f;
    float4 sk0 = ldkv4(base + 768 + lane * 4);
    float4 sk1 = ldkv4(base + 896 + lane * 4);
    float4 o0, o1;
    o0.x = fmaxf(sk0.x + a0.x * inv0, 0.f); o0.y = fmaxf(sk0.y + a0.y * inv0, 0.f);
    o0.z = fmaxf(sk0.z + a0.z * inv0, 0.f); o0.w = fmaxf(sk0.w + a0.w * inv0, 0.f);
    o1.x = fmaxf(sk1.x + a1.x * inv1, 0.f); o1.y = fmaxf(sk1.y + a1.y * inv1, 0.f);
    o1.z = fmaxf(sk1.z + a1.z * inv1, 0.f); o1.w = fmaxf(sk1.w + a1.w * inv1, 0.f);
    __nv_bfloat16* row = img + (size_t)node * 512;
    img_write4(row, 256, lane * 4, o0);
    img_write4(row, 256, 128 + lane * 4, o1);
}

// ---------------- host orchestration ----------------
static void run_gemm(int bn, const __nv_bfloat16* A, const __nv_bfloat16* W,
                     const float* b0, const float* b1, const float* b2, const float* b3,
                     int Nc, int Kbase, int act,
                     __nv_bfloat16* img, int imgK, int imgColOff,
                     const int* batch, float* pool, __half* outh) {
    dim3 grid(Nc / bn, NTILES);
    if (bn == 64)
        gemm_mma<64><<<grid, 256, NSTAGE * (16384 + 64 * 128)>>>(A, W, b0, b1, b2, b3, Nc,
                                                                 Kbase, act, img, imgK,
                                                                 imgColOff, batch, pool, outh);
    else
        gemm_mma<128><<<grid, 256, NSTAGE * (16384 + 128 * 128)>>>(A, W, b0, b1, b2, b3, Nc,
                                                                   Kbase, act, img, imgK,
                                                                   imgColOff, batch, pool, outh);
}

extern "C" void kernel_launch(void* const* d_in, const int* in_sizes, int n_in,
                              void* d_out, int out_size) {
    const float* x     = (const float*)d_in[0];
    const int*   ei    = (const int*)d_in[1];
    const int*   batch = (const int*)d_in[2];
    const float* s1_wl = (const float*)d_in[3];
    const float* s1_bl = (const float*)d_in[4];
    const float* s1_wr = (const float*)d_in[5];
    const float* s2_wl = (const float*)d_in[6];
    const float* s2_bl = (const float*)d_in[7];
    const float* s2_wr = (const float*)d_in[8];
    const float* t1_wq = (const float*)d_in[9];
    const float* t1_bq = (const float*)d_in[10];
    const float* t1_wk = (const float*)d_in[11];
    const float* t1_bk = (const float*)d_in[12];
    const float* t1_wv = (const float*)d_in[13];
    const float* t1_bv = (const float*)d_in[14];
    const float* t1_ws = (const float*)d_in[15];
    const float* t1_bs = (const float*)d_in[16];
    const float* t2_wq = (const float*)d_in[17];
    const float* t2_bq = (const float*)d_in[18];
    const float* t2_wk = (const float*)d_in[19];
    const float* t2_bk = (const float*)d_in[20];
    const float* t2_wv = (const float*)d_in[21];
    const float* t2_bv = (const float*)d_in[22];
    const float* t2_ws = (const float*)d_in[23];
    const float* t2_bs = (const float*)d_in[24];
    const float* p1_w  = (const float*)d_in[25];
    const float* p1_b  = (const float*)d_in[26];
    const float* p2_w  = (const float*)d_in[27];
    const float* p2_b  = (const float*)d_in[28];

    const int* e_src = ei;
    const int* e_dst = ei + EE;

    cudaFuncSetAttribute(gemm_mma<128>, cudaFuncAttributeMaxDynamicSharedMemorySize,
                         NSTAGE * (16384 + 128 * 128));
    cudaFuncSetAttribute(gemm_mma<64>, cudaFuncAttributeMaxDynamicSharedMemorySize,
                         NSTAGE * (16384 + 64 * 128));

    __half *d_h1h, *d_kvh;
    __nv_bfloat16 *d_i0, *d_i1, *d_W;
    cudaGetSymbolAddress((void**)&d_h1h, g_h1h);
    cudaGetSymbolAddress((void**)&d_kvh, g_kvh);
    cudaGetSymbolAddress((void**)&d_i0, g_img0);
    cudaGetSymbolAddress((void**)&d_i1, g_img1);
    cudaGetSymbolAddress((void**)&d_W, g_Wbf);

    // CSR build
    k_zero<<<(NN + 255) / 256, 256>>>((float*)d_out);
    k_hist<<<(EE + 255) / 256, 256>>>(e_dst);
    k_scan<<<1, 1024>>>();
    k_scatter<<<(EE + 255) / 256, 256>>>(e_src, e_dst);

    // fused weight conversion (one launch for all 12 tensors)
    {
        WJobs jobs;
        int cum = 0, idx = 0;
        auto add = [&](const float* w1, const float* w2, int k1, int K, int nw, int off) {
            cum += nw * K;
            jobs.j[idx++] = WJob{w1, w2, k1, K, nw, off, cum};
        };
        add(s1_wl, s1_wr, 128, 256, 128, OFF_S1);
        add(s2_wl, s2_wr, 128, 256, 256, OFF_S2);
        add(t1_wq, t1_wq, 256, 256, 256, OFF_T1 + 0 * 256 * 768);
        add(t1_wk, t1_wk, 256, 256, 256, OFF_T1 + 1 * 256 * 768);
        add(t1_wv, t1_wv, 256, 256, 256, OFF_T1 + 2 * 256 * 768);
        add(t1_ws, t1_ws, 256, 256, 256, OFF_T1 + 3 * 256 * 768);
        add(t2_wq, t2_wq, 256, 256, 256, OFF_T2 + 0 * 256 * 768);
        add(t2_wk, t2_wk, 256, 256, 256, OFF_T2 + 1 * 256 * 768);
        add(t2_wv, t2_wv, 256, 256, 256, OFF_T2 + 2 * 256 * 768);
        add(t2_ws, t2_ws, 256, 256, 256, OFF_T2 + 3 * 256 * 768);
        add(p1_w, p1_w, 256, 256, 512, OFF_P1);
        add(p2_w, p2_w, 512, 512, 128, OFF_P2);
        k_convW_all<<<(WTOTAL + 255) / 256, 256>>>(jobs);
    }

    // SAGE 1 input image (img0): mean(x) + x in one launch
    k_prep1<<<(NN * 32 + 255) / 256, 256>>>(x, d_i0);
    // S1: h1 -> fp16 + img1 cols [128,256)
    run_gemm(64, d_i0, d_W + OFF_S1, s1_bl, s1_bl, s1_bl, s1_bl,
             128, 256, 1, d_i1, 256, 128, nullptr, nullptr, d_h1h);

    // SAGE 2: mean(h1 fp16) -> img1[0:128); S2 -> img0[0:256)
    k_sage_agg_h<<<(NN * 32 + 255) / 256, 256>>>(d_h1h, d_i1);
    run_gemm(64, d_i1, d_W + OFF_S2, s2_bl, s2_bl, s2_bl, s2_bl,
             256, 256, 1, d_i0, 256, 0, nullptr, nullptr, nullptr);

    // TransformerConv 1: q|k|v|skip all fp16 -> kvh
    run_gemm(128, d_i0, d_W + OFF_T1, t1_bq, t1_bk, t1_bv, t1_bs,
             1024, 256, 0, nullptr, 0, 0, nullptr, nullptr, d_kvh);
    k_attn<<<(NN * 32 + 255) / 256, 256>>>(d_kvh, d_i1);

    // TransformerConv 2
    run_gemm(128, d_i1, d_W + OFF_T2, t2_bq, t2_bk, t2_bv, t2_bs,
             1024, 256, 0, nullptr, 0, 0, nullptr, nullptr, d_kvh);
    k_attn<<<(NN * 32 + 255) / 256, 256>>>(d_kvh, d_i0);

    // proj MLP: P1 -> img1 (K=512 compact); P2 -> sigmoid + fused pool
    run_gemm(64, d_i0, d_W + OFF_P1, p1_b, p1_b + 256, p1_b, p1_b,
             512, 256, 1, d_i1, 512, 0, nullptr, nullptr, nullptr);
    run_gemm(64, d_i1, d_W + OFF_P2, p2_b, p2_b, p2_b, p2_b,
             128, 512, 2, nullptr, 0, 0, batch, (float*)d_out, nullptr);
}

// round 12
// speedup vs baseline: 1.4663x; 1.2505x over previous
#include <cuda_runtime.h>
#include <cuda_bf16.h>
#include <cuda_fp16.h>
#include <math.h>
#include <stdint.h>

#define NN 20000
#define EE 320000
#define GG 64
#define MPAD 20096          // 157 * 128
#define NTILES 157

// ---------------- device scratch ----------------
__device__ __half g_h1h[NN * 128];              // h1 fp16 (for SAGE-2 aggregation)
__device__ __half g_kvh[(size_t)NN * 1024];     // q|k|v|skip fp16 per node
__device__ int g_deg[NN];
__device__ int g_fill[NN];
__device__ int g_rowptr[NN + 1];
__device__ int g_csrc[EE];

// ping-pong compact fp16 hi|lo A-images: [MPAD][2K], widest K=512 -> 1024 cols
__device__ __half g_img0[(size_t)MPAD * 1024];
__device__ __half g_img1[(size_t)MPAD * 1024];
// fp16 weight images, layout [Nc][K] (hi only)
__device__ __half g_Wh[819200];

// weight image offsets (elements)
#define OFF_S1   0          // 128 x 256
#define OFF_S2   32768      // 256 x 256
#define OFF_T1   98304      // 4 x (256 x 256)
#define OFF_T2   360448
#define OFF_P1   622592     // 512 x 256
#define OFF_P2   753664     // 128 x 512

__device__ __forceinline__ uint32_t smem_u32(const void* p) {
    uint32_t a;
    asm("{ .reg .u64 t; cvta.to.shared.u64 t, %1; cvt.u32.u64 %0, t; }" : "=r"(a) : "l"(p));
    return a;
}
__device__ __forceinline__ void cpa16(uint32_t dst, const void* src) {
    asm volatile("cp.async.cg.shared.global [%0], [%1], 16;" :: "r"(dst), "l"(src));
}

// write 4 consecutive floats as fp16 hi @ c, fp16 lo @ K+c (row stride 2K)
__device__ __forceinline__ void img_write4(__half* row, int K, int c, float4 v) {
    __half2 hh0 = __floats2half2_rn(v.x, v.y);
    __half2 hh1 = __floats2half2_rn(v.z, v.w);
    __half2 ll0 = __floats2half2_rn(v.x - __half2float(__low2half(hh0)),
                                    v.y - __half2float(__high2half(hh0)));
    __half2 ll1 = __floats2half2_rn(v.z - __half2float(__low2half(hh1)),
                                    v.w - __half2float(__high2half(hh1)));
    *(__half2*)(row + c) = hh0;     *(__half2*)(row + c + 2) = hh1;
    *(__half2*)(row + K + c) = ll0; *(__half2*)(row + K + c + 2) = ll1;
}

// load 4 consecutive fp16 values as float4
__device__ __forceinline__ float4 ldkv4(const __half* p) {
    uint2 u = *(const uint2*)p;
    __half2 a = *reinterpret_cast<const __half2*>(&u.x);
    __half2 b = *reinterpret_cast<const __half2*>(&u.y);
    float2 fa = __half22float2(a), fb = __half22float2(b);
    return make_float4(fa.x, fa.y, fb.x, fb.y);
}

// ---------------- CSR build ----------------
__global__ void k_zero(float* out) {
    int i = blockIdx.x * blockDim.x + threadIdx.x;
    if (i < NN) { g_deg[i] = 0; g_fill[i] = 0; }
    if (i < GG * 128) out[i] = 0.0f;
}
__global__ void k_hist(const int* __restrict__ dst) {
    int e = blockIdx.x * blockDim.x + threadIdx.x;
    if (e < EE) atomicAdd(&g_deg[dst[e]], 1);
}
// fast scan: thread-serial partials (20/thread) + one 1024 Hillis-Steele
__global__ void k_scan() {
    __shared__ int sh[1024];
    const int PER = 20;  // 1024*20 >= NN
    int tid = threadIdx.x;
    int base = tid * PER;
    int local[PER];
    int sum = 0;
#pragma unroll
    for (int i = 0; i < PER; i++) {
        int idx = base + i;
        int v = (idx < NN) ? g_deg[idx] : 0;
        local[i] = sum;
        sum += v;
    }
    sh[tid] = sum;
    __syncthreads();
    for (int off = 1; off < 1024; off <<= 1) {
        int t = (tid >= off) ? sh[tid - off] : 0;
        __syncthreads();
        sh[tid] += t;
        __syncthreads();
    }
    int carry = (tid > 0) ? sh[tid - 1] : 0;
#pragma unroll
    for (int i = 0; i < PER; i++) {
        int idx = base + i;
        if (idx < NN) g_rowptr[idx] = carry + local[i];
    }
    if (tid == 1023) g_rowptr[NN] = sh[1023];
}
__global__ void k_scatter(const int* __restrict__ src, const int* __restrict__ dst) {
    int e = blockIdx.x * blockDim.x + threadIdx.x;
    if (e >= EE) return;
    int d = dst[e];
    int pos = atomicAdd(&g_fill[d], 1);
    g_csrc[g_rowptr[d] + pos] = src[e];
}

// ---------------- fused prep: sage mean (cols [0,128)) + x (cols [128,256)) ---
__global__ void k_prep1(const float* __restrict__ x, __half* __restrict__ img) {
    int w = (blockIdx.x * blockDim.x + threadIdx.x) >> 5;
    int lane = threadIdx.x & 31;
    if (w >= NN) return;
    int beg = g_rowptr[w], end = g_rowptr[w + 1];
    float4 acc = make_float4(0.f, 0.f, 0.f, 0.f);
#pragma unroll 4
    for (int e = beg; e < end; e++) {
        int s = g_csrc[e];
        float4 xv = *(const float4*)(x + (size_t)s * 128 + lane * 4);
        acc.x += xv.x; acc.y += xv.y; acc.z += xv.z; acc.w += xv.w;
    }
    float inv = 1.0f / fmaxf((float)(end - beg), 1.0f);
    acc.x *= inv; acc.y *= inv; acc.z *= inv; acc.w *= inv;
    __half* row = img + (size_t)w * 512;
    img_write4(row, 256, lane * 4, acc);
    float4 xo = *(const float4*)(x + (size_t)w * 128 + lane * 4);
    img_write4(row, 256, 128 + lane * 4, xo);
}

// ---------------- SAGE mean aggregation over fp16 h1 -> image cols [0,128) ---
__global__ void k_sage_agg_h(const __half* __restrict__ x, __half* __restrict__ img) {
    int w = (blockIdx.x * blockDim.x + threadIdx.x) >> 5;
    int lane = threadIdx.x & 31;
    if (w >= NN) return;
    int beg = g_rowptr[w], end = g_rowptr[w + 1];
    float4 acc = make_float4(0.f, 0.f, 0.f, 0.f);
#pragma unroll 4
    for (int e = beg; e < end; e++) {
        int s = g_csrc[e];
        float4 xv = ldkv4(x + (size_t)s * 128 + lane * 4);
        acc.x += xv.x; acc.y += xv.y; acc.z += xv.z; acc.w += xv.w;
    }
    float inv = 1.0f / fmaxf((float)(end - beg), 1.0f);
    acc.x *= inv; acc.y *= inv; acc.z *= inv; acc.w *= inv;
    img_write4(img + (size_t)w * 512, 256, lane * 4, acc);
}

// ---------------- fused weight conversion: all 12 tensors, fp16 hi only ------
struct WJob { const float *w1, *w2; int k1, K, nw, off, cumEnd; };
struct WJobs { WJob j[12]; };
#define WTOTAL 819200

__global__ void k_convW_all(WJobs jobs) {
    int idx = blockIdx.x * blockDim.x + threadIdx.x;
    if (idx >= WTOTAL) return;
    int s = 0;
    while (idx >= jobs.j[s].cumEnd) s++;
    const WJob J = jobs.j[s];
    int local = idx - (s ? jobs.j[s - 1].cumEnd : 0);
    int n = local / J.K;
    int k = local - n * J.K;
    float val = (k < J.k1) ? J.w1[(size_t)k * J.nw + n] : J.w2[(size_t)(k - J.k1) * J.nw + n];
    g_Wh[(size_t)J.off + (size_t)n * J.K + k] = __float2half_rn(val);
}

// ---------------- 3-stage pipelined mma.sync fp16 GEMM, templated BN ---------
// A compact [M][2K] hi|lo fp16; W [Nc][K] fp16; logical K-tiles 2K/64.
// W chunk for logical tile c is (c mod KA) -- same W streamed for hi and lo.
#define NSTAGE 3

template <int BN>
__global__ void __launch_bounds__(256, 2)
gemm_mma(const __half* __restrict__ A, const __half* __restrict__ W,
         const float* __restrict__ b0, const float* __restrict__ b1,
         const float* __restrict__ b2, const float* __restrict__ b3,
         int Nc, int Kbase, int act,
         __half* __restrict__ img, int imgK, int imgColOff,
         const int* __restrict__ batch, float* __restrict__ pool,
         __half* __restrict__ outh) {
    constexpr int STB = 16384 + BN * 128;       // A tile 16KB + B tile
    constexpr int MI = (BN == 128) ? 4 : 2;     // warp M sub-tiles (x16 rows)
    extern __shared__ char smem[];
    const int tid = threadIdx.x;
    const int wid = tid >> 5, lane = tid & 31;
    const int bm = blockIdx.y * 128;
    const int bn = blockIdx.x * BN;
    const int wm = (BN == 128) ? ((wid & 1) << 6) : ((wid & 3) << 5);
    const int wn = (BN == 128) ? ((wid >> 1) << 5) : ((wid >> 2) << 5);
    const uint32_t sb = smem_u32(smem);

    float acc[MI][4][4];
#pragma unroll
    for (int i = 0; i < MI; i++)
#pragma unroll
        for (int j = 0; j < 4; j++)
#pragma unroll
            for (int t = 0; t < 4; t++) acc[i][j][t] = 0.f;

    const int KA = Kbase >> 6;        // W chunks (and A hi chunks)
    const int nK = 2 * KA;            // logical k-tiles: hi pass + lo pass
    const int KtotA = 2 * Kbase;

    auto issue = [&](int c, int buf) {
        int wc = (c < KA) ? c : (c - KA);       // W chunk (replayed for lo pass)
        int ka0 = c << 6;                       // A chunk = logical tile
        int kw0 = wc << 6;
        uint32_t base = sb + buf * STB;
#pragma unroll
        for (int l = 0; l < 4; l++) {
            int idx = tid + l * 256;
            int row = idx >> 3, u = idx & 7;
            uint32_t sw = row * 128 + ((u ^ (row & 7)) << 4);
            cpa16(base + sw, A + (size_t)(bm + row) * KtotA + ka0 + u * 8);
        }
#pragma unroll
        for (int l = 0; l < BN / 32; l++) {
            int idx = tid + l * 256;
            int row = idx >> 3, u = idx & 7;
            uint32_t sw = row * 128 + ((u ^ (row & 7)) << 4);
            cpa16(base + 16384 + sw, W + (size_t)(bn + row) * Kbase + kw0 + u * 8);
        }
        asm volatile("cp.async.commit_group;" ::: "memory");
    };

    issue(0, 0);
    if (nK > 1) issue(1, 1);
    for (int c = 0; c < nK; c++) {
        if (c + 1 < nK) asm volatile("cp.async.wait_group 1;" ::: "memory");
        else            asm volatile("cp.async.wait_group 0;" ::: "memory");
        __syncthreads();          // retires all readers of buffer (c-1)%3
        if (c + 2 < nK) issue(c + 2, (c + 2) % NSTAGE);   // writes (c-1)%3: safe

        int buf = c % NSTAGE;
        uint32_t sAb = sb + buf * STB;
        uint32_t sBb = sAb + 16384;
#pragma unroll
        for (int s = 0; s < 4; s++) {
            uint32_t a[MI][4], b[4][2];
#pragma unroll
            for (int i = 0; i < MI; i++) {
                int row = wm + i * 16 + (lane & 15);
                int u = (s << 1) + (lane >> 4);
                uint32_t ad = sAb + row * 128 + ((u ^ (row & 7)) << 4);
                asm volatile("ldmatrix.sync.aligned.m8n8.x4.shared.b16 {%0,%1,%2,%3}, [%4];"
                    : "=r"(a[i][0]), "=r"(a[i][1]), "=r"(a[i][2]), "=r"(a[i][3]) : "r"(ad));
            }
#pragma unroll
            for (int jj = 0; jj < 2; jj++) {
                int row = wn + (jj << 4) + ((lane >> 4) << 3) + (lane & 7);
                int u = (s << 1) + ((lane >> 3) & 1);
                uint32_t ad = sBb + row * 128 + ((u ^ (row & 7)) << 4);
                asm volatile("ldmatrix.sync.aligned.m8n8.x4.shared.b16 {%0,%1,%2,%3}, [%4];"
                    : "=r"(b[jj * 2][0]), "=r"(b[jj * 2][1]),
                      "=r"(b[jj * 2 + 1][0]), "=r"(b[jj * 2 + 1][1]) : "r"(ad));
            }
#pragma unroll
            for (int i = 0; i < MI; i++)
#pragma unroll
                for (int j = 0; j < 4; j++)
                    asm volatile("mma.sync.aligned.m16n8k16.row.col.f32.f16.f16.f32 "
                        "{%0,%1,%2,%3}, {%4,%5,%6,%7}, {%8,%9}, {%0,%1,%2,%3};"
                        : "+f"(acc[i][j][0]), "+f"(acc[i][j][1]),
                          "+f"(acc[i][j][2]), "+f"(acc[i][j][3])
                        : "r"(a[i][0]), "r"(a[i][1]), "r"(a[i][2]), "r"(a[i][3]),
                          "r"(b[j][0]), "r"(b[j][1]));
        }
    }

    // epilogue
    const float* bsel[4] = {b0, b1, b2, b3};
    const int stride2K = 2 * imgK;
#pragma unroll
    for (int i = 0; i < MI; i++) {
        int r0 = bm + wm + i * 16 + (lane >> 2);
        int r1 = r0 + 8;
#pragma unroll
        for (int j = 0; j < 4; j++) {
            int c = bn + wn + (j << 3) + ((lane & 3) << 1);
            const float* bp = bsel[c >> 8];
            float bv0 = bp[c & 255], bv1 = bp[(c & 255) + 1];
            float v00 = acc[i][j][0] + bv0, v01 = acc[i][j][1] + bv1;
            float v10 = acc[i][j][2] + bv0, v11 = acc[i][j][3] + bv1;
            if (act == 1) {
                v00 = fmaxf(v00, 0.f); v01 = fmaxf(v01, 0.f);
                v10 = fmaxf(v10, 0.f); v11 = fmaxf(v11, 0.f);
            } else if (act == 2) {
                v00 = 1.f / (1.f + __expf(-v00)); v01 = 1.f / (1.f + __expf(-v01));
                v10 = 1.f / (1.f + __expf(-v10)); v11 = 1.f / (1.f + __expf(-v11));
            }
            if (outh) {
                if (r0 < NN)
                    *(__half2*)(outh + (size_t)r0 * Nc + c) = __floats2half2_rn(v00, v01);
                if (r1 < NN)
                    *(__half2*)(outh + (size_t)r1 * Nc + c) = __floats2half2_rn(v10, v11);
            }
            if (img) {
                int ic = imgColOff + c;
                if (r0 < NN) {
                    __half* row = img + (size_t)r0 * stride2K;
                    __half2 hh = __floats2half2_rn(v00, v01);
                    __half2 ll = __floats2half2_rn(v00 - __half2float(__low2half(hh)),
                                                   v01 - __half2float(__high2half(hh)));
                    *(__half2*)(row + ic) = hh;
                    *(__half2*)(row + imgK + ic) = ll;
                }
                if (r1 < NN) {
                    __half* row = img + (size_t)r1 * stride2K;
                    __half2 hh = __floats2half2_rn(v10, v11);
                    __half2 ll = __floats2half2_rn(v10 - __half2float(__low2half(hh)),
                                                   v11 - __half2float(__high2half(hh)));
                    *(__half2*)(row + ic) = hh;
                    *(__half2*)(row + imgK + ic) = ll;
                }
            }
            if (pool) {
                if (r0 < NN) {
                    int g = batch[r0] * 128;
                    atomicMax((int*)&pool[g + c], __float_as_int(v00));
                    atomicMax((int*)&pool[g + c + 1], __float_as_int(v01));
                }
                if (r1 < NN) {
                    int g = batch[r1] * 128;
                    atomicMax((int*)&pool[g + c], __float_as_int(v10));
                    atomicMax((int*)&pool[g + c + 1], __float_as_int(v11));
                }
            }
        }
    }
}

// ---------------- attention: warp per node, 8 heads, pairwise, all-fp16 ------
__device__ __forceinline__ float dot4(float4 a, float4 b) {
    return a.x * b.x + a.y * b.y + a.z * b.z + a.w * b.w;
}

__global__ void k_attn(const __half* __restrict__ kvh, __half* __restrict__ img) {
    int node = (blockIdx.x * blockDim.x + threadIdx.x) >> 5;
    if (node >= NN) return;
    int lane = threadIdx.x & 31;
    const __half* base = kvh + (size_t)node * 1024;
    const float scl = 0.17677669529663687f;
    float4 q0 = ldkv4(base + lane * 4);
    float4 q1 = ldkv4(base + 128 + lane * 4);
    q0.x *= scl; q0.y *= scl; q0.z *= scl; q0.w *= scl;
    q1.x *= scl; q1.y *= scl; q1.z *= scl; q1.w *= scl;
    int beg = g_rowptr[node], end = g_rowptr[node + 1];
    float m0 = -3.0e38f, s0 = 0.f, m1 = -3.0e38f, s1 = 0.f;
    float4 a0 = make_float4(0.f, 0.f, 0.f, 0.f);
    float4 a1 = make_float4(0.f, 0.f, 0.f, 0.f);
    int e = beg;
    for (; e + 1 < end; e += 2) {
        int sa = g_csrc[e], sbn = g_csrc[e + 1];
        const __half* ka = kvh + (size_t)sa * 1024 + 256;
        const __half* kb = kvh + (size_t)sbn * 1024 + 256;
        float4 ka0 = ldkv4(ka + lane * 4);
        float4 ka1 = ldkv4(ka + 128 + lane * 4);
        float4 va0 = ldkv4(ka + 256 + lane * 4);
        float4 va1 = ldkv4(ka + 384 + lane * 4);
        float4 kb0 = ldkv4(kb + lane * 4);
        float4 kb1 = ldkv4(kb + 128 + lane * 4);
        float4 vb0 = ldkv4(kb + 256 + lane * 4);
        float4 vb1 = ldkv4(kb + 384 + lane * 4);
        float da0 = dot4(q0, ka0), da1 = dot4(q1, ka1);
        float db0 = dot4(q0, kb0), db1 = dot4(q1, kb1);
#pragma unroll
        for (int off = 4; off; off >>= 1) {
            da0 += __shfl_xor_sync(0xffffffffu, da0, off);
            da1 += __shfl_xor_sync(0xffffffffu, da1, off);
            db0 += __shfl_xor_sync(0xffffffffu, db0, off);
            db1 += __shfl_xor_sync(0xffffffffu, db1, off);
        }
        {
            float mn = fmaxf(m0, fmaxf(da0, db0));
            float sc = __expf(m0 - mn);
            float pa = __expf(da0 - mn);
            float pb = __expf(db0 - mn);
            s0 = s0 * sc + pa + pb;
            a0.x = a0.x * sc + pa * va0.x + pb * vb0.x;
            a0.y = a0.y * sc + pa * va0.y + pb * vb0.y;
            a0.z = a0.z * sc + pa * va0.z + pb * vb0.z;
            a0.w = a0.w * sc + pa * va0.w + pb * vb0.w;
            m0 = mn;
        }
        {
            float mn = fmaxf(m1, fmaxf(da1, db1));
            float sc = __expf(m1 - mn);
            float pa = __expf(da1 - mn);
            float pb = __expf(db1 - mn);
            s1 = s1 * sc + pa + pb;
            a1.x = a1.x * sc + pa * va1.x + pb * vb1.x;
            a1.y = a1.y * sc + pa * va1.y + pb * vb1.y;
            a1.z = a1.z * sc + pa * va1.z + pb * vb1.z;
            a1.w = a1.w * sc + pa * va1.w + pb * vb1.w;
            m1 = mn;
        }
    }
    if (e < end) {   // tail edge
        int sn = g_csrc[e];
        const __half* kb = kvh + (size_t)sn * 1024 + 256;
        float4 k0 = ldkv4(kb + lane * 4);
        float4 k1 = ldkv4(kb + 128 + lane * 4);
        float4 v0 = ldkv4(kb + 256 + lane * 4);
        float4 v1 = ldkv4(kb + 384 + lane * 4);
        float d0 = dot4(q0, k0), d1 = dot4(q1, k1);
#pragma unroll
        for (int off = 4; off; off >>= 1) {
            d0 += __shfl_xor_sync(0xffffffffu, d0, off);
            d1 += __shfl_xor_sync(0xffffffffu, d1, off);
        }
        float mn0 = fmaxf(m0, d0);
        float sc0 = __expf(m0 - mn0);
        float p0 = __expf(d0 - mn0);
        s0 = s0 * sc0 + p0;
        a0.x = a0.x * sc0 + p0 * v0.x; a0.y = a0.y * sc0 + p0 * v0.y;
        a0.z = a0.z * sc0 + p0 * v0.z; a0.w = a0.w * sc0 + p0 * v0.w;
        m0 = mn0;
        float mn1 = fmaxf(m1, d1);
        float sc1 = __expf(m1 - mn1);
        float p1 = __expf(d1 - mn1);
        s1 = s1 * sc1 + p1;
        a1.x = a1.x * sc1 + p1 * v1.x; a1.y = a1.y * sc1 + p1 * v1.y;
        a1.z = a1.z * sc1 + p1 * v1.z; a1.w = a1.w * sc1 + p1 * v1.w;
        m1 = mn1;
    }
    float inv0 = (end > beg) ? (1.f / s0) : 0.f;
    float inv1 = (end > beg) ? (1.f / s1) : 0.f;
    float4 sk0 = ldkv4(base + 768 + lane * 4);
    float4 sk1 = ldkv4(base + 896 + lane * 4);
    float4 o0, o1;
    o0.x = fmaxf(sk0.x + a0.x * inv0, 0.f); o0.y = fmaxf(sk0.y + a0.y * inv0, 0.f);
    o0.z = fmaxf(sk0.z + a0.z * inv0, 0.f); o0.w = fmaxf(sk0.w + a0.w * inv0, 0.f);
    o1.x = fmaxf(sk1.x + a1.x * inv1, 0.f); o1.y = fmaxf(sk1.y + a1.y * inv1, 0.f);
    o1.z = fmaxf(sk1.z + a1.z * inv1, 0.f); o1.w = fmaxf(sk1.w + a1.w * inv1, 0.f);
    __half* row = img + (size_t)node * 512;
    img_write4(row, 256, lane * 4, o0);
    img_write4(row, 256, 128 + lane * 4, o1);
}

// ---------------- host orchestration ----------------
static void run_gemm(int bn, const __half* A, const __half* W,
                     const float* b0, const float* b1, const float* b2, const float* b3,
                     int Nc, int Kbase, int act,
                     __half* img, int imgK, int imgColOff,
                     const int* batch, float* pool, __half* outh) {
    dim3 grid(Nc / bn, NTILES);
    if (bn == 64)
        gemm_mma<64><<<grid, 256, NSTAGE * (16384 + 64 * 128)>>>(A, W, b0, b1, b2, b3, Nc,
                                                                 Kbase, act, img, imgK,
                                                                 imgColOff, batch, pool, outh);
    else
        gemm_mma<128><<<grid, 256, NSTAGE * (16384 + 128 * 128)>>>(A, W, b0, b1, b2, b3, Nc,
                                                                   Kbase, act, img, imgK,
                                                                   imgColOff, batch, pool, outh);
}

extern "C" void kernel_launch(void* const* d_in, const int* in_sizes, int n_in,
                              void* d_out, int out_size) {
    const float* x     = (const float*)d_in[0];
    const int*   ei    = (const int*)d_in[1];
    const int*   batch = (const int*)d_in[2];
    const float* s1_wl = (const float*)d_in[3];
    const float* s1_bl = (const float*)d_in[4];
    const float* s1_wr = (const float*)d_in[5];
    const float* s2_wl = (const float*)d_in[6];
    const float* s2_bl = (const float*)d_in[7];
    const float* s2_wr = (const float*)d_in[8];
    const float* t1_wq = (const float*)d_in[9];
    const float* t1_bq = (const float*)d_in[10];
    const float* t1_wk = (const float*)d_in[11];
    const float* t1_bk = (const float*)d_in[12];
    const float* t1_wv = (const float*)d_in[13];
    const float* t1_bv = (const float*)d_in[14];
    const float* t1_ws = (const float*)d_in[15];
    const float* t1_bs = (const float*)d_in[16];
    const float* t2_wq = (const float*)d_in[17];
    const float* t2_bq = (const float*)d_in[18];
    const float* t2_wk = (const float*)d_in[19];
    const float* t2_bk = (const float*)d_in[20];
    const float* t2_wv = (const float*)d_in[21];
    const float* t2_bv = (const float*)d_in[22];
    const float* t2_ws = (const float*)d_in[23];
    const float* t2_bs = (const float*)d_in[24];
    const float* p1_w  = (const float*)d_in[25];
    const float* p1_b  = (const float*)d_in[26];
    const float* p2_w  = (const float*)d_in[27];
    const float* p2_b  = (const float*)d_in[28];

    const int* e_src = ei;
    const int* e_dst = ei + EE;

    cudaFuncSetAttribute(gemm_mma<128>, cudaFuncAttributeMaxDynamicSharedMemorySize,
                         NSTAGE * (16384 + 128 * 128));
    cudaFuncSetAttribute(gemm_mma<64>, cudaFuncAttributeMaxDynamicSharedMemorySize,
                         NSTAGE * (16384 + 64 * 128));

    __half *d_h1h, *d_kvh, *d_i0, *d_i1, *d_W;
    cudaGetSymbolAddress((void**)&d_h1h, g_h1h);
    cudaGetSymbolAddress((void**)&d_kvh, g_kvh);
    cudaGetSymbolAddress((void**)&d_i0, g_img0);
    cudaGetSymbolAddress((void**)&d_i1, g_img1);
    cudaGetSymbolAddress((void**)&d_W, g_Wh);

    // CSR build
    k_zero<<<(NN + 255) / 256, 256>>>((float*)d_out);
    k_hist<<<(EE + 255) / 256, 256>>>(e_dst);
    k_scan<<<1, 1024>>>();
    k_scatter<<<(EE + 255) / 256, 256>>>(e_src, e_dst);

    // fused weight conversion (one launch for all 12 tensors)
    {
        WJobs jobs;
        int cum = 0, idx = 0;
        auto add = [&](const float* w1, const float* w2, int k1, int K, int nw, int off) {
            cum += nw * K;
            jobs.j[idx++] = WJob{w1, w2, k1, K, nw, off, cum};
        };
        add(s1_wl, s1_wr, 128, 256, 128, OFF_S1);
        add(s2_wl, s2_wr, 128, 256, 256, OFF_S2);
        add(t1_wq, t1_wq, 256, 256, 256, OFF_T1 + 0 * 65536);
        add(t1_wk, t1_wk, 256, 256, 256, OFF_T1 + 1 * 65536);
        add(t1_wv, t1_wv, 256, 256, 256, OFF_T1 + 2 * 65536);
        add(t1_ws, t1_ws, 256, 256, 256, OFF_T1 + 3 * 65536);
        add(t2_wq, t2_wq, 256, 256, 256, OFF_T2 + 0 * 65536);
        add(t2_wk, t2_wk, 256, 256, 256, OFF_T2 + 1 * 65536);
        add(t2_wv, t2_wv, 256, 256, 256, OFF_T2 + 2 * 65536);
        add(t2_ws, t2_ws, 256, 256, 256, OFF_T2 + 3 * 65536);
        add(p1_w, p1_w, 256, 256, 512, OFF_P1);
        add(p2_w, p2_w, 512, 512, 128, OFF_P2);
        k_convW_all<<<(WTOTAL + 255) / 256, 256>>>(jobs);
    }

    // SAGE 1 input image (img0): mean(x) + x in one launch
    k_prep1<<<(NN * 32 + 255) / 256, 256>>>(x, d_i0);
    // S1: h1 -> fp16 + img1 cols [128,256)
    run_gemm(64, d_i0, d_W + OFF_S1, s1_bl, s1_bl, s1_bl, s1_bl,
             128, 256, 1, d_i1, 256, 128, nullptr, nullptr, d_h1h);

    // SAGE 2: mean(h1 fp16) -> img1[0:128); S2 -> img0[0:256)
    k_sage_agg_h<<<(NN * 32 + 255) / 256, 256>>>(d_h1h, d_i1);
    run_gemm(64, d_i1, d_W + OFF_S2, s2_bl, s2_bl, s2_bl, s2_bl,
             256, 256, 1, d_i0, 256, 0, nullptr, nullptr, nullptr);

    // TransformerConv 1: q|k|v|skip all fp16 -> kvh
    run_gemm(128, d_i0, d_W + OFF_T1, t1_bq, t1_bk, t1_bv, t1_bs,
             1024, 256, 0, nullptr, 0, 0, nullptr, nullptr, d_kvh);
    k_attn<<<(NN * 32 + 255) / 256, 256>>>(d_kvh, d_i1);

    // TransformerConv 2
    run_gemm(128, d_i1, d_W + OFF_T2, t2_bq, t2_bk, t2_bv, t2_bs,
             1024, 256, 0, nullptr, 0, 0, nullptr, nullptr, d_kvh);
    k_attn<<<(NN * 32 + 255) / 256, 256>>>(d_kvh, d_i0);

    // proj MLP: P1 -> img1 (K=512 compact); P2 -> sigmoid + fused pool
    run_gemm(64, d_i0, d_W + OFF_P1, p1_b, p1_b + 256, p1_b, p1_b,
             512, 256, 1, d_i1, 512, 0, nullptr, nullptr, nullptr);
    run_gemm(64, d_i1, d_W + OFF_P2, p2_b, p2_b, p2_b, p2_b,
             128, 512, 2, nullptr, 0, 0, batch, (float*)d_out, nullptr);
}

// round 13
// speedup vs baseline: 1.9648x; 1.3400x over previous
#include <cuda_runtime.h>
#include <cuda_bf16.h>
#include <cuda_fp16.h>
#include <math.h>
#include <stdint.h>

#define NN 20000
#define EE 320000
#define GG 64
#define MPAD 20096          // 157 * 128
#define NTILES 157

// ---------------- device scratch ----------------
__device__ __half g_kvh[(size_t)NN * 1024];     // q|k|v|skip fp16 per node
__device__ int g_deg[NN];
__device__ int g_fill[NN];
__device__ int g_rowptr[NN + 1];
__device__ int g_csrc[EE];

// ping-pong plain fp16 activation images: [MPAD][K], widest K=512
__device__ __half g_img0[(size_t)MPAD * 512];
__device__ __half g_img1[(size_t)MPAD * 512];
// fp16 weight images, layout [Nc][K]
__device__ __half g_Wh[819200];

// weight image offsets (elements)
#define OFF_S1   0          // 128 x 256
#define OFF_S2   32768      // 256 x 256
#define OFF_T1   98304      // 4 x (256 x 256)
#define OFF_T2   360448
#define OFF_P1   622592     // 512 x 256
#define OFF_P2   753664     // 128 x 512

__device__ __forceinline__ uint32_t smem_u32(const void* p) {
    uint32_t a;
    asm("{ .reg .u64 t; cvta.to.shared.u64 t, %1; cvt.u32.u64 %0, t; }" : "=r"(a) : "l"(p));
    return a;
}
__device__ __forceinline__ void cpa16(uint32_t dst, const void* src) {
    asm volatile("cp.async.cg.shared.global [%0], [%1], 16;" :: "r"(dst), "l"(src));
}
// store 4 floats as 4 fp16
__device__ __forceinline__ void sth4(__half* p, float4 v) {
    *(__half2*)p = __floats2half2_rn(v.x, v.y);
    *(__half2*)(p + 2) = __floats2half2_rn(v.z, v.w);
}
// load 4 consecutive fp16 values as float4
__device__ __forceinline__ float4 ldkv4(const __half* p) {
    uint2 u = *(const uint2*)p;
    __half2 a = *reinterpret_cast<const __half2*>(&u.x);
    __half2 b = *reinterpret_cast<const __half2*>(&u.y);
    float2 fa = __half22float2(a), fb = __half22float2(b);
    return make_float4(fa.x, fa.y, fb.x, fb.y);
}

// ---------------- CSR build ----------------
__global__ void k_zero(float* out) {
    int i = blockIdx.x * blockDim.x + threadIdx.x;
    if (i < NN) { g_deg[i] = 0; g_fill[i] = 0; }
    if (i < GG * 128) out[i] = 0.0f;
}
__global__ void k_hist(const int* __restrict__ dst) {
    int e = blockIdx.x * blockDim.x + threadIdx.x;
    if (e < EE) atomicAdd(&g_deg[dst[e]], 1);
}
// fast scan: thread-serial partials (20/thread) + one 1024 Hillis-Steele
__global__ void k_scan() {
    __shared__ int sh[1024];
    const int PER = 20;  // 1024*20 >= NN
    int tid = threadIdx.x;
    int base = tid * PER;
    int local[PER];
    int sum = 0;
#pragma unroll
    for (int i = 0; i < PER; i++) {
        int idx = base + i;
        int v = (idx < NN) ? g_deg[idx] : 0;
        local[i] = sum;
        sum += v;
    }
    sh[tid] = sum;
    __syncthreads();
    for (int off = 1; off < 1024; off <<= 1) {
        int t = (tid >= off) ? sh[tid - off] : 0;
        __syncthreads();
        sh[tid] += t;
        __syncthreads();
    }
    int carry = (tid > 0) ? sh[tid - 1] : 0;
#pragma unroll
    for (int i = 0; i < PER; i++) {
        int idx = base + i;
        if (idx < NN) g_rowptr[idx] = carry + local[i];
    }
    if (tid == 1023) g_rowptr[NN] = sh[1023];
}
__global__ void k_scatter(const int* __restrict__ src, const int* __restrict__ dst) {
    int e = blockIdx.x * blockDim.x + threadIdx.x;
    if (e >= EE) return;
    int d = dst[e];
    int pos = atomicAdd(&g_fill[d], 1);
    g_csrc[g_rowptr[d] + pos] = src[e];
}

// ---------------- fused prep: sage mean (cols [0,128)) + x (cols [128,256)) ---
__global__ void k_prep1(const float* __restrict__ x, __half* __restrict__ img) {
    int w = (blockIdx.x * blockDim.x + threadIdx.x) >> 5;
    int lane = threadIdx.x & 31;
    if (w >= NN) return;
    int beg = g_rowptr[w], end = g_rowptr[w + 1];
    float4 acc = make_float4(0.f, 0.f, 0.f, 0.f);
#pragma unroll 4
    for (int e = beg; e < end; e++) {
        int s = g_csrc[e];
        float4 xv = *(const float4*)(x + (size_t)s * 128 + lane * 4);
        acc.x += xv.x; acc.y += xv.y; acc.z += xv.z; acc.w += xv.w;
    }
    float inv = 1.0f / fmaxf((float)(end - beg), 1.0f);
    acc.x *= inv; acc.y *= inv; acc.z *= inv; acc.w *= inv;
    __half* row = img + (size_t)w * 256;
    sth4(row + lane * 4, acc);
    float4 xo = *(const float4*)(x + (size_t)w * 128 + lane * 4);
    sth4(row + 128 + lane * 4, xo);
}

// ---------------- SAGE-2 aggregation: mean over img cols [128,256) -> [0,128)
__global__ void k_sage_agg_h(__half* __restrict__ img) {
    int w = (blockIdx.x * blockDim.x + threadIdx.x) >> 5;
    int lane = threadIdx.x & 31;
    if (w >= NN) return;
    int beg = g_rowptr[w], end = g_rowptr[w + 1];
    float4 acc = make_float4(0.f, 0.f, 0.f, 0.f);
#pragma unroll 4
    for (int e = beg; e < end; e++) {
        int s = g_csrc[e];
        float4 xv = ldkv4(img + (size_t)s * 256 + 128 + lane * 4);
        acc.x += xv.x; acc.y += xv.y; acc.z += xv.z; acc.w += xv.w;
    }
    float inv = 1.0f / fmaxf((float)(end - beg), 1.0f);
    acc.x *= inv; acc.y *= inv; acc.z *= inv; acc.w *= inv;
    sth4(img + (size_t)w * 256 + lane * 4, acc);
}

// ---------------- fused weight conversion: all 12 tensors, fp16 --------------
struct WJob { const float *w1, *w2; int k1, K, nw, off, cumEnd; };
struct WJobs { WJob j[12]; };
#define WTOTAL 819200

__global__ void k_convW_all(WJobs jobs) {
    int idx = blockIdx.x * blockDim.x + threadIdx.x;
    if (idx >= WTOTAL) return;
    int s = 0;
    while (idx >= jobs.j[s].cumEnd) s++;
    const WJob J = jobs.j[s];
    int local = idx - (s ? jobs.j[s - 1].cumEnd : 0);
    int n = local / J.K;
    int k = local - n * J.K;
    float val = (k < J.k1) ? J.w1[(size_t)k * J.nw + n] : J.w2[(size_t)(k - J.k1) * J.nw + n];
    g_Wh[(size_t)J.off + (size_t)n * J.K + k] = __float2half_rn(val);
}

// ---------------- 3-stage pipelined mma.sync fp16 GEMM, templated BN ---------
// A [M][K] fp16; W [Nc][K] fp16; K-tiles K/64.
#define NSTAGE 3

template <int BN>
__global__ void __launch_bounds__(256, 2)
gemm_mma(const __half* __restrict__ A, const __half* __restrict__ W,
         const float* __restrict__ b0, const float* __restrict__ b1,
         const float* __restrict__ b2, const float* __restrict__ b3,
         int Nc, int Kbase, int act,
         __half* __restrict__ img, int imgStride, int imgColOff,
         const int* __restrict__ batch, float* __restrict__ pool,
         __half* __restrict__ outh) {
    constexpr int STB = 16384 + BN * 128;       // A tile 16KB + B tile
    constexpr int MI = (BN == 128) ? 4 : 2;     // warp M sub-tiles (x16 rows)
    extern __shared__ char smem[];
    const int tid = threadIdx.x;
    const int wid = tid >> 5, lane = tid & 31;
    const int bm = blockIdx.y * 128;
    const int bn = blockIdx.x * BN;
    const int wm = (BN == 128) ? ((wid & 1) << 6) : ((wid & 3) << 5);
    const int wn = (BN == 128) ? ((wid >> 1) << 5) : ((wid >> 2) << 5);
    const uint32_t sb = smem_u32(smem);

    float acc[MI][4][4];
#pragma unroll
    for (int i = 0; i < MI; i++)
#pragma unroll
        for (int j = 0; j < 4; j++)
#pragma unroll
            for (int t = 0; t < 4; t++) acc[i][j][t] = 0.f;

    const int nK = Kbase >> 6;

    auto issue = [&](int c, int buf) {
        int k0 = c << 6;
        uint32_t base = sb + buf * STB;
#pragma unroll
        for (int l = 0; l < 4; l++) {
            int idx = tid + l * 256;
            int row = idx >> 3, u = idx & 7;
            uint32_t sw = row * 128 + ((u ^ (row & 7)) << 4);
            cpa16(base + sw, A + (size_t)(bm + row) * Kbase + k0 + u * 8);
        }
#pragma unroll
        for (int l = 0; l < BN / 32; l++) {
            int idx = tid + l * 256;
            int row = idx >> 3, u = idx & 7;
            uint32_t sw = row * 128 + ((u ^ (row & 7)) << 4);
            cpa16(base + 16384 + sw, W + (size_t)(bn + row) * Kbase + k0 + u * 8);
        }
        asm volatile("cp.async.commit_group;" ::: "memory");
    };

    issue(0, 0);
    if (nK > 1) issue(1, 1);
    for (int c = 0; c < nK; c++) {
        if (c + 1 < nK) asm volatile("cp.async.wait_group 1;" ::: "memory");
        else            asm volatile("cp.async.wait_group 0;" ::: "memory");
        __syncthreads();          // retires all readers of buffer (c-1)%3
        if (c + 2 < nK) issue(c + 2, (c + 2) % NSTAGE);   // writes (c-1)%3: safe

        int buf = c % NSTAGE;
        uint32_t sAb = sb + buf * STB;
        uint32_t sBb = sAb + 16384;
#pragma unroll
        for (int s = 0; s < 4; s++) {
            uint32_t a[MI][4], b[4][2];
#pragma unroll
            for (int i = 0; i < MI; i++) {
                int row = wm + i * 16 + (lane & 15);
                int u = (s << 1) + (lane >> 4);
                uint32_t ad = sAb + row * 128 + ((u ^ (row & 7)) << 4);
                asm volatile("ldmatrix.sync.aligned.m8n8.x4.shared.b16 {%0,%1,%2,%3}, [%4];"
                    : "=r"(a[i][0]), "=r"(a[i][1]), "=r"(a[i][2]), "=r"(a[i][3]) : "r"(ad));
            }
#pragma unroll
            for (int jj = 0; jj < 2; jj++) {
                int row = wn + (jj << 4) + ((lane >> 4) << 3) + (lane & 7);
                int u = (s << 1) + ((lane >> 3) & 1);
                uint32_t ad = sBb + row * 128 + ((u ^ (row & 7)) << 4);
                asm volatile("ldmatrix.sync.aligned.m8n8.x4.shared.b16 {%0,%1,%2,%3}, [%4];"
                    : "=r"(b[jj * 2][0]), "=r"(b[jj * 2][1]),
                      "=r"(b[jj * 2 + 1][0]), "=r"(b[jj * 2 + 1][1]) : "r"(ad));
            }
#pragma unroll
            for (int i = 0; i < MI; i++)
#pragma unroll
                for (int j = 0; j < 4; j++)
                    asm volatile("mma.sync.aligned.m16n8k16.row.col.f32.f16.f16.f32 "
                        "{%0,%1,%2,%3}, {%4,%5,%6,%7}, {%8,%9}, {%0,%1,%2,%3};"
                        : "+f"(acc[i][j][0]), "+f"(acc[i][j][1]),
                          "+f"(acc[i][j][2]), "+f"(acc[i][j][3])
                        : "r"(a[i][0]), "r"(a[i][1]), "r"(a[i][2]), "r"(a[i][3]),
                          "r"(b[j][0]), "r"(b[j][1]));
        }
    }

    // epilogue
    const float* bsel[4] = {b0, b1, b2, b3};
#pragma unroll
    for (int i = 0; i < MI; i++) {
        int r0 = bm + wm + i * 16 + (lane >> 2);
        int r1 = r0 + 8;
#pragma unroll
        for (int j = 0; j < 4; j++) {
            int c = bn + wn + (j << 3) + ((lane & 3) << 1);
            const float* bp = bsel[c >> 8];
            float bv0 = bp[c & 255], bv1 = bp[(c & 255) + 1];
            float v00 = acc[i][j][0] + bv0, v01 = acc[i][j][1] + bv1;
            float v10 = acc[i][j][2] + bv0, v11 = acc[i][j][3] + bv1;
            if (act == 1) {
                v00 = fmaxf(v00, 0.f); v01 = fmaxf(v01, 0.f);
                v10 = fmaxf(v10, 0.f); v11 = fmaxf(v11, 0.f);
            } else if (act == 2) {
                v00 = 1.f / (1.f + __expf(-v00)); v01 = 1.f / (1.f + __expf(-v01));
                v10 = 1.f / (1.f + __expf(-v10)); v11 = 1.f / (1.f + __expf(-v11));
            }
            if (outh) {
                if (r0 < NN)
                    *(__half2*)(outh + (size_t)r0 * Nc + c) = __floats2half2_rn(v00, v01);
                if (r1 < NN)
                    *(__half2*)(outh + (size_t)r1 * Nc + c) = __floats2half2_rn(v10, v11);
            }
            if (img) {
                int ic = imgColOff + c;
                if (r0 < NN)
                    *(__half2*)(img + (size_t)r0 * imgStride + ic) = __floats2half2_rn(v00, v01);
                if (r1 < NN)
                    *(__half2*)(img + (size_t)r1 * imgStride + ic) = __floats2half2_rn(v10, v11);
            }
            if (pool) {
                if (r0 < NN) {
                    int g = batch[r0] * 128;
                    atomicMax((int*)&pool[g + c], __float_as_int(v00));
                    atomicMax((int*)&pool[g + c + 1], __float_as_int(v01));
                }
                if (r1 < NN) {
                    int g = batch[r1] * 128;
                    atomicMax((int*)&pool[g + c], __float_as_int(v10));
                    atomicMax((int*)&pool[g + c + 1], __float_as_int(v11));
                }
            }
        }
    }
}

// ---------------- attention: warp per node, 8 heads, pairwise, all-fp16 ------
__device__ __forceinline__ float dot4(float4 a, float4 b) {
    return a.x * b.x + a.y * b.y + a.z * b.z + a.w * b.w;
}

__global__ void k_attn(const __half* __restrict__ kvh, __half* __restrict__ img) {
    int node = (blockIdx.x * blockDim.x + threadIdx.x) >> 5;
    if (node >= NN) return;
    int lane = threadIdx.x & 31;
    const __half* base = kvh + (size_t)node * 1024;
    const float scl = 0.17677669529663687f;
    float4 q0 = ldkv4(base + lane * 4);
    float4 q1 = ldkv4(base + 128 + lane * 4);
    q0.x *= scl; q0.y *= scl; q0.z *= scl; q0.w *= scl;
    q1.x *= scl; q1.y *= scl; q1.z *= scl; q1.w *= scl;
    int beg = g_rowptr[node], end = g_rowptr[node + 1];
    float m0 = -3.0e38f, s0 = 0.f, m1 = -3.0e38f, s1 = 0.f;
    float4 a0 = make_float4(0.f, 0.f, 0.f, 0.f);
    float4 a1 = make_float4(0.f, 0.f, 0.f, 0.f);
    int e = beg;
    for (; e + 1 < end; e += 2) {
        int sa = g_csrc[e], sbn = g_csrc[e + 1];
        const __half* ka = kvh + (size_t)sa * 1024 + 256;
        const __half* kb = kvh + (size_t)sbn * 1024 + 256;
        float4 ka0 = ldkv4(ka + lane * 4);
        float4 ka1 = ldkv4(ka + 128 + lane * 4);
        float4 va0 = ldkv4(ka + 256 + lane * 4);
        float4 va1 = ldkv4(ka + 384 + lane * 4);
        float4 kb0 = ldkv4(kb + lane * 4);
        float4 kb1 = ldkv4(kb + 128 + lane * 4);
        float4 vb0 = ldkv4(kb + 256 + lane * 4);
        float4 vb1 = ldkv4(kb + 384 + lane * 4);
        float da0 = dot4(q0, ka0), da1 = dot4(q1, ka1);
        float db0 = dot4(q0, kb0), db1 = dot4(q1, kb1);
#pragma unroll
        for (int off = 4; off; off >>= 1) {
            da0 += __shfl_xor_sync(0xffffffffu, da0, off);
            da1 += __shfl_xor_sync(0xffffffffu, da1, off);
            db0 += __shfl_xor_sync(0xffffffffu, db0, off);
            db1 += __shfl_xor_sync(0xffffffffu, db1, off);
        }
        {
            float mn = fmaxf(m0, fmaxf(da0, db0));
            float sc = __expf(m0 - mn);
            float pa = __expf(da0 - mn);
            float pb = __expf(db0 - mn);
            s0 = s0 * sc + pa + pb;
            a0.x = a0.x * sc + pa * va0.x + pb * vb0.x;
            a0.y = a0.y * sc + pa * va0.y + pb * vb0.y;
            a0.z = a0.z * sc + pa * va0.z + pb * vb0.z;
            a0.w = a0.w * sc + pa * va0.w + pb * vb0.w;
            m0 = mn;
        }
        {
            float mn = fmaxf(m1, fmaxf(da1, db1));
            float sc = __expf(m1 - mn);
            float pa = __expf(da1 - mn);
            float pb = __expf(db1 - mn);
            s1 = s1 * sc + pa + pb;
            a1.x = a1.x * sc + pa * va1.x + pb * vb1.x;
            a1.y = a1.y * sc + pa * va1.y + pb * vb1.y;
            a1.z = a1.z * sc + pa * va1.z + pb * vb1.z;
            a1.w = a1.w * sc + pa * va1.w + pb * vb1.w;
            m1 = mn;
        }
    }
    if (e < end) {   // tail edge
        int sn = g_csrc[e];
        const __half* kb = kvh + (size_t)sn * 1024 + 256;
        float4 k0 = ldkv4(kb + lane * 4);
        float4 k1 = ldkv4(kb + 128 + lane * 4);
        float4 v0 = ldkv4(kb + 256 + lane * 4);
        float4 v1 = ldkv4(kb + 384 + lane * 4);
        float d0 = dot4(q0, k0), d1 = dot4(q1, k1);
#pragma unroll
        for (int off = 4; off; off >>= 1) {
            d0 += __shfl_xor_sync(0xffffffffu, d0, off);
            d1 += __shfl_xor_sync(0xffffffffu, d1, off);
        }
        float mn0 = fmaxf(m0, d0);
        float sc0 = __expf(m0 - mn0);
        float p0 = __expf(d0 - mn0);
        s0 = s0 * sc0 + p0;
        a0.x = a0.x * sc0 + p0 * v0.x; a0.y = a0.y * sc0 + p0 * v0.y;
        a0.z = a0.z * sc0 + p0 * v0.z; a0.w = a0.w * sc0 + p0 * v0.w;
        m0 = mn0;
        float mn1 = fmaxf(m1, d1);
        float sc1 = __expf(m1 - mn1);
        float p1 = __expf(d1 - mn1);
        s1 = s1 * sc1 + p1;
        a1.x = a1.x * sc1 + p1 * v1.x; a1.y = a1.y * sc1 + p1 * v1.y;
        a1.z = a1.z * sc1 + p1 * v1.z; a1.w = a1.w * sc1 + p1 * v1.w;
        m1 = mn1;
    }
    float inv0 = (end > beg) ? (1.f / s0) : 0.f;
    float inv1 = (end > beg) ? (1.f / s1) : 0.f;
    float4 sk0 = ldkv4(base + 768 + lane * 4);
    float4 sk1 = ldkv4(base + 896 + lane * 4);
    float4 o0, o1;
    o0.x = fmaxf(sk0.x + a0.x * inv0, 0.f); o0.y = fmaxf(sk0.y + a0.y * inv0, 0.f);
    o0.z = fmaxf(sk0.z + a0.z * inv0, 0.f); o0.w = fmaxf(sk0.w + a0.w * inv0, 0.f);
    o1.x = fmaxf(sk1.x + a1.x * inv1, 0.f); o1.y = fmaxf(sk1.y + a1.y * inv1, 0.f);
    o1.z = fmaxf(sk1.z + a1.z * inv1, 0.f); o1.w = fmaxf(sk1.w + a1.w * inv1, 0.f);
    __half* row = img + (size_t)node * 256;
    sth4(row + lane * 4, o0);
    sth4(row + 128 + lane * 4, o1);
}

// ---------------- host orchestration ----------------
static void run_gemm(int bn, const __half* A, const __half* W,
                     const float* b0, const float* b1, const float* b2, const float* b3,
                     int Nc, int Kbase, int act,
                     __half* img, int imgStride, int imgColOff,
                     const int* batch, float* pool, __half* outh) {
    dim3 grid(Nc / bn, NTILES);
    if (bn == 64)
        gemm_mma<64><<<grid, 256, NSTAGE * (16384 + 64 * 128)>>>(A, W, b0, b1, b2, b3, Nc,
                                                                 Kbase, act, img, imgStride,
                                                                 imgColOff, batch, pool, outh);
    else
        gemm_mma<128><<<grid, 256, NSTAGE * (16384 + 128 * 128)>>>(A, W, b0, b1, b2, b3, Nc,
                                                                   Kbase, act, img, imgStride,
                                                                   imgColOff, batch, pool, outh);
}

extern "C" void kernel_launch(void* const* d_in, const int* in_sizes, int n_in,
                              void* d_out, int out_size) {
    const float* x     = (const float*)d_in[0];
    const int*   ei    = (const int*)d_in[1];
    const int*   batch = (const int*)d_in[2];
    const float* s1_wl = (const float*)d_in[3];
    const float* s1_bl = (const float*)d_in[4];
    const float* s1_wr = (const float*)d_in[5];
    const float* s2_wl = (const float*)d_in[6];
    const float* s2_bl = (const float*)d_in[7];
    const float* s2_wr = (const float*)d_in[8];
    const float* t1_wq = (const float*)d_in[9];
    const float* t1_bq = (const float*)d_in[10];
    const float* t1_wk = (const float*)d_in[11];
    const float* t1_bk = (const float*)d_in[12];
    const float* t1_wv = (const float*)d_in[13];
    const float* t1_bv = (const float*)d_in[14];
    const float* t1_ws = (const float*)d_in[15];
    const float* t1_bs = (const float*)d_in[16];
    const float* t2_wq = (const float*)d_in[17];
    const float* t2_bq = (const float*)d_in[18];
    const float* t2_wk = (const float*)d_in[19];
    const float* t2_bk = (const float*)d_in[20];
    const float* t2_wv = (const float*)d_in[21];
    const float* t2_bv = (const float*)d_in[22];
    const float* t2_ws = (const float*)d_in[23];
    const float* t2_bs = (const float*)d_in[24];
    const float* p1_w  = (const float*)d_in[25];
    const float* p1_b  = (const float*)d_in[26];
    const float* p2_w  = (const float*)d_in[27];
    const float* p2_b  = (const float*)d_in[28];

    const int* e_src = ei;
    const int* e_dst = ei + EE;

    cudaFuncSetAttribute(gemm_mma<128>, cudaFuncAttributeMaxDynamicSharedMemorySize,
                         NSTAGE * (16384 + 128 * 128));
    cudaFuncSetAttribute(gemm_mma<64>, cudaFuncAttributeMaxDynamicSharedMemorySize,
                         NSTAGE * (16384 + 64 * 128));

    __half *d_kvh, *d_i0, *d_i1, *d_W;
    cudaGetSymbolAddress((void**)&d_kvh, g_kvh);
    cudaGetSymbolAddress((void**)&d_i0, g_img0);
    cudaGetSymbolAddress((void**)&d_i1, g_img1);
    cudaGetSymbolAddress((void**)&d_W, g_Wh);

    // CSR build
    k_zero<<<(NN + 255) / 256, 256>>>((float*)d_out);
    k_hist<<<(EE + 255) / 256, 256>>>(e_dst);
    k_scan<<<1, 1024>>>();
    k_scatter<<<(EE + 255) / 256, 256>>>(e_src, e_dst);

    // fused weight conversion (one launch for all 12 tensors)
    {
        WJobs jobs;
        int cum = 0, idx = 0;
        auto add = [&](const float* w1, const float* w2, int k1, int K, int nw, int off) {
            cum += nw * K;
            jobs.j[idx++] = WJob{w1, w2, k1, K, nw, off, cum};
        };
        add(s1_wl, s1_wr, 128, 256, 128, OFF_S1);
        add(s2_wl, s2_wr, 128, 256, 256, OFF_S2);
        add(t1_wq, t1_wq, 256, 256, 256, OFF_T1 + 0 * 65536);
        add(t1_wk, t1_wk, 256, 256, 256, OFF_T1 + 1 * 65536);
        add(t1_wv, t1_wv, 256, 256, 256, OFF_T1 + 2 * 65536);
        add(t1_ws, t1_ws, 256, 256, 256, OFF_T1 + 3 * 65536);
        add(t2_wq, t2_wq, 256, 256, 256, OFF_T2 + 0 * 65536);
        add(t2_wk, t2_wk, 256, 256, 256, OFF_T2 + 1 * 65536);
        add(t2_wv, t2_wv, 256, 256, 256, OFF_T2 + 2 * 65536);
        add(t2_ws, t2_ws, 256, 256, 256, OFF_T2 + 3 * 65536);
        add(p1_w, p1_w, 256, 256, 512, OFF_P1);
        add(p2_w, p2_w, 512, 512, 128, OFF_P2);
        k_convW_all<<<(WTOTAL + 255) / 256, 256>>>(jobs);
    }

    // SAGE 1 input image (img0): mean(x) + x in one launch
    k_prep1<<<(NN * 32 + 255) / 256, 256>>>(x, d_i0);
    // S1: h1 -> img1 cols [128,256)
    run_gemm(64, d_i0, d_W + OFF_S1, s1_bl, s1_bl, s1_bl, s1_bl,
             128, 256, 1, d_i1, 256, 128, nullptr, nullptr, nullptr);

    // SAGE 2: mean over img1 cols[128,256) -> img1 cols[0,128); S2 -> img0
    k_sage_agg_h<<<(NN * 32 + 255) / 256, 256>>>(d_i1);
    run_gemm(64, d_i1, d_W + OFF_S2, s2_bl, s2_bl, s2_bl, s2_bl,
             256, 256, 1, d_i0, 256, 0, nullptr, nullptr, nullptr);

    // TransformerConv 1: q|k|v|skip all fp16 -> kvh
    run_gemm(128, d_i0, d_W + OFF_T1, t1_bq, t1_bk, t1_bv, t1_bs,
             1024, 256, 0, nullptr, 0, 0, nullptr, nullptr, d_kvh);
    k_attn<<<(NN * 32 + 255) / 256, 256>>>(d_kvh, d_i1);

    // TransformerConv 2
    run_gemm(128, d_i1, d_W + OFF_T2, t2_bq, t2_bk, t2_bv, t2_bs,
             1024, 256, 0, nullptr, 0, 0, nullptr, nullptr, d_kvh);
    k_attn<<<(NN * 32 + 255) / 256, 256>>>(d_kvh, d_i0);

    // proj MLP: P1 -> img1 (stride 512); P2 -> sigmoid + fused pool
    run_gemm(64, d_i0, d_W + OFF_P1, p1_b, p1_b + 256, p1_b, p1_b,
             512, 256, 1, d_i1, 512, 0, nullptr, nullptr, nullptr);
    run_gemm(64, d_i1, d_W + OFF_P2, p2_b, p2_b, p2_b, p2_b,
             128, 512, 2, nullptr, 0, 0, batch, (float*)d_out, nullptr);
}

// round 15
// speedup vs baseline: 1.9736x; 1.0045x over previous
#include <cuda_runtime.h>
#include <cuda_bf16.h>
#include <cuda_fp16.h>
#include <math.h>
#include <stdint.h>

#define NN 20000
#define EE 320000
#define GG 64
#define MPAD 20096          // 157 * 128
#define NTILES 157

// ---------------- device scratch ----------------
__device__ __half g_xh[NN * 128];               // x converted to fp16
__device__ __half g_kvh[(size_t)NN * 1024];     // q|k|v|skip fp16 per node
__device__ int g_deg[NN];
__device__ int g_fill[NN];
__device__ int g_rowptr[NN + 1];
__device__ int g_csrc[EE];

// ping-pong plain fp16 activation images: [MPAD][K], widest K=512
__device__ __half g_img0[(size_t)MPAD * 512];
__device__ __half g_img1[(size_t)MPAD * 512];
// fp16 weight images, layout [Nc][K]
__device__ __half g_Wh[819200];

// weight image offsets (elements)
#define OFF_S1   0          // 128 x 256
#define OFF_S2   32768      // 256 x 256
#define OFF_T1   98304      // 4 x (256 x 256)
#define OFF_T2   360448
#define OFF_P1   622592     // 512 x 256
#define OFF_P2   753664     // 128 x 512

__device__ __forceinline__ uint32_t smem_u32(const void* p) {
    uint32_t a;
    asm("{ .reg .u64 t; cvta.to.shared.u64 t, %1; cvt.u32.u64 %0, t; }" : "=r"(a) : "l"(p));
    return a;
}
__device__ __forceinline__ void cpa16(uint32_t dst, const void* src) {
    asm volatile("cp.async.cg.shared.global [%0], [%1], 16;" :: "r"(dst), "l"(src));
}
// store 4 floats as 4 fp16
__device__ __forceinline__ void sth4(__half* p, float4 v) {
    *(__half2*)p = __floats2half2_rn(v.x, v.y);
    *(__half2*)(p + 2) = __floats2half2_rn(v.z, v.w);
}
// load 4 consecutive fp16 values as float4
__device__ __forceinline__ float4 ldkv4(const __half* p) {
    uint2 u = *(const uint2*)p;
    __half2 a = *reinterpret_cast<const __half2*>(&u.x);
    __half2 b = *reinterpret_cast<const __half2*>(&u.y);
    float2 fa = __half22float2(a), fb = __half22float2(b);
    return make_float4(fa.x, fa.y, fb.x, fb.y);
}

// ---------------- CSR build ----------------
__global__ void k_zero(float* out) {
    int i = blockIdx.x * blockDim.x + threadIdx.x;
    if (i < NN) { g_deg[i] = 0; g_fill[i] = 0; }
    if (i < GG * 128) out[i] = 0.0f;
}
__global__ void k_hist(const int* __restrict__ dst) {
    int e = blockIdx.x * blockDim.x + threadIdx.x;
    if (e < EE) atomicAdd(&g_deg[dst[e]], 1);
}
// fast scan: thread-serial partials (20/thread) + one 1024 Hillis-Steele
__global__ void k_scan() {
    __shared__ int sh[1024];
    const int PER = 20;  // 1024*20 >= NN
    int tid = threadIdx.x;
    int base = tid * PER;
    int local[PER];
    int sum = 0;
#pragma unroll
    for (int i = 0; i < PER; i++) {
        int idx = base + i;
        int v = (idx < NN) ? g_deg[idx] : 0;
        local[i] = sum;
        sum += v;
    }
    sh[tid] = sum;
    __syncthreads();
    for (int off = 1; off < 1024; off <<= 1) {
        int t = (tid >= off) ? sh[tid - off] : 0;
        __syncthreads();
        sh[tid] += t;
        __syncthreads();
    }
    int carry = (tid > 0) ? sh[tid - 1] : 0;
#pragma unroll
    for (int i = 0; i < PER; i++) {
        int idx = base + i;
        if (idx < NN) g_rowptr[idx] = carry + local[i];
    }
    if (tid == 1023) g_rowptr[NN] = sh[1023];
}
__global__ void k_scatter(const int* __restrict__ src, const int* __restrict__ dst) {
    int e = blockIdx.x * blockDim.x + threadIdx.x;
    if (e >= EE) return;
    int d = dst[e];
    int pos = atomicAdd(&g_fill[d], 1);
    g_csrc[g_rowptr[d] + pos] = src[e];
}

// ---------------- x -> fp16 ----------------
__global__ void k_convX(const float* __restrict__ x) {
    int idx = blockIdx.x * blockDim.x + threadIdx.x;
    if (idx >= NN * 32) return;
    float4 v = *(const float4*)(x + (size_t)idx * 4);
    sth4(g_xh + (size_t)idx * 4, v);
}

// ---------------- fused prep: sage mean (cols [0,128)) + x (cols [128,256)) ---
__global__ void k_prep1(__half* __restrict__ img) {
    int w = (blockIdx.x * blockDim.x + threadIdx.x) >> 5;
    int lane = threadIdx.x & 31;
    if (w >= NN) return;
    int beg = g_rowptr[w], end = g_rowptr[w + 1];
    float4 acc = make_float4(0.f, 0.f, 0.f, 0.f);
#pragma unroll 4
    for (int e = beg; e < end; e++) {
        int s = g_csrc[e];
        float4 xv = ldkv4(g_xh + (size_t)s * 128 + lane * 4);
        acc.x += xv.x; acc.y += xv.y; acc.z += xv.z; acc.w += xv.w;
    }
    float inv = 1.0f / fmaxf((float)(end - beg), 1.0f);
    acc.x *= inv; acc.y *= inv; acc.z *= inv; acc.w *= inv;
    __half* row = img + (size_t)w * 256;
    sth4(row + lane * 4, acc);
    // copy own x (already fp16) into cols [128,256)
    *(uint2*)(row + 128 + lane * 4) = *(const uint2*)(g_xh + (size_t)w * 128 + lane * 4);
}

// ---------------- SAGE-2 aggregation: mean over img cols [128,256) -> [0,128)
__global__ void k_sage_agg_h(__half* __restrict__ img) {
    int w = (blockIdx.x * blockDim.x + threadIdx.x) >> 5;
    int lane = threadIdx.x & 31;
    if (w >= NN) return;
    int beg = g_rowptr[w], end = g_rowptr[w + 1];
    float4 acc = make_float4(0.f, 0.f, 0.f, 0.f);
#pragma unroll 4
    for (int e = beg; e < end; e++) {
        int s = g_csrc[e];
        float4 xv = ldkv4(img + (size_t)s * 256 + 128 + lane * 4);
        acc.x += xv.x; acc.y += xv.y; acc.z += xv.z; acc.w += xv.w;
    }
    float inv = 1.0f / fmaxf((float)(end - beg), 1.0f);
    acc.x *= inv; acc.y *= inv; acc.z *= inv; acc.w *= inv;
    sth4(img + (size_t)w * 256 + lane * 4, acc);
}

// ---------------- fused weight conversion: all 12 tensors, fp16 --------------
struct WJob { const float *w1, *w2; int k1, K, nw, off, cumEnd; };
struct WJobs { WJob j[12]; };
#define WTOTAL 819200

__global__ void k_convW_all(WJobs jobs) {
    int idx = blockIdx.x * blockDim.x + threadIdx.x;
    if (idx >= WTOTAL) return;
    int s = 0;
    while (idx >= jobs.j[s].cumEnd) s++;
    const WJob J = jobs.j[s];
    int local = idx - (s ? jobs.j[s - 1].cumEnd : 0);
    int n = local / J.K;
    int k = local - n * J.K;
    float val = (k < J.k1) ? J.w1[(size_t)k * J.nw + n] : J.w2[(size_t)(k - J.k1) * J.nw + n];
    g_Wh[(size_t)J.off + (size_t)n * J.K + k] = __float2half_rn(val);
}

// ---------------- 3-stage pipelined mma.sync fp16 GEMM, templated BN ---------
// A [M][K] fp16; W [Nc][K] fp16; K-tiles K/64.
#define NSTAGE 3

template <int BN>
__global__ void __launch_bounds__(256, 2)
gemm_mma(const __half* __restrict__ A, const __half* __restrict__ W,
         const float* __restrict__ b0, const float* __restrict__ b1,
         const float* __restrict__ b2, const float* __restrict__ b3,
         int Nc, int Kbase, int act,
         __half* __restrict__ img, int imgStride, int imgColOff,
         const int* __restrict__ batch, float* __restrict__ pool,
         __half* __restrict__ outh) {
    constexpr int STB = 16384 + BN * 128;       // A tile 16KB + B tile
    constexpr int MI = (BN == 128) ? 4 : 2;     // warp M sub-tiles (x16 rows)
    extern __shared__ char smem[];
    const int tid = threadIdx.x;
    const int wid = tid >> 5, lane = tid & 31;
    const int bm = blockIdx.y * 128;
    const int bn = blockIdx.x * BN;
    const int wm = (BN == 128) ? ((wid & 1) << 6) : ((wid & 3) << 5);
    const int wn = (BN == 128) ? ((wid >> 1) << 5) : ((wid >> 2) << 5);
    const uint32_t sb = smem_u32(smem);

    float acc[MI][4][4];
#pragma unroll
    for (int i = 0; i < MI; i++)
#pragma unroll
        for (int j = 0; j < 4; j++)
#pragma unroll
            for (int t = 0; t < 4; t++) acc[i][j][t] = 0.f;

    const int nK = Kbase >> 6;

    auto issue = [&](int c, int buf) {
        int k0 = c << 6;
        uint32_t base = sb + buf * STB;
#pragma unroll
        for (int l = 0; l < 4; l++) {
            int idx = tid + l * 256;
            int row = idx >> 3, u = idx & 7;
            uint32_t sw = row * 128 + ((u ^ (row & 7)) << 4);
            cpa16(base + sw, A + (size_t)(bm + row) * Kbase + k0 + u * 8);
        }
#pragma unroll
        for (int l = 0; l < BN / 32; l++) {
            int idx = tid + l * 256;
            int row = idx >> 3, u = idx & 7;
            uint32_t sw = row * 128 + ((u ^ (row & 7)) << 4);
            cpa16(base + 16384 + sw, W + (size_t)(bn + row) * Kbase + k0 + u * 8);
        }
        asm volatile("cp.async.commit_group;" ::: "memory");
    };

    issue(0, 0);
    if (nK > 1) issue(1, 1);
    for (int c = 0; c < nK; c++) {
        if (c + 1 < nK) asm volatile("cp.async.wait_group 1;" ::: "memory");
        else            asm volatile("cp.async.wait_group 0;" ::: "memory");
        __syncthreads();          // retires all readers of buffer (c-1)%3
        if (c + 2 < nK) issue(c + 2, (c + 2) % NSTAGE);   // writes (c-1)%3: safe

        int buf = c % NSTAGE;
        uint32_t sAb = sb + buf * STB;
        uint32_t sBb = sAb + 16384;
#pragma unroll
        for (int s = 0; s < 4; s++) {
            uint32_t a[MI][4], b[4][2];
#pragma unroll
            for (int i = 0; i < MI; i++) {
                int row = wm + i * 16 + (lane & 15);
                int u = (s << 1) + (lane >> 4);
                uint32_t ad = sAb + row * 128 + ((u ^ (row & 7)) << 4);
                asm volatile("ldmatrix.sync.aligned.m8n8.x4.shared.b16 {%0,%1,%2,%3}, [%4];"
                    : "=r"(a[i][0]), "=r"(a[i][1]), "=r"(a[i][2]), "=r"(a[i][3]) : "r"(ad));
            }
#pragma unroll
            for (int jj = 0; jj < 2; jj++) {
                int row = wn + (jj << 4) + ((lane >> 4) << 3) + (lane & 7);
                int u = (s << 1) + ((lane >> 3) & 1);
                uint32_t ad = sBb + row * 128 + ((u ^ (row & 7)) << 4);
                asm volatile("ldmatrix.sync.aligned.m8n8.x4.shared.b16 {%0,%1,%2,%3}, [%4];"
                    : "=r"(b[jj * 2][0]), "=r"(b[jj * 2][1]),
                      "=r"(b[jj * 2 + 1][0]), "=r"(b[jj * 2 + 1][1]) : "r"(ad));
            }
#pragma unroll
            for (int i = 0; i < MI; i++)
#pragma unroll
                for (int j = 0; j < 4; j++)
                    asm volatile("mma.sync.aligned.m16n8k16.row.col.f32.f16.f16.f32 "
                        "{%0,%1,%2,%3}, {%4,%5,%6,%7}, {%8,%9}, {%0,%1,%2,%3};"
                        : "+f"(acc[i][j][0]), "+f"(acc[i][j][1]),
                          "+f"(acc[i][j][2]), "+f"(acc[i][j][3])
                        : "r"(a[i][0]), "r"(a[i][1]), "r"(a[i][2]), "r"(a[i][3]),
                          "r"(b[j][0]), "r"(b[j][1]));
        }
    }

    // epilogue
    const float* bsel[4] = {b0, b1, b2, b3};
#pragma unroll
    for (int i = 0; i < MI; i++) {
        int r0 = bm + wm + i * 16 + (lane >> 2);
        int r1 = r0 + 8;
#pragma unroll
        for (int j = 0; j < 4; j++) {
            int c = bn + wn + (j << 3) + ((lane & 3) << 1);
            const float* bp = bsel[c >> 8];
            float bv0 = bp[c & 255], bv1 = bp[(c & 255) + 1];
            float v00 = acc[i][j][0] + bv0, v01 = acc[i][j][1] + bv1;
            float v10 = acc[i][j][2] + bv0, v11 = acc[i][j][3] + bv1;
            if (act == 1) {
                v00 = fmaxf(v00, 0.f); v01 = fmaxf(v01, 0.f);
                v10 = fmaxf(v10, 0.f); v11 = fmaxf(v11, 0.f);
            } else if (act == 2) {
                v00 = 1.f / (1.f + __expf(-v00)); v01 = 1.f / (1.f + __expf(-v01));
                v10 = 1.f / (1.f + __expf(-v10)); v11 = 1.f / (1.f + __expf(-v11));
            }
            if (outh) {
                if (r0 < NN)
                    *(__half2*)(outh + (size_t)r0 * Nc + c) = __floats2half2_rn(v00, v01);
                if (r1 < NN)
                    *(__half2*)(outh + (size_t)r1 * Nc + c) = __floats2half2_rn(v10, v11);
            }
            if (img) {
                int ic = imgColOff + c;
                if (r0 < NN)
                    *(__half2*)(img + (size_t)r0 * imgStride + ic) = __floats2half2_rn(v00, v01);
                if (r1 < NN)
                    *(__half2*)(img + (size_t)r1 * imgStride + ic) = __floats2half2_rn(v10, v11);
            }
            if (pool) {
                if (r0 < NN) {
                    int g = batch[r0] * 128;
                    atomicMax((int*)&pool[g + c], __float_as_int(v00));
                    atomicMax((int*)&pool[g + c + 1], __float_as_int(v01));
                }
                if (r1 < NN) {
                    int g = batch[r1] * 128;
                    atomicMax((int*)&pool[g + c], __float_as_int(v10));
                    atomicMax((int*)&pool[g + c + 1], __float_as_int(v11));
                }
            }
        }
    }
}

// ---------------- attention: warp per node, 8 heads, pairwise, all-fp16 ------
__device__ __forceinline__ float dot4(float4 a, float4 b) {
    return a.x * b.x + a.y * b.y + a.z * b.z + a.w * b.w;
}

__global__ void k_attn(const __half* __restrict__ kvh, __half* __restrict__ img) {
    int node = (blockIdx.x * blockDim.x + threadIdx.x) >> 5;
    if (node >= NN) return;
    int lane = threadIdx.x & 31;
    const __half* base = kvh + (size_t)node * 1024;
    const float scl = 0.17677669529663687f;
    float4 q0 = ldkv4(base + lane * 4);
    float4 q1 = ldkv4(base + 128 + lane * 4);
    q0.x *= scl; q0.y *= scl; q0.z *= scl; q0.w *= scl;
    q1.x *= scl; q1.y *= scl; q1.z *= scl; q1.w *= scl;
    int beg = g_rowptr[node], end = g_rowptr[node + 1];
    float m0 = -3.0e38f, s0 = 0.f, m1 = -3.0e38f, s1 = 0.f;
    float4 a0 = make_float4(0.f, 0.f, 0.f, 0.f);
    float4 a1 = make_float4(0.f, 0.f, 0.f, 0.f);
    int e = beg;
#pragma unroll 2
    for (; e + 1 < end; e += 2) {
        int sa = g_csrc[e], sbn = g_csrc[e + 1];
        const __half* ka = kvh + (size_t)sa * 1024 + 256;
        const __half* kb = kvh + (size_t)sbn * 1024 + 256;
        float4 ka0 = ldkv4(ka + lane * 4);
        float4 ka1 = ldkv4(ka + 128 + lane * 4);
        float4 va0 = ldkv4(ka + 256 + lane * 4);
        float4 va1 = ldkv4(ka + 384 + lane * 4);
        float4 kb0 = ldkv4(kb + lane * 4);
        float4 kb1 = ldkv4(kb + 128 + lane * 4);
        float4 vb0 = ldkv4(kb + 256 + lane * 4);
        float4 vb1 = ldkv4(kb + 384 + lane * 4);
        float da0 = dot4(q0, ka0), da1 = dot4(q1, ka1);
        float db0 = dot4(q0, kb0), db1 = dot4(q1, kb1);
#pragma unroll
        for (int off = 4; off; off >>= 1) {
            da0 += __shfl_xor_sync(0xffffffffu, da0, off);
            da1 += __shfl_xor_sync(0xffffffffu, da1, off);
            db0 += __shfl_xor_sync(0xffffffffu, db0, off);
            db1 += __shfl_xor_sync(0xffffffffu, db1, off);
        }
        {
            float mn = fmaxf(m0, fmaxf(da0, db0));
            float sc = __expf(m0 - mn);
            float pa = __expf(da0 - mn);
            float pb = __expf(db0 - mn);
            s0 = s0 * sc + pa + pb;
            a0.x = a0.x * sc + pa * va0.x + pb * vb0.x;
            a0.y = a0.y * sc + pa * va0.y + pb * vb0.y;
            a0.z = a0.z * sc + pa * va0.z + pb * vb0.z;
            a0.w = a0.w * sc + pa * va0.w + pb * vb0.w;
            m0 = mn;
        }
        {
            float mn = fmaxf(m1, fmaxf(da1, db1));
            float sc = __expf(m1 - mn);
            float pa = __expf(da1 - mn);
            float pb = __expf(db1 - mn);
            s1 = s1 * sc + pa + pb;
            a1.x = a1.x * sc + pa * va1.x + pb * vb1.x;
            a1.y = a1.y * sc + pa * va1.y + pb * vb1.y;
            a1.z = a1.z * sc + pa * va1.z + pb * vb1.z;
            a1.w = a1.w * sc + pa * va1.w + pb * vb1.w;
            m1 = mn;
        }
    }
    if (e < end) {   // tail edge
        int sn = g_csrc[e];
        const __half* kb = kvh + (size_t)sn * 1024 + 256;
        float4 k0 = ldkv4(kb + lane * 4);
        float4 k1 = ldkv4(kb + 128 + lane * 4);
        float4 v0 = ldkv4(kb + 256 + lane * 4);
        float4 v1 = ldkv4(kb + 384 + lane * 4);
        float d0 = dot4(q0, k0), d1 = dot4(q1, k1);
#pragma unroll
        for (int off = 4; off; off >>= 1) {
            d0 += __shfl_xor_sync(0xffffffffu, d0, off);
            d1 += __shfl_xor_sync(0xffffffffu, d1, off);
        }
        float mn0 = fmaxf(m0, d0);
        float sc0 = __expf(m0 - mn0);
        float p0 = __expf(d0 - mn0);
        s0 = s0 * sc0 + p0;
        a0.x = a0.x * sc0 + p0 * v0.x; a0.y = a0.y * sc0 + p0 * v0.y;
        a0.z = a0.z * sc0 + p0 * v0.z; a0.w = a0.w * sc0 + p0 * v0.w;
        m0 = mn0;
        float mn1 = fmaxf(m1, d1);
        float sc1 = __expf(m1 - mn1);
        float p1 = __expf(d1 - mn1);
        s1 = s1 * sc1 + p1;
        a1.x = a1.x * sc1 + p1 * v1.x; a1.y = a1.y * sc1 + p1 * v1.y;
        a1.z = a1.z * sc1 + p1 * v1.z; a1.w = a1.w * sc1 + p1 * v1.w;
        m1 = mn1;
    }
    float inv0 = (end > beg) ? (1.f / s0) : 0.f;
    float inv1 = (end > beg) ? (1.f / s1) : 0.f;
    float4 sk0 = ldkv4(base + 768 + lane * 4);
    float4 sk1 = ldkv4(base + 896 + lane * 4);
    float4 o0, o1;
    o0.x = fmaxf(sk0.x + a0.x * inv0, 0.f); o0.y = fmaxf(sk0.y + a0.y * inv0, 0.f);
    o0.z = fmaxf(sk0.z + a0.z * inv0, 0.f); o0.w = fmaxf(sk0.w + a0.w * inv0, 0.f);
    o1.x = fmaxf(sk1.x + a1.x * inv1, 0.f); o1.y = fmaxf(sk1.y + a1.y * inv1, 0.f);
    o1.z = fmaxf(sk1.z + a1.z * inv1, 0.f); o1.w = fmaxf(sk1.w + a1.w * inv1, 0.f);
    __half* row = img + (size_t)node * 256;
    sth4(row + lane * 4, o0);
    sth4(row + 128 + lane * 4, o1);
}

// ---------------- host orchestration ----------------
static void run_gemm(int bn, const __half* A, const __half* W,
                     const float* b0, const float* b1, const float* b2, const float* b3,
                     int Nc, int Kbase, int act,
                     __half* img, int imgStride, int imgColOff,
                     const int* batch, float* pool, __half* outh) {
    dim3 grid(Nc / bn, NTILES);
    if (bn == 64)
        gemm_mma<64><<<grid, 256, NSTAGE * (16384 + 64 * 128)>>>(A, W, b0, b1, b2, b3, Nc,
                                                                 Kbase, act, img, imgStride,
                                                                 imgColOff, batch, pool, outh);
    else
        gemm_mma<128><<<grid, 256, NSTAGE * (16384 + 128 * 128)>>>(A, W, b0, b1, b2, b3, Nc,
                                                                   Kbase, act, img, imgStride,
                                                                   imgColOff, batch, pool, outh);
}

extern "C" void kernel_launch(void* const* d_in, const int* in_sizes, int n_in,
                              void* d_out, int out_size) {
    const float* x     = (const float*)d_in[0];
    const int*   ei    = (const int*)d_in[1];
    const int*   batch = (const int*)d_in[2];
    const float* s1_wl = (const float*)d_in[3];
    const float* s1_bl = (const float*)d_in[4];
    const float* s1_wr = (const float*)d_in[5];
    const float* s2_wl = (const float*)d_in[6];
    const float* s2_bl = (const float*)d_in[7];
    const float* s2_wr = (const float*)d_in[8];
    const float* t1_wq = (const float*)d_in[9];
    const float* t1_bq = (const float*)d_in[10];
    const float* t1_wk = (const float*)d_in[11];
    const float* t1_bk = (const float*)d_in[12];
    const float* t1_wv = (const float*)d_in[13];
    const float* t1_bv = (const float*)d_in[14];
    const float* t1_ws = (const float*)d_in[15];
    const float* t1_bs = (const float*)d_in[16];
    const float* t2_wq = (const float*)d_in[17];
    const float* t2_bq = (const float*)d_in[18];
    const float* t2_wk = (const float*)d_in[19];
    const float* t2_bk = (const float*)d_in[20];
    const float* t2_wv = (const float*)d_in[21];
    const float* t2_bv = (const float*)d_in[22];
    const float* t2_ws = (const float*)d_in[23];
    const float* t2_bs = (const float*)d_in[24];
    const float* p1_w  = (const float*)d_in[25];
    const float* p1_b  = (const float*)d_in[26];
    const float* p2_w  = (const float*)d_in[27];
    const float* p2_b  = (const float*)d_in[28];

    const int* e_src = ei;
    const int* e_dst = ei + EE;

    cudaFuncSetAttribute(gemm_mma<128>, cudaFuncAttributeMaxDynamicSharedMemorySize,
                         NSTAGE * (16384 + 128 * 128));
    cudaFuncSetAttribute(gemm_mma<64>, cudaFuncAttributeMaxDynamicSharedMemorySize,
                         NSTAGE * (16384 + 64 * 128));

    __half *d_kvh, *d_i0, *d_i1, *d_W;
    cudaGetSymbolAddress((void**)&d_kvh, g_kvh);
    cudaGetSymbolAddress((void**)&d_i0, g_img0);
    cudaGetSymbolAddress((void**)&d_i1, g_img1);
    cudaGetSymbolAddress((void**)&d_W, g_Wh);

    // CSR build + x conversion
    k_zero<<<(NN + 255) / 256, 256>>>((float*)d_out);
    k_hist<<<(EE + 255) / 256, 256>>>(e_dst);
    k_convX<<<(NN * 32 + 255) / 256, 256>>>(x);
    k_scan<<<1, 1024>>>();
    k_scatter<<<(EE + 255) / 256, 256>>>(e_src, e_dst);

    // fused weight conversion (one launch for all 12 tensors)
    {
        WJobs jobs;
        int cum = 0, idx = 0;
        auto add = [&](const float* w1, const float* w2, int k1, int K, int nw, int off) {
            cum += nw * K;
            jobs.j[idx++] = WJob{w1, w2, k1, K, nw, off, cum};
        };
        add(s1_wl, s1_wr, 128, 256, 128, OFF_S1);
        add(s2_wl, s2_wr, 128, 256, 256, OFF_S2);
        add(t1_wq, t1_wq, 256, 256, 256, OFF_T1 + 0 * 65536);
        add(t1_wk, t1_wk, 256, 256, 256, OFF_T1 + 1 * 65536);
        add(t1_wv, t1_wv, 256, 256, 256, OFF_T1 + 2 * 65536);
        add(t1_ws, t1_ws, 256, 256, 256, OFF_T1 + 3 * 65536);
        add(t2_wq, t2_wq, 256, 256, 256, OFF_T2 + 0 * 65536);
        add(t2_wk, t2_wk, 256, 256, 256, OFF_T2 + 1 * 65536);
        add(t2_wv, t2_wv, 256, 256, 256, OFF_T2 + 2 * 65536);
        add(t2_ws, t2_ws, 256, 256, 256, OFF_T2 + 3 * 65536);
        add(p1_w, p1_w, 256, 256, 512, OFF_P1);
        add(p2_w, p2_w, 512, 512, 128, OFF_P2);
        k_convW_all<<<(WTOTAL + 255) / 256, 256>>>(jobs);
    }

    // SAGE 1 input image (img0): mean(x fp16) + x fp16 in one launch
    k_prep1<<<(NN * 32 + 255) / 256, 256>>>(d_i0);
    // S1: h1 -> img1 cols [128,256)
    run_gemm(64, d_i0, d_W + OFF_S1, s1_bl, s1_bl, s1_bl, s1_bl,
             128, 256, 1, d_i1, 256, 128, nullptr, nullptr, nullptr);

    // SAGE 2: mean over img1 cols[128,256) -> img1 cols[0,128); S2 -> img0
    k_sage_agg_h<<<(NN * 32 + 255) / 256, 256>>>(d_i1);
    run_gemm(64, d_i1, d_W + OFF_S2, s2_bl, s2_bl, s2_bl, s2_bl,
             256, 256, 1, d_i0, 256, 0, nullptr, nullptr, nullptr);

    // TransformerConv 1: q|k|v|skip all fp16 -> kvh
    run_gemm(128, d_i0, d_W + OFF_T1, t1_bq, t1_bk, t1_bv, t1_bs,
             1024, 256, 0, nullptr, 0, 0, nullptr, nullptr, d_kvh);
    k_attn<<<(NN * 32 + 255) / 256, 256>>>(d_kvh, d_i1);

    // TransformerConv 2
    run_gemm(128, d_i1, d_W + OFF_T2, t2_bq, t2_bk, t2_bv, t2_bs,
             1024, 256, 0, nullptr, 0, 0, nullptr, nullptr, d_kvh);
    k_attn<<<(NN * 32 + 255) / 256, 256>>>(d_kvh, d_i0);

    // proj MLP: P1 -> img1 (stride 512); P2 -> sigmoid + fused pool
    run_gemm(64, d_i0, d_W + OFF_P1, p1_b, p1_b + 256, p1_b, p1_b,
             512, 256, 1, d_i1, 512, 0, nullptr, nullptr, nullptr);
    run_gemm(64, d_i1, d_W + OFF_P2, p2_b, p2_b, p2_b, p2_b,
             128, 512, 2, nullptr, 0, 0, batch, (float*)d_out, nullptr);
}

// round 16
// speedup vs baseline: 2.0463x; 1.0368x over previous
#include <cuda_runtime.h>
#include <cuda_bf16.h>
#include <cuda_fp16.h>
#include <math.h>
#include <stdint.h>

#define NN 20000
#define EE 320000
#define GG 64
#define MPAD 20096          // 157 * 128
#define NTILES 157
#define SCANB 20            // scan blocks (20*1024 >= NN)

// ---------------- device scratch ----------------
__device__ __half g_xh[NN * 128];               // x converted to fp16
__device__ __half g_kvh[(size_t)NN * 1024];     // q|k|v|skip fp16 per node
__device__ int g_deg[NN];
__device__ int g_fill[NN];
__device__ int g_rowptr[NN + 1];
__device__ int g_csrc[EE];
__device__ int g_bsum[SCANB];

// ping-pong plain fp16 activation images: [MPAD][K], widest K=512
__device__ __half g_img0[(size_t)MPAD * 512];
__device__ __half g_img1[(size_t)MPAD * 512];
// fp16 weight images, layout [Nc][K]
__device__ __half g_Wh[819200];

// weight image offsets (elements)
#define OFF_S1   0          // 128 x 256
#define OFF_S2   32768      // 256 x 256
#define OFF_T1   98304      // 4 x (256 x 256)
#define OFF_T2   360448
#define OFF_P1   622592     // 512 x 256
#define OFF_P2   753664     // 128 x 512

__device__ __forceinline__ uint32_t smem_u32(const void* p) {
    uint32_t a;
    asm("{ .reg .u64 t; cvta.to.shared.u64 t, %1; cvt.u32.u64 %0, t; }" : "=r"(a) : "l"(p));
    return a;
}
__device__ __forceinline__ void cpa16(uint32_t dst, const void* src) {
    asm volatile("cp.async.cg.shared.global [%0], [%1], 16;" :: "r"(dst), "l"(src));
}
// store 4 floats as 4 fp16
__device__ __forceinline__ void sth4(__half* p, float4 v) {
    *(__half2*)p = __floats2half2_rn(v.x, v.y);
    *(__half2*)(p + 2) = __floats2half2_rn(v.z, v.w);
}
// load 4 consecutive fp16 values as float4
__device__ __forceinline__ float4 ldkv4(const __half* p) {
    uint2 u = *(const uint2*)p;
    __half2 a = *reinterpret_cast<const __half2*>(&u.x);
    __half2 b = *reinterpret_cast<const __half2*>(&u.y);
    float2 fa = __half22float2(a), fb = __half22float2(b);
    return make_float4(fa.x, fa.y, fb.x, fb.y);
}

// ---------------- CSR build ----------------
__global__ void k_zero(float* out) {
    int i = blockIdx.x * blockDim.x + threadIdx.x;
    if (i < NN) { g_deg[i] = 0; g_fill[i] = 0; }
    if (i < GG * 128) out[i] = 0.0f;
}
__global__ void k_hist(const int* __restrict__ dst) {
    int e = blockIdx.x * blockDim.x + threadIdx.x;
    if (e < EE) atomicAdd(&g_deg[dst[e]], 1);
}
// 3-phase parallel scan
__global__ void k_scan1() {
    __shared__ int sh[1024];
    int b = blockIdx.x, tid = threadIdx.x;
    int idx = b * 1024 + tid;
    int v = (idx < NN) ? g_deg[idx] : 0;
    sh[tid] = v;
    __syncthreads();
    for (int off = 1; off < 1024; off <<= 1) {
        int t = (tid >= off) ? sh[tid - off] : 0;
        __syncthreads();
        sh[tid] += t;
        __syncthreads();
    }
    if (idx < NN) g_rowptr[idx] = sh[tid] - v;   // block-local exclusive
    if (tid == 1023) g_bsum[b] = sh[1023];
}
__global__ void k_scan2() {
    int tid = threadIdx.x;   // 32 threads
    int orig = (tid < SCANB) ? g_bsum[tid] : 0;
    int v = orig;
#pragma unroll
    for (int off = 1; off < 32; off <<= 1) {
        int t = __shfl_up_sync(0xffffffffu, v, off);
        if (tid >= off) v += t;
    }
    if (tid < SCANB) g_bsum[tid] = v - orig;     // exclusive block offset
    if (tid == SCANB - 1) g_rowptr[NN] = v;      // total
}
__global__ void k_scan3() {
    int b = blockIdx.x, tid = threadIdx.x;
    int idx = b * 1024 + tid;
    if (b > 0 && idx < NN) g_rowptr[idx] += g_bsum[b];
}
__global__ void k_scatter(const int* __restrict__ src, const int* __restrict__ dst) {
    int e = blockIdx.x * blockDim.x + threadIdx.x;
    if (e >= EE) return;
    int d = dst[e];
    int pos = atomicAdd(&g_fill[d], 1);
    g_csrc[g_rowptr[d] + pos] = src[e];
}

// ---------------- x -> fp16 ----------------
__global__ void k_convX(const float* __restrict__ x) {
    int idx = blockIdx.x * blockDim.x + threadIdx.x;
    if (idx >= NN * 32) return;
    float4 v = *(const float4*)(x + (size_t)idx * 4);
    sth4(g_xh + (size_t)idx * 4, v);
}

// ---------------- fused prep: sage mean (cols [0,128)) + x (cols [128,256)) ---
__global__ void k_prep1(__half* __restrict__ img) {
    int w = (blockIdx.x * blockDim.x + threadIdx.x) >> 5;
    int lane = threadIdx.x & 31;
    if (w >= NN) return;
    int beg = g_rowptr[w], end = g_rowptr[w + 1];
    float4 acc = make_float4(0.f, 0.f, 0.f, 0.f);
#pragma unroll 4
    for (int e = beg; e < end; e++) {
        int s = g_csrc[e];
        float4 xv = ldkv4(g_xh + (size_t)s * 128 + lane * 4);
        acc.x += xv.x; acc.y += xv.y; acc.z += xv.z; acc.w += xv.w;
    }
    float inv = 1.0f / fmaxf((float)(end - beg), 1.0f);
    acc.x *= inv; acc.y *= inv; acc.z *= inv; acc.w *= inv;
    __half* row = img + (size_t)w * 256;
    sth4(row + lane * 4, acc);
    *(uint2*)(row + 128 + lane * 4) = *(const uint2*)(g_xh + (size_t)w * 128 + lane * 4);
}

// ---------------- SAGE-2 aggregation: mean over img cols [128,256) -> [0,128)
__global__ void k_sage_agg_h(__half* __restrict__ img) {
    int w = (blockIdx.x * blockDim.x + threadIdx.x) >> 5;
    int lane = threadIdx.x & 31;
    if (w >= NN) return;
    int beg = g_rowptr[w], end = g_rowptr[w + 1];
    float4 acc = make_float4(0.f, 0.f, 0.f, 0.f);
#pragma unroll 4
    for (int e = beg; e < end; e++) {
        int s = g_csrc[e];
        float4 xv = ldkv4(img + (size_t)s * 256 + 128 + lane * 4);
        acc.x += xv.x; acc.y += xv.y; acc.z += xv.z; acc.w += xv.w;
    }
    float inv = 1.0f / fmaxf((float)(end - beg), 1.0f);
    acc.x *= inv; acc.y *= inv; acc.z *= inv; acc.w *= inv;
    sth4(img + (size_t)w * 256 + lane * 4, acc);
}

// ---------------- fused weight conversion: all 12 tensors, fp16 --------------
struct WJob { const float *w1, *w2; int k1, K, nw, off, cumEnd; };
struct WJobs { WJob j[12]; };
#define WTOTAL 819200

__global__ void k_convW_all(WJobs jobs) {
    int idx = blockIdx.x * blockDim.x + threadIdx.x;
    if (idx >= WTOTAL) return;
    int s = 0;
    while (idx >= jobs.j[s].cumEnd) s++;
    const WJob J = jobs.j[s];
    int local = idx - (s ? jobs.j[s - 1].cumEnd : 0);
    int n = local / J.K;
    int k = local - n * J.K;
    float val = (k < J.k1) ? J.w1[(size_t)k * J.nw + n] : J.w2[(size_t)(k - J.k1) * J.nw + n];
    g_Wh[(size_t)J.off + (size_t)n * J.K + k] = __float2half_rn(val);
}

// ---------------- 3-stage pipelined mma.sync fp16 GEMM, templated BN ---------
#define NSTAGE 3

template <int BN>
__global__ void __launch_bounds__(256, 2)
gemm_mma(const __half* __restrict__ A, const __half* __restrict__ W,
         const float* __restrict__ b0, const float* __restrict__ b1,
         const float* __restrict__ b2, const float* __restrict__ b3,
         int Nc, int Kbase, int act,
         __half* __restrict__ img, int imgStride, int imgColOff,
         const int* __restrict__ batch, float* __restrict__ pool,
         __half* __restrict__ outh) {
    constexpr int STB = 16384 + BN * 128;
    constexpr int MI = (BN == 128) ? 4 : 2;
    extern __shared__ char smem[];
    const int tid = threadIdx.x;
    const int wid = tid >> 5, lane = tid & 31;
    const int bm = blockIdx.y * 128;
    const int bn = blockIdx.x * BN;
    const int wm = (BN == 128) ? ((wid & 1) << 6) : ((wid & 3) << 5);
    const int wn = (BN == 128) ? ((wid >> 1) << 5) : ((wid >> 2) << 5);
    const uint32_t sb = smem_u32(smem);

    float acc[MI][4][4];
#pragma unroll
    for (int i = 0; i < MI; i++)
#pragma unroll
        for (int j = 0; j < 4; j++)
#pragma unroll
            for (int t = 0; t < 4; t++) acc[i][j][t] = 0.f;

    const int nK = Kbase >> 6;

    auto issue = [&](int c, int buf) {
        int k0 = c << 6;
        uint32_t base = sb + buf * STB;
#pragma unroll
        for (int l = 0; l < 4; l++) {
            int idx = tid + l * 256;
            int row = idx >> 3, u = idx & 7;
            uint32_t sw = row * 128 + ((u ^ (row & 7)) << 4);
            cpa16(base + sw, A + (size_t)(bm + row) * Kbase + k0 + u * 8);
        }
#pragma unroll
        for (int l = 0; l < BN / 32; l++) {
            int idx = tid + l * 256;
            int row = idx >> 3, u = idx & 7;
            uint32_t sw = row * 128 + ((u ^ (row & 7)) << 4);
            cpa16(base + 16384 + sw, W + (size_t)(bn + row) * Kbase + k0 + u * 8);
        }
        asm volatile("cp.async.commit_group;" ::: "memory");
    };

    issue(0, 0);
    if (nK > 1) issue(1, 1);
    for (int c = 0; c < nK; c++) {
        if (c + 1 < nK) asm volatile("cp.async.wait_group 1;" ::: "memory");
        else            asm volatile("cp.async.wait_group 0;" ::: "memory");
        __syncthreads();
        if (c + 2 < nK) issue(c + 2, (c + 2) % NSTAGE);

        int buf = c % NSTAGE;
        uint32_t sAb = sb + buf * STB;
        uint32_t sBb = sAb + 16384;
#pragma unroll
        for (int s = 0; s < 4; s++) {
            uint32_t a[MI][4], b[4][2];
#pragma unroll
            for (int i = 0; i < MI; i++) {
                int row = wm + i * 16 + (lane & 15);
                int u = (s << 1) + (lane >> 4);
                uint32_t ad = sAb + row * 128 + ((u ^ (row & 7)) << 4);
                asm volatile("ldmatrix.sync.aligned.m8n8.x4.shared.b16 {%0,%1,%2,%3}, [%4];"
                    : "=r"(a[i][0]), "=r"(a[i][1]), "=r"(a[i][2]), "=r"(a[i][3]) : "r"(ad));
            }
#pragma unroll
            for (int jj = 0; jj < 2; jj++) {
                int row = wn + (jj << 4) + ((lane >> 4) << 3) + (lane & 7);
                int u = (s << 1) + ((lane >> 3) & 1);
                uint32_t ad = sBb + row * 128 + ((u ^ (row & 7)) << 4);
                asm volatile("ldmatrix.sync.aligned.m8n8.x4.shared.b16 {%0,%1,%2,%3}, [%4];"
                    : "=r"(b[jj * 2][0]), "=r"(b[jj * 2][1]),
                      "=r"(b[jj * 2 + 1][0]), "=r"(b[jj * 2 + 1][1]) : "r"(ad));
            }
#pragma unroll
            for (int i = 0; i < MI; i++)
#pragma unroll
                for (int j = 0; j < 4; j++)
                    asm volatile("mma.sync.aligned.m16n8k16.row.col.f32.f16.f16.f32 "
                        "{%0,%1,%2,%3}, {%4,%5,%6,%7}, {%8,%9}, {%0,%1,%2,%3};"
                        : "+f"(acc[i][j][0]), "+f"(acc[i][j][1]),
                          "+f"(acc[i][j][2]), "+f"(acc[i][j][3])
                        : "r"(a[i][0]), "r"(a[i][1]), "r"(a[i][2]), "r"(a[i][3]),
                          "r"(b[j][0]), "r"(b[j][1]));
        }
    }

    // epilogue
    const float* bsel[4] = {b0, b1, b2, b3};
#pragma unroll
    for (int i = 0; i < MI; i++) {
        int r0 = bm + wm + i * 16 + (lane >> 2);
        int r1 = r0 + 8;
#pragma unroll
        for (int j = 0; j < 4; j++) {
            int c = bn + wn + (j << 3) + ((lane & 3) << 1);
            const float* bp = bsel[c >> 8];
            float bv0 = bp[c & 255], bv1 = bp[(c & 255) + 1];
            float v00 = acc[i][j][0] + bv0, v01 = acc[i][j][1] + bv1;
            float v10 = acc[i][j][2] + bv0, v11 = acc[i][j][3] + bv1;
            if (act == 1) {
                v00 = fmaxf(v00, 0.f); v01 = fmaxf(v01, 0.f);
                v10 = fmaxf(v10, 0.f); v11 = fmaxf(v11, 0.f);
            } else if (act == 2) {
                v00 = 1.f / (1.f + __expf(-v00)); v01 = 1.f / (1.f + __expf(-v01));
                v10 = 1.f / (1.f + __expf(-v10)); v11 = 1.f / (1.f + __expf(-v11));
            }
            if (outh) {
                if (r0 < NN)
                    *(__half2*)(outh + (size_t)r0 * Nc + c) = __floats2half2_rn(v00, v01);
                if (r1 < NN)
                    *(__half2*)(outh + (size_t)r1 * Nc + c) = __floats2half2_rn(v10, v11);
            }
            if (img) {
                int ic = imgColOff + c;
                if (r0 < NN)
                    *(__half2*)(img + (size_t)r0 * imgStride + ic) = __floats2half2_rn(v00, v01);
                if (r1 < NN)
                    *(__half2*)(img + (size_t)r1 * imgStride + ic) = __floats2half2_rn(v10, v11);
            }
            if (pool) {
                if (r0 < NN) {
                    int g = batch[r0] * 128;
                    atomicMax((int*)&pool[g + c], __float_as_int(v00));
                    atomicMax((int*)&pool[g + c + 1], __float_as_int(v01));
                }
                if (r1 < NN) {
                    int g = batch[r1] * 128;
                    atomicMax((int*)&pool[g + c], __float_as_int(v10));
                    atomicMax((int*)&pool[g + c + 1], __float_as_int(v11));
                }
            }
        }
    }
}

// ---------------- attention: warp per node, 8 heads, pairwise, all-fp16 ------
__device__ __forceinline__ float dot4(float4 a, float4 b) {
    return a.x * b.x + a.y * b.y + a.z * b.z + a.w * b.w;
}

__global__ void k_attn(const __half* __restrict__ kvh, __half* __restrict__ img) {
    int node = (blockIdx.x * blockDim.x + threadIdx.x) >> 5;
    if (node >= NN) return;
    int lane = threadIdx.x & 31;
    const __half* base = kvh + (size_t)node * 1024;
    const float scl = 0.17677669529663687f;
    float4 q0 = ldkv4(base + lane * 4);
    float4 q1 = ldkv4(base + 128 + lane * 4);
    q0.x *= scl; q0.y *= scl; q0.z *= scl; q0.w *= scl;
    q1.x *= scl; q1.y *= scl; q1.z *= scl; q1.w *= scl;
    int beg = g_rowptr[node], end = g_rowptr[node + 1];
    float m0 = -3.0e38f, s0 = 0.f, m1 = -3.0e38f, s1 = 0.f;
    float4 a0 = make_float4(0.f, 0.f, 0.f, 0.f);
    float4 a1 = make_float4(0.f, 0.f, 0.f, 0.f);
    int e = beg;
#pragma unroll 2
    for (; e + 1 < end; e += 2) {
        int sa = g_csrc[e], sbn = g_csrc[e + 1];
        const __half* ka = kvh + (size_t)sa * 1024 + 256;
        const __half* kb = kvh + (size_t)sbn * 1024 + 256;
        float4 ka0 = ldkv4(ka + lane * 4);
        float4 ka1 = ldkv4(ka + 128 + lane * 4);
        float4 va0 = ldkv4(ka + 256 + lane * 4);
        float4 va1 = ldkv4(ka + 384 + lane * 4);
        float4 kb0 = ldkv4(kb + lane * 4);
        float4 kb1 = ldkv4(kb + 128 + lane * 4);
        float4 vb0 = ldkv4(kb + 256 + lane * 4);
        float4 vb1 = ldkv4(kb + 384 + lane * 4);
        float da0 = dot4(q0, ka0), da1 = dot4(q1, ka1);
        float db0 = dot4(q0, kb0), db1 = dot4(q1, kb1);
#pragma unroll
        for (int off = 4; off; off >>= 1) {
            da0 += __shfl_xor_sync(0xffffffffu, da0, off);
            da1 += __shfl_xor_sync(0xffffffffu, da1, off);
            db0 += __shfl_xor_sync(0xffffffffu, db0, off);
            db1 += __shfl_xor_sync(0xffffffffu, db1, off);
        }
        {
            float mn = fmaxf(m0, fmaxf(da0, db0));
            float sc = __expf(m0 - mn);
            float pa = __expf(da0 - mn);
            float pb = __expf(db0 - mn);
            s0 = s0 * sc + pa + pb;
            a0.x = a0.x * sc + pa * va0.x + pb * vb0.x;
            a0.y = a0.y * sc + pa * va0.y + pb * vb0.y;
            a0.z = a0.z * sc + pa * va0.z + pb * vb0.z;
            a0.w = a0.w * sc + pa * va0.w + pb * vb0.w;
            m0 = mn;
        }
        {
            float mn = fmaxf(m1, fmaxf(da1, db1));
            float sc = __expf(m1 - mn);
            float pa = __expf(da1 - mn);
            float pb = __expf(db1 - mn);
            s1 = s1 * sc + pa + pb;
            a1.x = a1.x * sc + pa * va1.x + pb * vb1.x;
            a1.y = a1.y * sc + pa * va1.y + pb * vb1.y;
            a1.z = a1.z * sc + pa * va1.z + pb * vb1.z;
            a1.w = a1.w * sc + pa * va1.w + pb * vb1.w;
            m1 = mn;
        }
    }
    if (e < end) {
        int sn = g_csrc[e];
        const __half* kb = kvh + (size_t)sn * 1024 + 256;
        float4 k0 = ldkv4(kb + lane * 4);
        float4 k1 = ldkv4(kb + 128 + lane * 4);
        float4 v0 = ldkv4(kb + 256 + lane * 4);
        float4 v1 = ldkv4(kb + 384 + lane * 4);
        float d0 = dot4(q0, k0), d1 = dot4(q1, k1);
#pragma unroll
        for (int off = 4; off; off >>= 1) {
            d0 += __shfl_xor_sync(0xffffffffu, d0, off);
            d1 += __shfl_xor_sync(0xffffffffu, d1, off);
        }
        float mn0 = fmaxf(m0, d0);
        float sc0 = __expf(m0 - mn0);
        float p0 = __expf(d0 - mn0);
        s0 = s0 * sc0 + p0;
        a0.x = a0.x * sc0 + p0 * v0.x; a0.y = a0.y * sc0 + p0 * v0.y;
        a0.z = a0.z * sc0 + p0 * v0.z; a0.w = a0.w * sc0 + p0 * v0.w;
        m0 = mn0;
        float mn1 = fmaxf(m1, d1);
        float sc1 = __expf(m1 - mn1);
        float p1 = __expf(d1 - mn1);
        s1 = s1 * sc1 + p1;
        a1.x = a1.x * sc1 + p1 * v1.x; a1.y = a1.y * sc1 + p1 * v1.y;
        a1.z = a1.z * sc1 + p1 * v1.z; a1.w = a1.w * sc1 + p1 * v1.w;
        m1 = mn1;
    }
    float inv0 = (end > beg) ? (1.f / s0) : 0.f;
    float inv1 = (end > beg) ? (1.f / s1) : 0.f;
    float4 sk0 = ldkv4(base + 768 + lane * 4);
    float4 sk1 = ldkv4(base + 896 + lane * 4);
    float4 o0, o1;
    o0.x = fmaxf(sk0.x + a0.x * inv0, 0.f); o0.y = fmaxf(sk0.y + a0.y * inv0, 0.f);
    o0.z = fmaxf(sk0.z + a0.z * inv0, 0.f); o0.w = fmaxf(sk0.w + a0.w * inv0, 0.f);
    o1.x = fmaxf(sk1.x + a1.x * inv1, 0.f); o1.y = fmaxf(sk1.y + a1.y * inv1, 0.f);
    o1.z = fmaxf(sk1.z + a1.z * inv1, 0.f); o1.w = fmaxf(sk1.w + a1.w * inv1, 0.f);
    __half* row = img + (size_t)node * 256;
    sth4(row + lane * 4, o0);
    sth4(row + 128 + lane * 4, o1);
}

// ---------------- host orchestration ----------------
static void run_gemm(int bn, const __half* A, const __half* W,
                     const float* b0, const float* b1, const float* b2, const float* b3,
                     int Nc, int Kbase, int act,
                     __half* img, int imgStride, int imgColOff,
                     const int* batch, float* pool, __half* outh) {
    dim3 grid(Nc / bn, NTILES);
    if (bn == 64)
        gemm_mma<64><<<grid, 256, NSTAGE * (16384 + 64 * 128)>>>(A, W, b0, b1, b2, b3, Nc,
                                                                 Kbase, act, img, imgStride,
                                                                 imgColOff, batch, pool, outh);
    else
        gemm_mma<128><<<grid, 256, NSTAGE * (16384 + 128 * 128)>>>(A, W, b0, b1, b2, b3, Nc,
                                                                   Kbase, act, img, imgStride,
                                                                   imgColOff, batch, pool, outh);
}

extern "C" void kernel_launch(void* const* d_in, const int* in_sizes, int n_in,
                              void* d_out, int out_size) {
    const float* x     = (const float*)d_in[0];
    const int*   ei    = (const int*)d_in[1];
    const int*   batch = (const int*)d_in[2];
    const float* s1_wl = (const float*)d_in[3];
    const float* s1_bl = (const float*)d_in[4];
    const float* s1_wr = (const float*)d_in[5];
    const float* s2_wl = (const float*)d_in[6];
    const float* s2_bl = (const float*)d_in[7];
    const float* s2_wr = (const float*)d_in[8];
    const float* t1_wq = (const float*)d_in[9];
    const float* t1_bq = (const float*)d_in[10];
    const float* t1_wk = (const float*)d_in[11];
    const float* t1_bk = (const float*)d_in[12];
    const float* t1_wv = (const float*)d_in[13];
    const float* t1_bv = (const float*)d_in[14];
    const float* t1_ws = (const float*)d_in[15];
    const float* t1_bs = (const float*)d_in[16];
    const float* t2_wq = (const float*)d_in[17];
    const float* t2_bq = (const float*)d_in[18];
    const float* t2_wk = (const float*)d_in[19];
    const float* t2_bk = (const float*)d_in[20];
    const float* t2_wv = (const float*)d_in[21];
    const float* t2_bv = (const float*)d_in[22];
    const float* t2_ws = (const float*)d_in[23];
    const float* t2_bs = (const float*)d_in[24];
    const float* p1_w  = (const float*)d_in[25];
    const float* p1_b  = (const float*)d_in[26];
    const float* p2_w  = (const float*)d_in[27];
    const float* p2_b  = (const float*)d_in[28];

    const int* e_src = ei;
    const int* e_dst = ei + EE;

    cudaFuncSetAttribute(gemm_mma<128>, cudaFuncAttributeMaxDynamicSharedMemorySize,
                         NSTAGE * (16384 + 128 * 128));
    cudaFuncSetAttribute(gemm_mma<64>, cudaFuncAttributeMaxDynamicSharedMemorySize,
                         NSTAGE * (16384 + 64 * 128));

    // second stream + events (created once, OUTSIDE capture: first call is the
    // correctness run; capture happens on later calls with these already live)
    static cudaStream_t s2 = nullptr;
    static cudaEvent_t evFork = nullptr, evJoin = nullptr;
    if (s2 == nullptr) {
        cudaStreamCreateWithFlags(&s2, cudaStreamNonBlocking);
        cudaEventCreateWithFlags(&evFork, cudaEventDisableTiming);
        cudaEventCreateWithFlags(&evJoin, cudaEventDisableTiming);
    }

    __half *d_kvh, *d_i0, *d_i1, *d_W;
    cudaGetSymbolAddress((void**)&d_kvh, g_kvh);
    cudaGetSymbolAddress((void**)&d_i0, g_img0);
    cudaGetSymbolAddress((void**)&d_i1, g_img1);
    cudaGetSymbolAddress((void**)&d_W, g_Wh);

    // ---- fork: convW + convX on s2, CSR build on main stream ----
    k_zero<<<(NN + 255) / 256, 256>>>((float*)d_out);
    cudaEventRecord(evFork, 0);
    cudaStreamWaitEvent(s2, evFork, 0);
    {
        WJobs jobs;
        int cum = 0, idx = 0;
        auto add = [&](const float* w1, const float* w2, int k1, int K, int nw, int off) {
            cum += nw * K;
            jobs.j[idx++] = WJob{w1, w2, k1, K, nw, off, cum};
        };
        add(s1_wl, s1_wr, 128, 256, 128, OFF_S1);
        add(s2_wl, s2_wr, 128, 256, 256, OFF_S2);
        add(t1_wq, t1_wq, 256, 256, 256, OFF_T1 + 0 * 65536);
        add(t1_wk, t1_wk, 256, 256, 256, OFF_T1 + 1 * 65536);
        add(t1_wv, t1_wv, 256, 256, 256, OFF_T1 + 2 * 65536);
        add(t1_ws, t1_ws, 256, 256, 256, OFF_T1 + 3 * 65536);
        add(t2_wq, t2_wq, 256, 256, 256, OFF_T2 + 0 * 65536);
        add(t2_wk, t2_wk, 256, 256, 256, OFF_T2 + 1 * 65536);
        add(t2_wv, t2_wv, 256, 256, 256, OFF_T2 + 2 * 65536);
        add(t2_ws, t2_ws, 256, 256, 256, OFF_T2 + 3 * 65536);
        add(p1_w, p1_w, 256, 256, 512, OFF_P1);
        add(p2_w, p2_w, 512, 512, 128, OFF_P2);
        k_convW_all<<<(WTOTAL + 255) / 256, 256, 0, s2>>>(jobs);
        k_convX<<<(NN * 32 + 255) / 256, 256, 0, s2>>>(x);
    }
    cudaEventRecord(evJoin, s2);

    // main stream: CSR build (parallel with s2 work)
    k_hist<<<(EE + 255) / 256, 256>>>(e_dst);
    k_scan1<<<SCANB, 1024>>>();
    k_scan2<<<1, 32>>>();
    k_scan3<<<SCANB, 1024>>>();
    k_scatter<<<(EE + 255) / 256, 256>>>(e_src, e_dst);

    // join: prep1 needs xh (s2) + CSR (main)
    cudaStreamWaitEvent(0, evJoin, 0);

    k_prep1<<<(NN * 32 + 255) / 256, 256>>>(d_i0);
    run_gemm(64, d_i0, d_W + OFF_S1, s1_bl, s1_bl, s1_bl, s1_bl,
             128, 256, 1, d_i1, 256, 128, nullptr, nullptr, nullptr);

    k_sage_agg_h<<<(NN * 32 + 255) / 256, 256>>>(d_i1);
    run_gemm(64, d_i1, d_W + OFF_S2, s2_bl, s2_bl, s2_bl, s2_bl,
             256, 256, 1, d_i0, 256, 0, nullptr, nullptr, nullptr);

    run_gemm(128, d_i0, d_W + OFF_T1, t1_bq, t1_bk, t1_bv, t1_bs,
             1024, 256, 0, nullptr, 0, 0, nullptr, nullptr, d_kvh);
    k_attn<<<(NN * 32 + 255) / 256, 256>>>(d_kvh, d_i1);

    run_gemm(128, d_i1, d_W + OFF_T2, t2_bq, t2_bk, t2_bv, t2_bs,
             1024, 256, 0, nullptr, 0, 0, nullptr, nullptr, d_kvh);
    k_attn<<<(NN * 32 + 255) / 256, 256>>>(d_kvh, d_i0);

    run_gemm(64, d_i0, d_W + OFF_P1, p1_b, p1_b + 256, p1_b, p1_b,
             512, 256, 1, d_i1, 512, 0, nullptr, nullptr, nullptr);
    run_gemm(64, d_i1, d_W + OFF_P2, p2_b, p2_b, p2_b, p2_b,
             128, 512, 2, nullptr, 0, 0, batch, (float*)d_out, nullptr);
}